// round 1
// baseline (speedup 1.0000x reference)
#include <cuda_runtime.h>

#define NH 20
#define DH 64
#define DMODEL 1280
#define BATCH 2
#define SEQ 2048
#define MTOT (BATCH*SEQ)      /* 4096 */
#define NQKV (3*DMODEL)       /* 3840 */

// Scratch (device globals: allocation-free rule)
__device__ float g_q[BATCH*NH*DH*SEQ];     // d-major: [b][h][dd][s]
__device__ float g_k[BATCH*NH*DH*SEQ];     // d-major: [b][h][dd][s]
__device__ float g_v[BATCH*NH*SEQ*DH];     // [b][h][s][dd]
__device__ float g_attn[MTOT*DMODEL];      // [b*s][h*64+dd]

// ---------------------------------------------------------------------------
// GEMM 1: qkv = X[4096,1280] @ Wqkv[1280,3840], scatter epilogue into g_q/g_k/g_v
// ---------------------------------------------------------------------------
__global__ __launch_bounds__(256) void qkv_gemm_kernel(
    const float* __restrict__ X, const float* __restrict__ W)
{
    __shared__ float As[8][128];
    __shared__ float Bs[8][128];

    const int tid = threadIdx.x;
    const int m0 = blockIdx.y * 128;
    const int n0 = blockIdx.x * 128;
    const int ty = tid >> 4, tx = tid & 15;

    const int ar = tid >> 1, ac = (tid & 1) * 4;   // A tile load coords
    const int br = tid >> 5, bc = (tid & 31) * 4;  // B tile load coords

    float acc[8][8];
#pragma unroll
    for (int i = 0; i < 8; i++)
#pragma unroll
        for (int j = 0; j < 8; j++) acc[i][j] = 0.f;

    for (int k0 = 0; k0 < DMODEL; k0 += 8) {
        float4 av = *(const float4*)&X[(m0 + ar) * DMODEL + k0 + ac];
        float4 bv = *(const float4*)&W[(k0 + br) * NQKV + n0 + bc];
        As[ac + 0][ar] = av.x; As[ac + 1][ar] = av.y;
        As[ac + 2][ar] = av.z; As[ac + 3][ar] = av.w;
        *(float4*)&Bs[br][bc] = bv;
        __syncthreads();
#pragma unroll
        for (int kk = 0; kk < 8; kk++) {
            float4 a0 = *(const float4*)&As[kk][ty * 8];
            float4 a1 = *(const float4*)&As[kk][ty * 8 + 4];
            float4 b0 = *(const float4*)&Bs[kk][tx * 8];
            float4 b1 = *(const float4*)&Bs[kk][tx * 8 + 4];
            float a[8] = {a0.x,a0.y,a0.z,a0.w,a1.x,a1.y,a1.z,a1.w};
            float b[8] = {b0.x,b0.y,b0.z,b0.w,b1.x,b1.y,b1.z,b1.w};
#pragma unroll
            for (int i = 0; i < 8; i++)
#pragma unroll
                for (int j = 0; j < 8; j++) acc[i][j] += a[i] * b[j];
        }
        __syncthreads();
    }

    // Epilogue: scatter. A 128-wide N tile lies fully inside one of q/k/v
    // (section boundaries at multiples of 1280; 1280 % 128 == 0).
    const int sec = n0 / DMODEL;                 // 0=q 1=k 2=v
    const int rem = n0 - sec * DMODEL + tx * 8;  // feature index within section
    const int h = rem >> 6;
    const int dd0 = rem & 63;                    // multiple of 8

#pragma unroll
    for (int i = 0; i < 8; i++) {
        const int m = m0 + ty * 8 + i;
        const int b = m >> 11, s = m & 2047;
        if (sec == 2) {
            float* dst = &g_v[((b * NH + h) * SEQ + s) * DH + dd0];
            *(float4*)&dst[0] = make_float4(acc[i][0], acc[i][1], acc[i][2], acc[i][3]);
            *(float4*)&dst[4] = make_float4(acc[i][4], acc[i][5], acc[i][6], acc[i][7]);
        } else {
            float* base = (sec == 0 ? g_q : g_k);
            float* dst = &base[((b * NH + h) * DH + dd0) * SEQ + s];
#pragma unroll
            for (int j = 0; j < 8; j++) dst[j * SEQ] = acc[i][j];
        }
    }
}

// ---------------------------------------------------------------------------
// Flash attention: grid (SEQ/64, NH, BATCH), 256 threads.
// Q/K are d-major in global so smem tiles need no transpose.
// smem: Qt[64][64] (Qt[d][r]), Kt[64][64] (Kt[d][c]), Vs[64][64], Ps[64][64]
// ---------------------------------------------------------------------------
__global__ __launch_bounds__(256) void flash_kernel(const float* __restrict__ Mask)
{
    extern __shared__ float sm[];
    float* Qt = sm;
    float* Kt = sm + 4096;
    float* Vs = sm + 8192;
    float* Ps = sm + 12288;

    const int tid = threadIdx.x;
    const int qb = blockIdx.x;   // query block (64 queries)
    const int h  = blockIdx.y;
    const int b  = blockIdx.z;
    const int ty = tid >> 4, tx = tid & 15;

    const float* qp = g_q + (size_t)(b * NH + h) * DH * SEQ;
    const float* kp = g_k + (size_t)(b * NH + h) * DH * SEQ;
    const float* vp = g_v + (size_t)(b * NH + h) * SEQ * DH;

    // Load Q tile (d-major): Qt[dd][r]
#pragma unroll
    for (int t = tid; t < 4096; t += 256) {
        const int dd = t >> 6, r = t & 63;
        Qt[t] = qp[dd * SEQ + qb * 64 + r];
    }

    float acc[4][4];
    float mrun[4], lrun[4];
#pragma unroll
    for (int i = 0; i < 4; i++) {
        mrun[i] = -1e30f; lrun[i] = 0.f;
#pragma unroll
        for (int j = 0; j < 4; j++) acc[i][j] = 0.f;
    }

    const float scale = 0.125f;  // 1/sqrt(64)

    for (int kb = 0; kb < SEQ / 64; kb++) {
        __syncthreads();  // prior iter's PV reads of Vs/Ps done
        // Load K tile (d-major) and V tile
#pragma unroll
        for (int t = tid; t < 4096; t += 256) {
            const int dd = t >> 6, c = t & 63;
            Kt[t] = kp[dd * SEQ + kb * 64 + c];
        }
#pragma unroll
        for (int t = tid; t < 4096; t += 256) {
            const int c = t >> 6, dd = t & 63;
            Vs[t] = vp[(kb * 64 + c) * DH + dd];
        }
        __syncthreads();

        // S = Q * K^T (4x4 micro-tile)
        float s[4][4];
#pragma unroll
        for (int i = 0; i < 4; i++)
#pragma unroll
            for (int j = 0; j < 4; j++) s[i][j] = 0.f;

#pragma unroll 4
        for (int d = 0; d < 64; d++) {
            float4 qa = *(const float4*)&Qt[d * 64 + ty * 4];
            float4 kv = *(const float4*)&Kt[d * 64 + tx * 4];
            float qv[4] = {qa.x, qa.y, qa.z, qa.w};
            float kw[4] = {kv.x, kv.y, kv.z, kv.w};
#pragma unroll
            for (int i = 0; i < 4; i++)
#pragma unroll
                for (int j = 0; j < 4; j++) s[i][j] += qv[i] * kw[j];
        }

        // scale + mask
#pragma unroll
        for (int i = 0; i < 4; i++) {
            const int qi = qb * 64 + ty * 4 + i;
            float4 mk = *(const float4*)&Mask[((size_t)b * SEQ + qi) * SEQ + kb * 64 + tx * 4];
            s[i][0] = s[i][0] * scale + mk.x;
            s[i][1] = s[i][1] * scale + mk.y;
            s[i][2] = s[i][2] * scale + mk.z;
            s[i][3] = s[i][3] * scale + mk.w;
        }

        // Online softmax (row groups = 16 consecutive lanes, shfl_xor <=8)
#pragma unroll
        for (int i = 0; i < 4; i++) {
            float rm = fmaxf(fmaxf(s[i][0], s[i][1]), fmaxf(s[i][2], s[i][3]));
#pragma unroll
            for (int o = 8; o > 0; o >>= 1)
                rm = fmaxf(rm, __shfl_xor_sync(0xffffffffu, rm, o));
            const float mn = fmaxf(mrun[i], rm);
            const float al = __expf(mrun[i] - mn);
            float rs = 0.f;
#pragma unroll
            for (int j = 0; j < 4; j++) {
                const float p = __expf(s[i][j] - mn);
                s[i][j] = p; rs += p;
            }
#pragma unroll
            for (int o = 8; o > 0; o >>= 1)
                rs += __shfl_xor_sync(0xffffffffu, rs, o);
            lrun[i] = lrun[i] * al + rs;
            mrun[i] = mn;
#pragma unroll
            for (int j = 0; j < 4; j++) acc[i][j] *= al;
        }

        // Write P to smem (safe: everyone passed top sync; prev reads done)
#pragma unroll
        for (int i = 0; i < 4; i++)
            *(float4*)&Ps[(ty * 4 + i) * 64 + tx * 4] =
                make_float4(s[i][0], s[i][1], s[i][2], s[i][3]);
        __syncthreads();

        // O += P * V (chunk c by 4 so P loads vectorize)
#pragma unroll 2
        for (int c0 = 0; c0 < 64; c0 += 4) {
            float4 pv[4];
#pragma unroll
            for (int i = 0; i < 4; i++)
                pv[i] = *(const float4*)&Ps[(ty * 4 + i) * 64 + c0];
            float pr[4][4] = {
                {pv[0].x, pv[0].y, pv[0].z, pv[0].w},
                {pv[1].x, pv[1].y, pv[1].z, pv[1].w},
                {pv[2].x, pv[2].y, pv[2].z, pv[2].w},
                {pv[3].x, pv[3].y, pv[3].z, pv[3].w}};
#pragma unroll
            for (int cc = 0; cc < 4; cc++) {
                float4 vv = *(const float4*)&Vs[(c0 + cc) * 64 + tx * 4];
                float vr[4] = {vv.x, vv.y, vv.z, vv.w};
#pragma unroll
                for (int i = 0; i < 4; i++)
#pragma unroll
                    for (int j = 0; j < 4; j++) acc[i][j] += pr[i][cc] * vr[j];
            }
        }
    }

    // Normalize + write: g_attn[b*S+q][h*64+dd]
#pragma unroll
    for (int i = 0; i < 4; i++) {
        const int qi = qb * 64 + ty * 4 + i;
        const float inv = 1.f / lrun[i];
        *(float4*)&g_attn[((size_t)b * SEQ + qi) * DMODEL + h * DH + tx * 4] =
            make_float4(acc[i][0] * inv, acc[i][1] * inv, acc[i][2] * inv, acc[i][3] * inv);
    }
}

// ---------------------------------------------------------------------------
// GEMM 2: out = attn[4096,1280] @ Wout[1280,1280] + b_out
// ---------------------------------------------------------------------------
__global__ __launch_bounds__(256) void out_gemm_kernel(
    const float* __restrict__ W, const float* __restrict__ Bias,
    float* __restrict__ Out)
{
    __shared__ float As[8][128];
    __shared__ float Bs[8][128];

    const int tid = threadIdx.x;
    const int m0 = blockIdx.y * 128;
    const int n0 = blockIdx.x * 128;
    const int ty = tid >> 4, tx = tid & 15;
    const int ar = tid >> 1, ac = (tid & 1) * 4;
    const int br = tid >> 5, bc = (tid & 31) * 4;

    float acc[8][8];
#pragma unroll
    for (int i = 0; i < 8; i++)
#pragma unroll
        for (int j = 0; j < 8; j++) acc[i][j] = 0.f;

    for (int k0 = 0; k0 < DMODEL; k0 += 8) {
        float4 av = *(const float4*)&g_attn[(m0 + ar) * DMODEL + k0 + ac];
        float4 bv = *(const float4*)&W[(k0 + br) * DMODEL + n0 + bc];
        As[ac + 0][ar] = av.x; As[ac + 1][ar] = av.y;
        As[ac + 2][ar] = av.z; As[ac + 3][ar] = av.w;
        *(float4*)&Bs[br][bc] = bv;
        __syncthreads();
#pragma unroll
        for (int kk = 0; kk < 8; kk++) {
            float4 a0 = *(const float4*)&As[kk][ty * 8];
            float4 a1 = *(const float4*)&As[kk][ty * 8 + 4];
            float4 b0 = *(const float4*)&Bs[kk][tx * 8];
            float4 b1 = *(const float4*)&Bs[kk][tx * 8 + 4];
            float a[8] = {a0.x,a0.y,a0.z,a0.w,a1.x,a1.y,a1.z,a1.w};
            float b[8] = {b0.x,b0.y,b0.z,b0.w,b1.x,b1.y,b1.z,b1.w};
#pragma unroll
            for (int i = 0; i < 8; i++)
#pragma unroll
                for (int j = 0; j < 8; j++) acc[i][j] += a[i] * b[j];
        }
        __syncthreads();
    }

    float4 bias0 = *(const float4*)&Bias[n0 + tx * 8];
    float4 bias1 = *(const float4*)&Bias[n0 + tx * 8 + 4];
#pragma unroll
    for (int i = 0; i < 8; i++) {
        const int m = m0 + ty * 8 + i;
        float* dst = &Out[(size_t)m * DMODEL + n0 + tx * 8];
        *(float4*)&dst[0] = make_float4(acc[i][0] + bias0.x, acc[i][1] + bias0.y,
                                        acc[i][2] + bias0.z, acc[i][3] + bias0.w);
        *(float4*)&dst[4] = make_float4(acc[i][4] + bias1.x, acc[i][5] + bias1.y,
                                        acc[i][6] + bias1.z, acc[i][7] + bias1.w);
    }
}

// ---------------------------------------------------------------------------
extern "C" void kernel_launch(void* const* d_in, const int* in_sizes, int n_in,
                              void* d_out, int out_size)
{
    const float* hidden = (const float*)d_in[0];  // (2,1,2048,1280)
    const float* mask   = (const float*)d_in[1];  // (2,1,2048,2048)
    const float* w_qkv  = (const float*)d_in[2];  // (1280,3840)
    const float* w_out  = (const float*)d_in[3];  // (1280,1280)
    const float* b_out  = (const float*)d_in[4];  // (1280,)
    float* out = (float*)d_out;                   // (2,1,2048,1280)

    cudaFuncSetAttribute(flash_kernel,
                         cudaFuncAttributeMaxDynamicSharedMemorySize, 65536);

    qkv_gemm_kernel<<<dim3(NQKV / 128, MTOT / 128), 256>>>(hidden, w_qkv);
    flash_kernel<<<dim3(SEQ / 64, NH, BATCH), 256, 65536>>>(mask);
    out_gemm_kernel<<<dim3(DMODEL / 128, MTOT / 128), 256>>>(w_out, b_out, out);
}

// round 5
// speedup vs baseline: 1.0027x; 1.0027x over previous
#include <cuda_runtime.h>
#include <cuda_bf16.h>
#include <cstdint>

#define NH 20
#define DH 64
#define DMODEL 1280
#define BATCH 2
#define SEQ 2048
#define MTOT (BATCH*SEQ)      /* 4096 */
#define KTOT 3840             /* 3 * 1280 split-K concat */
#define NST 60                /* 3840 / 64 */

// ---------------------------------------------------------------------------
// Device-global scratch (allocation-free rule)
// ---------------------------------------------------------------------------
__device__ float g_q[BATCH*NH*DH*SEQ];        // d-major: [b][h][dd][s]
__device__ float g_k[BATCH*NH*DH*SEQ];        // d-major: [b][h][dd][s]
__device__ float g_v[BATCH*NH*SEQ*DH];        // [b][h][s][dd]
__device__ float g_attn[MTOT*DMODEL];         // [b*s][h*64+dd]
__device__ __nv_bfloat16 g_Abuf[(size_t)MTOT*KTOT];   // [Xh | Xl | Xh]
__device__ __nv_bfloat16 g_Wt[(size_t)3840*KTOT];     // [n][Wh|Wh|Wl]
__device__ __nv_bfloat16 g_W2t[(size_t)1280*KTOT];
__device__ __nv_bfloat16 g_A2buf[(size_t)MTOT*KTOT];  // [Ah | Al | Ah] of attn

// ---------------------------------------------------------------------------
// Baseline-PTX helpers (sm_80-era: valid on compute_103 target)
// ---------------------------------------------------------------------------
__device__ __forceinline__ uint32_t smem_u32(const void* p) {
    uint32_t a;
    asm("{ .reg .u64 t; cvta.to.shared.u64 t, %1; cvt.u32.u64 %0, t; }"
        : "=r"(a) : "l"(p));
    return a;
}
__device__ __forceinline__ uint32_t swz(uint32_t off) {  // SW128 byte swizzle
    return off ^ ((off >> 3) & 0x70);
}

#define CP_ASYNC16(dst, src) \
    asm volatile("cp.async.cg.shared.global [%0], [%1], 16;" :: "r"(dst), "l"(src))
#define CP_COMMIT() asm volatile("cp.async.commit_group;" ::: "memory")
#define CP_WAIT1()  asm volatile("cp.async.wait_group 1;" ::: "memory")
#define CP_WAIT0()  asm volatile("cp.async.wait_group 0;" ::: "memory")

__device__ __forceinline__ void ldmA(uint32_t addr, uint32_t* r) {
    asm volatile("ldmatrix.sync.aligned.m8n8.x4.shared.b16 {%0,%1,%2,%3}, [%4];"
                 : "=r"(r[0]), "=r"(r[1]), "=r"(r[2]), "=r"(r[3]) : "r"(addr));
}
__device__ __forceinline__ void ldmB(uint32_t addr, uint32_t* r) {
    asm volatile("ldmatrix.sync.aligned.m8n8.x2.shared.b16 {%0,%1}, [%2];"
                 : "=r"(r[0]), "=r"(r[1]) : "r"(addr));
}
__device__ __forceinline__ void mma16816(float* c, const uint32_t* a, const uint32_t* b) {
    asm volatile("mma.sync.aligned.m16n8k16.row.col.f32.bf16.bf16.f32 "
                 "{%0,%1,%2,%3}, {%4,%5,%6,%7}, {%8,%9}, {%0,%1,%2,%3};"
                 : "+f"(c[0]), "+f"(c[1]), "+f"(c[2]), "+f"(c[3])
                 : "r"(a[0]), "r"(a[1]), "r"(a[2]), "r"(a[3]),
                   "r"(b[0]), "r"(b[1]));
}

// ---------------------------------------------------------------------------
// Split conversions (fp32 -> bf16 hi/lo sections)
// ---------------------------------------------------------------------------
union BfPack { __nv_bfloat16 h[4]; uint2 u; };

// src [rows][1280] fp32 -> dst [rows][3840] bf16 sections [hi | lo | hi]
__global__ __launch_bounds__(320) void split_rows_kernel(
    const float* __restrict__ src, __nv_bfloat16* __restrict__ dst)
{
    const int m = blockIdx.x;
    const int k4 = threadIdx.x * 4;
    float4 v = *(const float4*)&src[(size_t)m * DMODEL + k4];
    BfPack hi, lo;
    float f[4] = {v.x, v.y, v.z, v.w};
#pragma unroll
    for (int i = 0; i < 4; i++) {
        hi.h[i] = __float2bfloat16(f[i]);
        lo.h[i] = __float2bfloat16(f[i] - __bfloat162float(hi.h[i]));
    }
    __nv_bfloat16* row = dst + (size_t)m * KTOT;
    *(uint2*)&row[k4]            = hi.u;
    *(uint2*)&row[DMODEL + k4]   = lo.u;
    *(uint2*)&row[2*DMODEL + k4] = hi.u;
}

// src W [K=1280][N] fp32 -> dst [N][3840] bf16 sections [hi | hi | lo]
__global__ __launch_bounds__(256) void split_w_kernel(
    const float* __restrict__ src, __nv_bfloat16* __restrict__ dst, int N)
{
    const int idx = blockIdx.x * 256 + threadIdx.x;
    const int n = idx % N;
    const int k4i = idx / N;
    if (k4i >= DMODEL / 4) return;
    const int k = k4i * 4;
    BfPack hi, lo;
#pragma unroll
    for (int i = 0; i < 4; i++) {
        float w = src[(size_t)(k + i) * N + n];
        hi.h[i] = __float2bfloat16(w);
        lo.h[i] = __float2bfloat16(w - __bfloat162float(hi.h[i]));
    }
    __nv_bfloat16* row = dst + (size_t)n * KTOT;
    *(uint2*)&row[k]            = hi.u;
    *(uint2*)&row[DMODEL + k]   = hi.u;
    *(uint2*)&row[2*DMODEL + k] = lo.u;
}

// ---------------------------------------------------------------------------
// mma.sync GEMM: C[128x128] per CTA, 8 warps of 64x32, K'=3840 in 60 BK=64
// stages through a 3-buffer cp.async ring. SW128-swizzled smem tiles.
// mode 0: QKV scatter epilogue (q/k d-major, v row-major)
// mode 1: out = A*B^T + bias
// ---------------------------------------------------------------------------
#define STAGE_BYTES 32768     /* A 16KB + B 16KB */
#define SM_TOTAL (3*STAGE_BYTES)

__global__ __launch_bounds__(256) void gemm_mma_kernel(
    const __nv_bfloat16* __restrict__ A,   // [M][3840]
    const __nv_bfloat16* __restrict__ Bt,  // [N][3840]
    int mode, const float* __restrict__ bias, float* __restrict__ Cout)
{
    extern __shared__ __align__(1024) char smem[];
    const uint32_t sb = smem_u32(smem);
    const int tid = threadIdx.x;
    const int lane = tid & 31, wid = tid >> 5;
    const int wm = wid >> 2, wn = wid & 3;          // warp grid 2 x 4
    const int m0 = blockIdx.y * 128, n0 = blockIdx.x * 128;

    // stage loader: A tile 128x64 bf16 + B tile 128x64 bf16, 16B chunks
    auto load_stage = [&](int s, int buf) {
        const uint32_t base = sb + buf * STAGE_BYTES;
        const __nv_bfloat16* ap = A  + (size_t)m0 * KTOT + s * 64;
        const __nv_bfloat16* bp = Bt + (size_t)n0 * KTOT + s * 64;
#pragma unroll
        for (int i = 0; i < 4; i++) {
            const int t = tid + i * 256;
            const int r = t >> 3, c = t & 7;
            CP_ASYNC16(base + swz(r * 128 + c * 16), ap + (size_t)r * KTOT + c * 8);
        }
#pragma unroll
        for (int i = 0; i < 4; i++) {
            const int t = tid + i * 256;
            const int r = t >> 3, c = t & 7;
            CP_ASYNC16(base + 16384 + swz(r * 128 + c * 16), bp + (size_t)r * KTOT + c * 8);
        }
        CP_COMMIT();
    };

    float acc[4][4][4];
#pragma unroll
    for (int mi = 0; mi < 4; mi++)
#pragma unroll
        for (int ni = 0; ni < 4; ni++)
#pragma unroll
            for (int q = 0; q < 4; q++) acc[mi][ni][q] = 0.f;

    load_stage(0, 0);
    load_stage(1, 1);

    // ldmatrix per-lane address components
    const int arow = lane & 15;               // A: row within 16x16 frag
    const int acol = (lane >> 4) * 8;         // A: k offset (0/8)
    const int brow = lane & 7;                // B: n row within 8-row frag
    const int bcol = ((lane >> 3) & 1) * 8;   // B: k offset (lanes 0-15 used)

#pragma unroll 1
    for (int s = 0; s < NST; s++) {
        if (s + 1 < NST) { CP_WAIT1(); } else { CP_WAIT0(); }
        __syncthreads();
        if (s + 2 < NST) load_stage(s + 2, (s + 2) % 3);

        const uint32_t abase = sb + (s % 3) * STAGE_BYTES;
        const uint32_t bbase = abase + 16384;
#pragma unroll
        for (int kf = 0; kf < 4; kf++) {
            uint32_t a[4][4], b[4][2];
#pragma unroll
            for (int mi = 0; mi < 4; mi++)
                ldmA(abase + swz((wm*64 + mi*16 + arow) * 128 + (kf*16 + acol) * 2), a[mi]);
#pragma unroll
            for (int ni = 0; ni < 4; ni++)
                ldmB(bbase + swz((wn*32 + ni*8 + brow) * 128 + (kf*16 + bcol) * 2), b[ni]);
#pragma unroll
            for (int mi = 0; mi < 4; mi++)
#pragma unroll
                for (int ni = 0; ni < 4; ni++)
                    mma16816(acc[mi][ni], a[mi], b[ni]);
        }
    }

    // ---- epilogue ----
    const int grp = lane >> 2, tig = lane & 3;
#pragma unroll
    for (int mi = 0; mi < 4; mi++) {
#pragma unroll
        for (int half = 0; half < 2; half++) {
            const int r = wm * 64 + mi * 16 + grp + half * 8;
            const int m = m0 + r;
            const int bb = m >> 11, sq = m & 2047;
#pragma unroll
            for (int ni = 0; ni < 4; ni++) {
                const float v0 = acc[mi][ni][half * 2];
                const float v1 = acc[mi][ni][half * 2 + 1];
                const int nglob = n0 + wn * 32 + ni * 8 + tig * 2;
                if (mode == 1) {
                    float2 bv = *(const float2*)&bias[nglob];
                    *(float2*)&Cout[(size_t)m * DMODEL + nglob] =
                        make_float2(v0 + bv.x, v1 + bv.y);
                } else {
                    const int sec = nglob / DMODEL;
                    const int rem = nglob - sec * DMODEL;
                    const int h = rem >> 6, dd = rem & 63;
                    if (sec == 2) {
                        *(float2*)&g_v[(size_t)((bb * NH + h) * SEQ + sq) * DH + dd] =
                            make_float2(v0, v1);
                    } else {
                        float* dst = (sec == 0 ? g_q : g_k) +
                                     ((size_t)((bb * NH + h) * DH + dd)) * SEQ + sq;
                        dst[0] = v0;
                        dst[SEQ] = v1;
                    }
                }
            }
        }
    }
}

// ---------------------------------------------------------------------------
// Flash attention (fp32 SIMT, proven) — next-round target.
// ---------------------------------------------------------------------------
__global__ __launch_bounds__(256) void flash_kernel(const float* __restrict__ Mask)
{
    extern __shared__ float sm[];
    float* Qt = sm;
    float* Kt = sm + 4096;
    float* Vs = sm + 8192;
    float* Ps = sm + 12288;

    const int tid = threadIdx.x;
    const int qb = blockIdx.x;
    const int h  = blockIdx.y;
    const int b  = blockIdx.z;
    const int ty = tid >> 4, tx = tid & 15;

    const float* qp = g_q + (size_t)(b * NH + h) * DH * SEQ;
    const float* kp = g_k + (size_t)(b * NH + h) * DH * SEQ;
    const float* vp = g_v + (size_t)(b * NH + h) * SEQ * DH;

#pragma unroll
    for (int t = tid; t < 4096; t += 256) {
        const int dd = t >> 6, r = t & 63;
        Qt[t] = qp[dd * SEQ + qb * 64 + r];
    }

    float acc[4][4];
    float mrun[4], lrun[4];
#pragma unroll
    for (int i = 0; i < 4; i++) {
        mrun[i] = -1e30f; lrun[i] = 0.f;
#pragma unroll
        for (int j = 0; j < 4; j++) acc[i][j] = 0.f;
    }

    const float scale = 0.125f;

    for (int kb = 0; kb < SEQ / 64; kb++) {
        __syncthreads();
#pragma unroll
        for (int t = tid; t < 4096; t += 256) {
            const int dd = t >> 6, c = t & 63;
            Kt[t] = kp[dd * SEQ + kb * 64 + c];
        }
#pragma unroll
        for (int t = tid; t < 4096; t += 256) {
            const int c = t >> 6, dd = t & 63;
            Vs[t] = vp[(kb * 64 + c) * DH + dd];
        }
        __syncthreads();

        float s[4][4];
#pragma unroll
        for (int i = 0; i < 4; i++)
#pragma unroll
            for (int j = 0; j < 4; j++) s[i][j] = 0.f;

#pragma unroll 4
        for (int d = 0; d < 64; d++) {
            float4 qa = *(const float4*)&Qt[d * 64 + ty * 4];
            float4 kv = *(const float4*)&Kt[d * 64 + tx * 4];
            float qv[4] = {qa.x, qa.y, qa.z, qa.w};
            float kw[4] = {kv.x, kv.y, kv.z, kv.w};
#pragma unroll
            for (int i = 0; i < 4; i++)
#pragma unroll
                for (int j = 0; j < 4; j++) s[i][j] += qv[i] * kw[j];
        }

#pragma unroll
        for (int i = 0; i < 4; i++) {
            const int qi = qb * 64 + ty * 4 + i;
            float4 mk = *(const float4*)&Mask[((size_t)b * SEQ + qi) * SEQ + kb * 64 + tx * 4];
            s[i][0] = s[i][0] * scale + mk.x;
            s[i][1] = s[i][1] * scale + mk.y;
            s[i][2] = s[i][2] * scale + mk.z;
            s[i][3] = s[i][3] * scale + mk.w;
        }

#pragma unroll
        for (int i = 0; i < 4; i++) {
            float rm = fmaxf(fmaxf(s[i][0], s[i][1]), fmaxf(s[i][2], s[i][3]));
#pragma unroll
            for (int o = 8; o > 0; o >>= 1)
                rm = fmaxf(rm, __shfl_xor_sync(0xffffffffu, rm, o));
            const float mn = fmaxf(mrun[i], rm);
            const float al = __expf(mrun[i] - mn);
            float rs = 0.f;
#pragma unroll
            for (int j = 0; j < 4; j++) {
                const float p = __expf(s[i][j] - mn);
                s[i][j] = p; rs += p;
            }
#pragma unroll
            for (int o = 8; o > 0; o >>= 1)
                rs += __shfl_xor_sync(0xffffffffu, rs, o);
            lrun[i] = lrun[i] * al + rs;
            mrun[i] = mn;
#pragma unroll
            for (int j = 0; j < 4; j++) acc[i][j] *= al;
        }

#pragma unroll
        for (int i = 0; i < 4; i++)
            *(float4*)&Ps[(ty * 4 + i) * 64 + tx * 4] =
                make_float4(s[i][0], s[i][1], s[i][2], s[i][3]);
        __syncthreads();

#pragma unroll 2
        for (int c0 = 0; c0 < 64; c0 += 4) {
            float4 pv[4];
#pragma unroll
            for (int i = 0; i < 4; i++)
                pv[i] = *(const float4*)&Ps[(ty * 4 + i) * 64 + c0];
            float pr[4][4] = {
                {pv[0].x, pv[0].y, pv[0].z, pv[0].w},
                {pv[1].x, pv[1].y, pv[1].z, pv[1].w},
                {pv[2].x, pv[2].y, pv[2].z, pv[2].w},
                {pv[3].x, pv[3].y, pv[3].z, pv[3].w}};
#pragma unroll
            for (int cc = 0; cc < 4; cc++) {
                float4 vv = *(const float4*)&Vs[(c0 + cc) * 64 + tx * 4];
                float vr[4] = {vv.x, vv.y, vv.z, vv.w};
#pragma unroll
                for (int i = 0; i < 4; i++)
#pragma unroll
                    for (int j = 0; j < 4; j++) acc[i][j] += pr[i][cc] * vr[j];
            }
        }
    }

#pragma unroll
    for (int i = 0; i < 4; i++) {
        const int qi = qb * 64 + ty * 4 + i;
        const float inv = 1.f / lrun[i];
        *(float4*)&g_attn[((size_t)b * SEQ + qi) * DMODEL + h * DH + tx * 4] =
            make_float4(acc[i][0] * inv, acc[i][1] * inv, acc[i][2] * inv, acc[i][3] * inv);
    }
}

// ---------------------------------------------------------------------------
extern "C" void kernel_launch(void* const* d_in, const int* in_sizes, int n_in,
                              void* d_out, int out_size)
{
    const float* hidden = (const float*)d_in[0];
    const float* mask   = (const float*)d_in[1];
    const float* w_qkv  = (const float*)d_in[2];
    const float* w_out  = (const float*)d_in[3];
    const float* b_out  = (const float*)d_in[4];
    float* out = (float*)d_out;

    cudaFuncSetAttribute(flash_kernel,
                         cudaFuncAttributeMaxDynamicSharedMemorySize, 65536);
    cudaFuncSetAttribute(gemm_mma_kernel,
                         cudaFuncAttributeMaxDynamicSharedMemorySize, SM_TOTAL);

    __nv_bfloat16 *abuf, *wt, *w2t, *a2buf;
    float* attn;
    cudaGetSymbolAddress((void**)&abuf, g_Abuf);
    cudaGetSymbolAddress((void**)&wt, g_Wt);
    cudaGetSymbolAddress((void**)&w2t, g_W2t);
    cudaGetSymbolAddress((void**)&a2buf, g_A2buf);
    cudaGetSymbolAddress((void**)&attn, g_attn);

    // 1. split/convert inputs to bf16 hi/lo concat form
    split_rows_kernel<<<MTOT, 320>>>(hidden, abuf);
    split_w_kernel<<<(3840 * 320 + 255) / 256, 256>>>(w_qkv, wt, 3840);
    split_w_kernel<<<(1280 * 320 + 255) / 256, 256>>>(w_out, w2t, 1280);

    // 2. QKV projection on tensor cores (mma.sync)
    gemm_mma_kernel<<<dim3(3840 / 128, MTOT / 128), 256, SM_TOTAL>>>(
        abuf, wt, 0, nullptr, nullptr);

    // 3. attention
    flash_kernel<<<dim3(SEQ / 64, NH, BATCH), 256, 65536>>>(mask);

    // 4. split attn rows, out-projection on tensor cores
    split_rows_kernel<<<MTOT, 320>>>(attn, a2buf);
    gemm_mma_kernel<<<dim3(1280 / 128, MTOT / 128), 256, SM_TOTAL>>>(
        a2buf, w2t, 1, b_out, out);
}

// round 6
// speedup vs baseline: 2.8541x; 2.8463x over previous
#include <cuda_runtime.h>
#include <cuda_bf16.h>
#include <cstdint>

#define NH 20
#define DH 64
#define DMODEL 1280
#define BATCH 2
#define SEQ 2048
#define MTOT (BATCH*SEQ)      /* 4096 */
#define KTOT 3840             /* 3 * 1280 split-K concat */
#define NST 60                /* 3840 / 64 */

// ---------------------------------------------------------------------------
// Device-global scratch (allocation-free rule)
// ---------------------------------------------------------------------------
__device__ __nv_bfloat16 g_qh[BATCH*NH*SEQ*DH];  // [bh][s][dd]
__device__ __nv_bfloat16 g_ql[BATCH*NH*SEQ*DH];
__device__ __nv_bfloat16 g_kh[BATCH*NH*SEQ*DH];  // [bh][s][dd]
__device__ __nv_bfloat16 g_kl[BATCH*NH*SEQ*DH];
__device__ __nv_bfloat16 g_vh[BATCH*NH*DH*SEQ];  // d-major [bh][dd][s]
__device__ __nv_bfloat16 g_vl[BATCH*NH*DH*SEQ];
__device__ __nv_bfloat16 g_Abuf[(size_t)MTOT*KTOT];   // [Xh | Xl | Xh]
__device__ __nv_bfloat16 g_Wt[(size_t)3840*KTOT];     // [n][Wh|Wh|Wl]
__device__ __nv_bfloat16 g_W2t[(size_t)1280*KTOT];
__device__ __nv_bfloat16 g_A2buf[(size_t)MTOT*KTOT];  // [Ah | Al | Ah] of attn

// ---------------------------------------------------------------------------
// Baseline-PTX helpers (sm_80-era: valid on compute_103 target)
// ---------------------------------------------------------------------------
__device__ __forceinline__ uint32_t smem_u32(const void* p) {
    uint32_t a;
    asm("{ .reg .u64 t; cvta.to.shared.u64 t, %1; cvt.u32.u64 %0, t; }"
        : "=r"(a) : "l"(p));
    return a;
}
__device__ __forceinline__ uint32_t swz(uint32_t off) {  // SW128 byte swizzle
    return off ^ ((off >> 3) & 0x70);
}

#define CP_ASYNC16(dst, src) \
    asm volatile("cp.async.cg.shared.global [%0], [%1], 16;" :: "r"(dst), "l"(src))
#define CP_COMMIT() asm volatile("cp.async.commit_group;" ::: "memory")
#define CP_WAIT1()  asm volatile("cp.async.wait_group 1;" ::: "memory")
#define CP_WAIT0()  asm volatile("cp.async.wait_group 0;" ::: "memory")

__device__ __forceinline__ void ldm4(uint32_t addr, uint32_t* r) {
    asm volatile("ldmatrix.sync.aligned.m8n8.x4.shared.b16 {%0,%1,%2,%3}, [%4];"
                 : "=r"(r[0]), "=r"(r[1]), "=r"(r[2]), "=r"(r[3]) : "r"(addr));
}
__device__ __forceinline__ void ldmB(uint32_t addr, uint32_t* r) {
    asm volatile("ldmatrix.sync.aligned.m8n8.x2.shared.b16 {%0,%1}, [%2];"
                 : "=r"(r[0]), "=r"(r[1]) : "r"(addr));
}
__device__ __forceinline__ void mma16816(float* c, const uint32_t* a, const uint32_t* b) {
    asm volatile("mma.sync.aligned.m16n8k16.row.col.f32.bf16.bf16.f32 "
                 "{%0,%1,%2,%3}, {%4,%5,%6,%7}, {%8,%9}, {%0,%1,%2,%3};"
                 : "+f"(c[0]), "+f"(c[1]), "+f"(c[2]), "+f"(c[3])
                 : "r"(a[0]), "r"(a[1]), "r"(a[2]), "r"(a[3]),
                   "r"(b[0]), "r"(b[1]));
}

__device__ __forceinline__ uint32_t pack_bf(__nv_bfloat16 x, __nv_bfloat16 y) {
    __nv_bfloat162 t = __halves2bfloat162(x, y);
    return *reinterpret_cast<uint32_t*>(&t);
}

// ---------------------------------------------------------------------------
// Split conversions (fp32 -> bf16 hi/lo sections)
// ---------------------------------------------------------------------------
union BfPack { __nv_bfloat16 h[4]; uint2 u; };

// src [rows][1280] fp32 -> dst [rows][3840] bf16 sections [hi | lo | hi]
__global__ __launch_bounds__(320) void split_rows_kernel(
    const float* __restrict__ src, __nv_bfloat16* __restrict__ dst)
{
    const int m = blockIdx.x;
    const int k4 = threadIdx.x * 4;
    float4 v = *(const float4*)&src[(size_t)m * DMODEL + k4];
    BfPack hi, lo;
    float f[4] = {v.x, v.y, v.z, v.w};
#pragma unroll
    for (int i = 0; i < 4; i++) {
        hi.h[i] = __float2bfloat16(f[i]);
        lo.h[i] = __float2bfloat16(f[i] - __bfloat162float(hi.h[i]));
    }
    __nv_bfloat16* row = dst + (size_t)m * KTOT;
    *(uint2*)&row[k4]            = hi.u;
    *(uint2*)&row[DMODEL + k4]   = lo.u;
    *(uint2*)&row[2*DMODEL + k4] = hi.u;
}

// src W [K=1280][N] fp32 -> dst [N][3840] bf16 sections [hi | hi | lo]
__global__ __launch_bounds__(256) void split_w_kernel(
    const float* __restrict__ src, __nv_bfloat16* __restrict__ dst, int N)
{
    const int idx = blockIdx.x * 256 + threadIdx.x;
    const int n = idx % N;
    const int k4i = idx / N;
    if (k4i >= DMODEL / 4) return;
    const int k = k4i * 4;
    BfPack hi, lo;
#pragma unroll
    for (int i = 0; i < 4; i++) {
        float w = src[(size_t)(k + i) * N + n];
        hi.h[i] = __float2bfloat16(w);
        lo.h[i] = __float2bfloat16(w - __bfloat162float(hi.h[i]));
    }
    __nv_bfloat16* row = dst + (size_t)n * KTOT;
    *(uint2*)&row[k]            = hi.u;
    *(uint2*)&row[DMODEL + k]   = hi.u;
    *(uint2*)&row[2*DMODEL + k] = lo.u;
}

// ---------------------------------------------------------------------------
// mma.sync GEMM: C[128x128] per CTA, 8 warps of 64x32, K'=3840 in 60 BK=64
// stages through a 3-buffer cp.async ring.
// mode 0: QKV epilogue -> bf16 hi/lo q/k (row-major) and v (d-major)
// mode 1: out = A*B^T + bias (fp32)
// ---------------------------------------------------------------------------
#define STAGE_BYTES 32768     /* A 16KB + B 16KB */
#define SM_TOTAL (3*STAGE_BYTES)

__global__ __launch_bounds__(256) void gemm_mma_kernel(
    const __nv_bfloat16* __restrict__ A,   // [M][3840]
    const __nv_bfloat16* __restrict__ Bt,  // [N][3840]
    int mode, const float* __restrict__ bias, float* __restrict__ Cout)
{
    extern __shared__ __align__(1024) char smem[];
    const uint32_t sb = smem_u32(smem);
    const int tid = threadIdx.x;
    const int lane = tid & 31, wid = tid >> 5;
    const int wm = wid >> 2, wn = wid & 3;          // warp grid 2 x 4
    const int m0 = blockIdx.y * 128, n0 = blockIdx.x * 128;

    auto load_stage = [&](int s, int buf) {
        const uint32_t base = sb + buf * STAGE_BYTES;
        const __nv_bfloat16* ap = A  + (size_t)m0 * KTOT + s * 64;
        const __nv_bfloat16* bp = Bt + (size_t)n0 * KTOT + s * 64;
#pragma unroll
        for (int i = 0; i < 4; i++) {
            const int t = tid + i * 256;
            const int r = t >> 3, c = t & 7;
            CP_ASYNC16(base + swz(r * 128 + c * 16), ap + (size_t)r * KTOT + c * 8);
        }
#pragma unroll
        for (int i = 0; i < 4; i++) {
            const int t = tid + i * 256;
            const int r = t >> 3, c = t & 7;
            CP_ASYNC16(base + 16384 + swz(r * 128 + c * 16), bp + (size_t)r * KTOT + c * 8);
        }
        CP_COMMIT();
    };

    float acc[4][4][4];
#pragma unroll
    for (int mi = 0; mi < 4; mi++)
#pragma unroll
        for (int ni = 0; ni < 4; ni++)
#pragma unroll
            for (int q = 0; q < 4; q++) acc[mi][ni][q] = 0.f;

    load_stage(0, 0);
    load_stage(1, 1);

    const int arow = lane & 15;
    const int acol = (lane >> 4) * 8;
    const int brow = lane & 7;
    const int bcol = ((lane >> 3) & 1) * 8;

#pragma unroll 1
    for (int s = 0; s < NST; s++) {
        if (s + 1 < NST) { CP_WAIT1(); } else { CP_WAIT0(); }
        __syncthreads();
        if (s + 2 < NST) load_stage(s + 2, (s + 2) % 3);

        const uint32_t abase = sb + (s % 3) * STAGE_BYTES;
        const uint32_t bbase = abase + 16384;
#pragma unroll
        for (int kf = 0; kf < 4; kf++) {
            uint32_t a[4][4], b[4][2];
#pragma unroll
            for (int mi = 0; mi < 4; mi++)
                ldm4(abase + swz((wm*64 + mi*16 + arow) * 128 + (kf*16 + acol) * 2), a[mi]);
#pragma unroll
            for (int ni = 0; ni < 4; ni++)
                ldmB(bbase + swz((wn*32 + ni*8 + brow) * 128 + (kf*16 + bcol) * 2), b[ni]);
#pragma unroll
            for (int mi = 0; mi < 4; mi++)
#pragma unroll
                for (int ni = 0; ni < 4; ni++)
                    mma16816(acc[mi][ni], a[mi], b[ni]);
        }
    }

    // ---- epilogue ----
    const int grp = lane >> 2, tig = lane & 3;
#pragma unroll
    for (int mi = 0; mi < 4; mi++) {
#pragma unroll
        for (int half = 0; half < 2; half++) {
            const int r = wm * 64 + mi * 16 + grp + half * 8;
            const int m = m0 + r;
            const int bb = m >> 11, sq = m & 2047;
#pragma unroll
            for (int ni = 0; ni < 4; ni++) {
                const float v0 = acc[mi][ni][half * 2];
                const float v1 = acc[mi][ni][half * 2 + 1];
                const int nglob = n0 + wn * 32 + ni * 8 + tig * 2;
                if (mode == 1) {
                    float2 bv = *(const float2*)&bias[nglob];
                    *(float2*)&Cout[(size_t)m * DMODEL + nglob] =
                        make_float2(v0 + bv.x, v1 + bv.y);
                } else {
                    const int sec = nglob / DMODEL;
                    const int rem = nglob - sec * DMODEL;
                    const int hh = rem >> 6, dd = rem & 63;
                    const int bh = bb * NH + hh;
                    __nv_bfloat16 h0 = __float2bfloat16(v0);
                    __nv_bfloat16 h1 = __float2bfloat16(v1);
                    __nv_bfloat16 e0 = __float2bfloat16(v0 - __bfloat162float(h0));
                    __nv_bfloat16 e1 = __float2bfloat16(v1 - __bfloat162float(h1));
                    if (sec == 2) {
                        const size_t a0 = ((size_t)bh * DH + dd) * SEQ + sq;
                        const size_t a1 = ((size_t)bh * DH + dd + 1) * SEQ + sq;
                        g_vh[a0] = h0; g_vh[a1] = h1;
                        g_vl[a0] = e0; g_vl[a1] = e1;
                    } else {
                        const size_t a = ((size_t)bh * SEQ + sq) * DH + dd;
                        if (sec == 0) {
                            *(uint32_t*)&g_qh[a] = pack_bf(h0, h1);
                            *(uint32_t*)&g_ql[a] = pack_bf(e0, e1);
                        } else {
                            *(uint32_t*)&g_kh[a] = pack_bf(h0, h1);
                            *(uint32_t*)&g_kl[a] = pack_bf(e0, e1);
                        }
                    }
                }
            }
        }
    }
}

// ---------------------------------------------------------------------------
// Tensor-core flash attention.
// CTA: 128 queries x one (b,h); 8 warps, each M=16, N=64. 32 key tiles of 64.
// smem: Qh 16KB | Ql 16KB | 2 stages x {Kh,Kl,Vh,Vl each 8KB} = 96KB.
// Writes normalized output as split bf16 [Ah|Al|Ah] rows of g_A2buf.
// ---------------------------------------------------------------------------
#define FSM_TOTAL 98304

__global__ __launch_bounds__(256, 2) void flash_mma_kernel(const float* __restrict__ Mask)
{
    extern __shared__ __align__(1024) char fsm[];
    const uint32_t sb = smem_u32(fsm);
    const int tid = threadIdx.x, lane = tid & 31, wid = tid >> 5;
    const int grp = lane >> 2, tig = lane & 3;
    const int qb = blockIdx.x, h = blockIdx.y, b = blockIdx.z;
    const int bh = b * NH + h;

    const __nv_bfloat16* qhp = g_qh + ((size_t)bh * SEQ + qb * 128) * DH;
    const __nv_bfloat16* qlp = g_ql + ((size_t)bh * SEQ + qb * 128) * DH;
    const __nv_bfloat16* khp = g_kh + (size_t)bh * SEQ * DH;
    const __nv_bfloat16* klp = g_kl + (size_t)bh * SEQ * DH;
    const __nv_bfloat16* vhp = g_vh + (size_t)bh * DH * SEQ;
    const __nv_bfloat16* vlp = g_vl + (size_t)bh * DH * SEQ;

    // Q tiles (hi+lo), 128 rows x 128B each
#pragma unroll
    for (int i = 0; i < 4; i++) {
        const int t = tid + i * 256;
        const int r = t >> 3, c = t & 7;
        const uint32_t d = swz(r * 128 + c * 16);
        CP_ASYNC16(sb + d,         qhp + (size_t)r * DH + c * 8);
        CP_ASYNC16(sb + 16384 + d, qlp + (size_t)r * DH + c * 8);
    }

    auto load_kv = [&](int kb, int buf) {
        const uint32_t base = sb + 32768 + buf * 32768;
#pragma unroll
        for (int i = 0; i < 2; i++) {
            const int t = tid + i * 256;
            const int r = t >> 3, c = t & 7;
            const uint32_t d = swz(r * 128 + c * 16);
            CP_ASYNC16(base + d,         khp + (size_t)(kb * 64 + r) * DH + c * 8);
            CP_ASYNC16(base + 8192 + d,  klp + (size_t)(kb * 64 + r) * DH + c * 8);
            CP_ASYNC16(base + 16384 + d, vhp + (size_t)r * SEQ + kb * 64 + c * 8);
            CP_ASYNC16(base + 24576 + d, vlp + (size_t)r * SEQ + kb * 64 + c * 8);
        }
        CP_COMMIT();
    };
    load_kv(0, 0);   // group 0 = Q + stage0
    load_kv(1, 1);   // group 1 = stage1

    float O[8][4];
#pragma unroll
    for (int nf = 0; nf < 8; nf++)
#pragma unroll
        for (int q = 0; q < 4; q++) O[nf][q] = 0.f;
    float m0s = -1e30f, m1s = -1e30f, l0 = 0.f, l1 = 0.f;

    const int qrow0 = qb * 128 + wid * 16 + grp;
    const float* mk0 = Mask + ((size_t)b * SEQ + qrow0) * SEQ;
    const float* mk1 = mk0 + 8 * SEQ;

    const int arow = lane & 15;
    const int acol = (lane >> 4) * 8;
    const int b4row = ((lane >> 4) & 1) * 8 + (lane & 7);   // x4 B: rows for 2 n-frags
    const int b4col = ((lane >> 3) & 1) * 8;

    const float SCL2E = 0.125f * 1.44269504f;
    const float L2E = 1.44269504f;

#pragma unroll 1
    for (int kb = 0; kb < 32; kb++) {
        if (kb < 31) { CP_WAIT1(); } else { CP_WAIT0(); }
        __syncthreads();
        const uint32_t kbase = sb + 32768 + (kb & 1) * 32768;

        // ---- S = Qh Kh^T + Ql Kh^T + Qh Kl^T ----
        float S[8][4];
#pragma unroll
        for (int nf = 0; nf < 8; nf++)
#pragma unroll
            for (int q = 0; q < 4; q++) S[nf][q] = 0.f;

#pragma unroll
        for (int kf = 0; kf < 4; kf++) {
            uint32_t aqh[4], aql[4];
            const uint32_t qoff = swz((wid * 16 + arow) * 128 + (kf * 16 + acol) * 2);
            ldm4(sb + qoff, aqh);
            ldm4(sb + 16384 + qoff, aql);
#pragma unroll
            for (int n2 = 0; n2 < 4; n2++) {
                uint32_t kh4[4], kl4[4];
                const uint32_t off = swz((n2 * 16 + b4row) * 128 + (kf * 16 + b4col) * 2);
                ldm4(kbase + off, kh4);
                ldm4(kbase + 8192 + off, kl4);
                mma16816(S[n2*2],   aqh, kh4);
                mma16816(S[n2*2],   aql, kh4);
                mma16816(S[n2*2],   aqh, kl4);
                mma16816(S[n2*2+1], aqh, kh4 + 2);
                mma16816(S[n2*2+1], aql, kh4 + 2);
                mma16816(S[n2*2+1], aqh, kl4 + 2);
            }
        }

        // ---- scale + mask (log2 domain) ----
        const float* mr0 = mk0 + kb * 64;
        const float* mr1 = mk1 + kb * 64;
#pragma unroll
        for (int nf = 0; nf < 8; nf++) {
            float2 u = *(const float2*)&mr0[nf * 8 + tig * 2];
            float2 w = *(const float2*)&mr1[nf * 8 + tig * 2];
            S[nf][0] = fmaf(S[nf][0], SCL2E, u.x * L2E);
            S[nf][1] = fmaf(S[nf][1], SCL2E, u.y * L2E);
            S[nf][2] = fmaf(S[nf][2], SCL2E, w.x * L2E);
            S[nf][3] = fmaf(S[nf][3], SCL2E, w.y * L2E);
        }

        // ---- online softmax (rows grp / grp+8, reduce over tig lanes) ----
        float rm0 = -1e30f, rm1 = -1e30f;
#pragma unroll
        for (int nf = 0; nf < 8; nf++) {
            rm0 = fmaxf(rm0, fmaxf(S[nf][0], S[nf][1]));
            rm1 = fmaxf(rm1, fmaxf(S[nf][2], S[nf][3]));
        }
        rm0 = fmaxf(rm0, __shfl_xor_sync(0xffffffffu, rm0, 1));
        rm0 = fmaxf(rm0, __shfl_xor_sync(0xffffffffu, rm0, 2));
        rm1 = fmaxf(rm1, __shfl_xor_sync(0xffffffffu, rm1, 1));
        rm1 = fmaxf(rm1, __shfl_xor_sync(0xffffffffu, rm1, 2));
        const float mn0 = fmaxf(m0s, rm0), mn1 = fmaxf(m1s, rm1);
        const float al0 = exp2f(m0s - mn0), al1 = exp2f(m1s - mn1);
        m0s = mn0; m1s = mn1;
        float rs0 = 0.f, rs1 = 0.f;
#pragma unroll
        for (int nf = 0; nf < 8; nf++) {
            S[nf][0] = exp2f(S[nf][0] - mn0);
            S[nf][1] = exp2f(S[nf][1] - mn0);
            S[nf][2] = exp2f(S[nf][2] - mn1);
            S[nf][3] = exp2f(S[nf][3] - mn1);
            rs0 += S[nf][0] + S[nf][1];
            rs1 += S[nf][2] + S[nf][3];
        }
        rs0 += __shfl_xor_sync(0xffffffffu, rs0, 1);
        rs0 += __shfl_xor_sync(0xffffffffu, rs0, 2);
        rs1 += __shfl_xor_sync(0xffffffffu, rs1, 1);
        rs1 += __shfl_xor_sync(0xffffffffu, rs1, 2);
        l0 = l0 * al0 + rs0;
        l1 = l1 * al1 + rs1;
#pragma unroll
        for (int nf = 0; nf < 8; nf++) {
            O[nf][0] *= al0; O[nf][1] *= al0;
            O[nf][2] *= al1; O[nf][3] *= al1;
        }

        // ---- O += Ph Vh + Pl Vh + Ph Vl (P frags built from S in registers) ----
#pragma unroll
        for (int kc = 0; kc < 4; kc++) {
            uint32_t phi[4], plo[4];
#pragma unroll
            for (int half = 0; half < 2; half++) {
                const int nf = kc * 2 + half;      // S frag supplying k = kc*16 + half*8
                const float x0 = S[nf][0], y0 = S[nf][1];
                const float x1 = S[nf][2], y1 = S[nf][3];
                __nv_bfloat16 hx0 = __float2bfloat16(x0), hy0 = __float2bfloat16(y0);
                __nv_bfloat16 hx1 = __float2bfloat16(x1), hy1 = __float2bfloat16(y1);
                phi[half * 2 + 0] = pack_bf(hx0, hy0);   // row grp,   k half*8+tig*2
                phi[half * 2 + 1] = pack_bf(hx1, hy1);   // row grp+8
                plo[half * 2 + 0] = pack_bf(
                    __float2bfloat16(x0 - __bfloat162float(hx0)),
                    __float2bfloat16(y0 - __bfloat162float(hy0)));
                plo[half * 2 + 1] = pack_bf(
                    __float2bfloat16(x1 - __bfloat162float(hx1)),
                    __float2bfloat16(y1 - __bfloat162float(hy1)));
            }
            // NOTE: A frag ordering is {row grp k0-8, row grp+8 k0-8, row grp k8-16, row grp+8 k8-16}
            uint32_t pa_h[4] = {phi[0], phi[1], phi[2], phi[3]};
            uint32_t pa_l[4] = {plo[0], plo[1], plo[2], plo[3]};
#pragma unroll
            for (int n2 = 0; n2 < 4; n2++) {
                uint32_t vh4[4], vl4[4];
                const uint32_t off = swz((n2 * 16 + b4row) * 128 + (kc * 16 + b4col) * 2);
                ldm4(kbase + 16384 + off, vh4);
                ldm4(kbase + 24576 + off, vl4);
                mma16816(O[n2*2],   pa_h, vh4);
                mma16816(O[n2*2],   pa_l, vh4);
                mma16816(O[n2*2],   pa_h, vl4);
                mma16816(O[n2*2+1], pa_h, vh4 + 2);
                mma16816(O[n2*2+1], pa_l, vh4 + 2);
                mma16816(O[n2*2+1], pa_h, vl4 + 2);
            }
        }

        __syncthreads();
        if (kb + 2 < 32) load_kv(kb + 2, kb & 1);
    }

    // ---- epilogue: write normalized O as [Ah|Al|Ah] split rows of g_A2buf ----
    const float inv0 = 1.f / l0, inv1 = 1.f / l1;
    __nv_bfloat16* o0 = g_A2buf + ((size_t)b * SEQ + qrow0) * KTOT;
    __nv_bfloat16* o1 = o0 + (size_t)8 * KTOT;
#pragma unroll
    for (int nf = 0; nf < 8; nf++) {
        const int col = h * 64 + nf * 8 + tig * 2;
        {
            const float x = O[nf][0] * inv0, y = O[nf][1] * inv0;
            __nv_bfloat16 hx = __float2bfloat16(x), hy = __float2bfloat16(y);
            const uint32_t hi = pack_bf(hx, hy);
            const uint32_t lo = pack_bf(__float2bfloat16(x - __bfloat162float(hx)),
                                        __float2bfloat16(y - __bfloat162float(hy)));
            *(uint32_t*)&o0[col]          = hi;
            *(uint32_t*)&o0[DMODEL + col] = lo;
            *(uint32_t*)&o0[2*DMODEL + col] = hi;
        }
        {
            const float x = O[nf][2] * inv1, y = O[nf][3] * inv1;
            __nv_bfloat16 hx = __float2bfloat16(x), hy = __float2bfloat16(y);
            const uint32_t hi = pack_bf(hx, hy);
            const uint32_t lo = pack_bf(__float2bfloat16(x - __bfloat162float(hx)),
                                        __float2bfloat16(y - __bfloat162float(hy)));
            *(uint32_t*)&o1[col]          = hi;
            *(uint32_t*)&o1[DMODEL + col] = lo;
            *(uint32_t*)&o1[2*DMODEL + col] = hi;
        }
    }
}

// ---------------------------------------------------------------------------
extern "C" void kernel_launch(void* const* d_in, const int* in_sizes, int n_in,
                              void* d_out, int out_size)
{
    const float* hidden = (const float*)d_in[0];
    const float* mask   = (const float*)d_in[1];
    const float* w_qkv  = (const float*)d_in[2];
    const float* w_out  = (const float*)d_in[3];
    const float* b_out  = (const float*)d_in[4];
    float* out = (float*)d_out;

    cudaFuncSetAttribute(gemm_mma_kernel,
                         cudaFuncAttributeMaxDynamicSharedMemorySize, SM_TOTAL);
    cudaFuncSetAttribute(flash_mma_kernel,
                         cudaFuncAttributeMaxDynamicSharedMemorySize, FSM_TOTAL);

    __nv_bfloat16 *abuf, *wt, *w2t, *a2buf;
    cudaGetSymbolAddress((void**)&abuf, g_Abuf);
    cudaGetSymbolAddress((void**)&wt, g_Wt);
    cudaGetSymbolAddress((void**)&w2t, g_W2t);
    cudaGetSymbolAddress((void**)&a2buf, g_A2buf);

    // 1. split/convert inputs to bf16 hi/lo concat form
    split_rows_kernel<<<MTOT, 320>>>(hidden, abuf);
    split_w_kernel<<<(3840 * 320 + 255) / 256, 256>>>(w_qkv, wt, 3840);
    split_w_kernel<<<(1280 * 320 + 255) / 256, 256>>>(w_out, w2t, 1280);

    // 2. QKV projection (tensor cores) -> split bf16 q/k/v
    gemm_mma_kernel<<<dim3(3840 / 128, MTOT / 128), 256, SM_TOTAL>>>(
        abuf, wt, 0, nullptr, nullptr);

    // 3. tensor-core flash attention -> split bf16 attn rows
    flash_mma_kernel<<<dim3(SEQ / 128, NH, BATCH), 256, FSM_TOTAL>>>(mask);

    // 4. out-projection (tensor cores)
    gemm_mma_kernel<<<dim3(1280 / 128, MTOT / 128), 256, SM_TOTAL>>>(
        a2buf, w2t, 1, b_out, out);
}

// round 7
// speedup vs baseline: 3.3376x; 1.1694x over previous
#include <cuda_runtime.h>
#include <cuda_bf16.h>
#include <cuda_fp16.h>
#include <cstdint>

#define NH 20
#define DH 64
#define DMODEL 1280
#define BATCH 2
#define SEQ 2048
#define MTOT (BATCH*SEQ)      /* 4096 */
#define KTOT 3840             /* 3 * 1280 split-K concat */
#define NST 60                /* 3840 / 64 */

// ---------------------------------------------------------------------------
// Device-global scratch (allocation-free rule)
// ---------------------------------------------------------------------------
__device__ __half g_qh[BATCH*NH*SEQ*DH];         // [bh][s][dd] fp16 (hi only)
__device__ __half g_kh[BATCH*NH*SEQ*DH];         // [bh][s][dd] fp16 (hi only)
__device__ __half g_vh[BATCH*NH*DH*SEQ];         // d-major [bh][dd][s]
__device__ __half g_vl[BATCH*NH*DH*SEQ];         // fp16 residual of V
__device__ __nv_bfloat16 g_Abuf[(size_t)MTOT*KTOT];   // [Xh | Xl | Xh]
__device__ __nv_bfloat16 g_Wt[(size_t)3840*KTOT];     // [n][Wh|Wh|Wl]
__device__ __nv_bfloat16 g_W2t[(size_t)1280*KTOT];
__device__ __nv_bfloat16 g_A2buf[(size_t)MTOT*KTOT];  // [Ah | Al | Ah] of attn
__device__ unsigned char g_mflag[BATCH*32*32];        // mask 64x64 tile nonzero flags

// ---------------------------------------------------------------------------
// Baseline-PTX helpers
// ---------------------------------------------------------------------------
__device__ __forceinline__ uint32_t smem_u32(const void* p) {
    uint32_t a;
    asm("{ .reg .u64 t; cvta.to.shared.u64 t, %1; cvt.u32.u64 %0, t; }"
        : "=r"(a) : "l"(p));
    return a;
}
__device__ __forceinline__ uint32_t swz(uint32_t off) {  // SW128 byte swizzle
    return off ^ ((off >> 3) & 0x70);
}
__device__ __forceinline__ float ex2(float x) {
    float y;
    asm("ex2.approx.ftz.f32 %0, %1;" : "=f"(y) : "f"(x));
    return y;
}

#define CP_ASYNC16(dst, src) \
    asm volatile("cp.async.cg.shared.global [%0], [%1], 16;" :: "r"(dst), "l"(src))
#define CP_COMMIT() asm volatile("cp.async.commit_group;" ::: "memory")
#define CP_WAIT1()  asm volatile("cp.async.wait_group 1;" ::: "memory")
#define CP_WAIT0()  asm volatile("cp.async.wait_group 0;" ::: "memory")

__device__ __forceinline__ void ldm4(uint32_t addr, uint32_t* r) {
    asm volatile("ldmatrix.sync.aligned.m8n8.x4.shared.b16 {%0,%1,%2,%3}, [%4];"
                 : "=r"(r[0]), "=r"(r[1]), "=r"(r[2]), "=r"(r[3]) : "r"(addr));
}
__device__ __forceinline__ void mma_bf(float* c, const uint32_t* a, const uint32_t* b) {
    asm volatile("mma.sync.aligned.m16n8k16.row.col.f32.bf16.bf16.f32 "
                 "{%0,%1,%2,%3}, {%4,%5,%6,%7}, {%8,%9}, {%0,%1,%2,%3};"
                 : "+f"(c[0]), "+f"(c[1]), "+f"(c[2]), "+f"(c[3])
                 : "r"(a[0]), "r"(a[1]), "r"(a[2]), "r"(a[3]),
                   "r"(b[0]), "r"(b[1]));
}
__device__ __forceinline__ void mma_fp(float* c, const uint32_t* a, const uint32_t* b) {
    asm volatile("mma.sync.aligned.m16n8k16.row.col.f32.f16.f16.f32 "
                 "{%0,%1,%2,%3}, {%4,%5,%6,%7}, {%8,%9}, {%0,%1,%2,%3};"
                 : "+f"(c[0]), "+f"(c[1]), "+f"(c[2]), "+f"(c[3])
                 : "r"(a[0]), "r"(a[1]), "r"(a[2]), "r"(a[3]),
                   "r"(b[0]), "r"(b[1]));
}

__device__ __forceinline__ uint32_t pack_bf(__nv_bfloat16 x, __nv_bfloat16 y) {
    __nv_bfloat162 t = __halves2bfloat162(x, y);
    return *reinterpret_cast<uint32_t*>(&t);
}
__device__ __forceinline__ uint32_t pack_hf(__half x, __half y) {
    __half2 t = __halves2half2(x, y);
    return *reinterpret_cast<uint32_t*>(&t);
}

// ---------------------------------------------------------------------------
// Mask tile flags: 1 if any nonzero in the (b, qt, kt) 64x64 tile.
// ---------------------------------------------------------------------------
__global__ __launch_bounds__(128) void mask_flag_kernel(const float* __restrict__ Mask)
{
    const int blk = blockIdx.x;                 // b*1024 + qt*32 + kt
    const int b = blk >> 10, qt = (blk >> 5) & 31, kt = blk & 31;
    const float* p = Mask + ((size_t)b * SEQ + qt * 64) * SEQ + kt * 64;
    const int tid = threadIdx.x;
    bool nz = false;
#pragma unroll
    for (int i = 0; i < 8; i++) {
        const int t = tid + i * 128;            // 1024 float4 = 4096 floats
        const int r = t >> 4, c = (t & 15) * 4;
        float4 v = *(const float4*)&p[(size_t)r * SEQ + c];
        nz |= (v.x != 0.f) | (v.y != 0.f) | (v.z != 0.f) | (v.w != 0.f);
    }
    const int any = __syncthreads_or((int)nz);
    if (tid == 0) g_mflag[blk] = (unsigned char)(any != 0);
}

// ---------------------------------------------------------------------------
// Split conversions (fp32 -> bf16 hi/lo sections)
// ---------------------------------------------------------------------------
union BfPack { __nv_bfloat16 h[4]; uint2 u; };

__global__ __launch_bounds__(320) void split_rows_kernel(
    const float* __restrict__ src, __nv_bfloat16* __restrict__ dst)
{
    const int m = blockIdx.x;
    const int k4 = threadIdx.x * 4;
    float4 v = *(const float4*)&src[(size_t)m * DMODEL + k4];
    BfPack hi, lo;
    float f[4] = {v.x, v.y, v.z, v.w};
#pragma unroll
    for (int i = 0; i < 4; i++) {
        hi.h[i] = __float2bfloat16(f[i]);
        lo.h[i] = __float2bfloat16(f[i] - __bfloat162float(hi.h[i]));
    }
    __nv_bfloat16* row = dst + (size_t)m * KTOT;
    *(uint2*)&row[k4]            = hi.u;
    *(uint2*)&row[DMODEL + k4]   = lo.u;
    *(uint2*)&row[2*DMODEL + k4] = hi.u;
}

__global__ __launch_bounds__(256) void split_w_kernel(
    const float* __restrict__ src, __nv_bfloat16* __restrict__ dst, int N)
{
    const int idx = blockIdx.x * 256 + threadIdx.x;
    const int n = idx % N;
    const int k4i = idx / N;
    if (k4i >= DMODEL / 4) return;
    const int k = k4i * 4;
    BfPack hi, lo;
#pragma unroll
    for (int i = 0; i < 4; i++) {
        float w = src[(size_t)(k + i) * N + n];
        hi.h[i] = __float2bfloat16(w);
        lo.h[i] = __float2bfloat16(w - __bfloat162float(hi.h[i]));
    }
    __nv_bfloat16* row = dst + (size_t)n * KTOT;
    *(uint2*)&row[k]            = hi.u;
    *(uint2*)&row[DMODEL + k]   = hi.u;
    *(uint2*)&row[2*DMODEL + k] = lo.u;
}

// ---------------------------------------------------------------------------
// bf16-3-pass mma.sync GEMM: C[128x128] per CTA, 8 warps of 64x32.
// mode 0: QKV epilogue -> fp16 qh/kh (row-major), vh+vl (d-major)
// mode 1: out = A*B^T + bias (fp32)
// ---------------------------------------------------------------------------
#define STAGE_BYTES 32768
#define SM_TOTAL (3*STAGE_BYTES)

__global__ __launch_bounds__(256) void gemm_mma_kernel(
    const __nv_bfloat16* __restrict__ A,
    const __nv_bfloat16* __restrict__ Bt,
    int mode, const float* __restrict__ bias, float* __restrict__ Cout)
{
    extern __shared__ __align__(1024) char smem[];
    const uint32_t sb = smem_u32(smem);
    const int tid = threadIdx.x;
    const int lane = tid & 31, wid = tid >> 5;
    const int wm = wid >> 2, wn = wid & 3;
    const int m0 = blockIdx.y * 128, n0 = blockIdx.x * 128;

    auto load_stage = [&](int s, int buf) {
        const uint32_t base = sb + buf * STAGE_BYTES;
        const __nv_bfloat16* ap = A  + (size_t)m0 * KTOT + s * 64;
        const __nv_bfloat16* bp = Bt + (size_t)n0 * KTOT + s * 64;
#pragma unroll
        for (int i = 0; i < 4; i++) {
            const int t = tid + i * 256;
            const int r = t >> 3, c = t & 7;
            CP_ASYNC16(base + swz(r * 128 + c * 16), ap + (size_t)r * KTOT + c * 8);
        }
#pragma unroll
        for (int i = 0; i < 4; i++) {
            const int t = tid + i * 256;
            const int r = t >> 3, c = t & 7;
            CP_ASYNC16(base + 16384 + swz(r * 128 + c * 16), bp + (size_t)r * KTOT + c * 8);
        }
        CP_COMMIT();
    };

    float acc[4][4][4];
#pragma unroll
    for (int mi = 0; mi < 4; mi++)
#pragma unroll
        for (int ni = 0; ni < 4; ni++)
#pragma unroll
            for (int q = 0; q < 4; q++) acc[mi][ni][q] = 0.f;

    load_stage(0, 0);
    load_stage(1, 1);

    const int arow = lane & 15;
    const int acol = (lane >> 4) * 8;
    const int b4row = ((lane >> 4) & 1) * 8 + (lane & 7);
    const int b4col = ((lane >> 3) & 1) * 8;

#pragma unroll 1
    for (int s = 0; s < NST; s++) {
        if (s + 1 < NST) { CP_WAIT1(); } else { CP_WAIT0(); }
        __syncthreads();
        if (s + 2 < NST) load_stage(s + 2, (s + 2) % 3);

        const uint32_t abase = sb + (s % 3) * STAGE_BYTES;
        const uint32_t bbase = abase + 16384;
#pragma unroll
        for (int kf = 0; kf < 4; kf++) {
            uint32_t a[4][4], b2[2][4];
#pragma unroll
            for (int mi = 0; mi < 4; mi++)
                ldm4(abase + swz((wm*64 + mi*16 + arow) * 128 + (kf*16 + acol) * 2), a[mi]);
#pragma unroll
            for (int n2 = 0; n2 < 2; n2++)
                ldm4(bbase + swz((wn*32 + n2*16 + b4row) * 128 + (kf*16 + b4col) * 2), b2[n2]);
#pragma unroll
            for (int mi = 0; mi < 4; mi++)
#pragma unroll
                for (int n2 = 0; n2 < 2; n2++) {
                    mma_bf(acc[mi][n2*2],   a[mi], b2[n2]);
                    mma_bf(acc[mi][n2*2+1], a[mi], b2[n2] + 2);
                }
        }
    }

    // ---- epilogue ----
    const int grp = lane >> 2, tig = lane & 3;
#pragma unroll
    for (int mi = 0; mi < 4; mi++) {
#pragma unroll
        for (int half = 0; half < 2; half++) {
            const int r = wm * 64 + mi * 16 + grp + half * 8;
            const int m = m0 + r;
            const int bb = m >> 11, sq = m & 2047;
#pragma unroll
            for (int ni = 0; ni < 4; ni++) {
                const float v0 = acc[mi][ni][half * 2];
                const float v1 = acc[mi][ni][half * 2 + 1];
                const int nglob = n0 + wn * 32 + ni * 8 + tig * 2;
                if (mode == 1) {
                    float2 bv = *(const float2*)&bias[nglob];
                    *(float2*)&Cout[(size_t)m * DMODEL + nglob] =
                        make_float2(v0 + bv.x, v1 + bv.y);
                } else {
                    const int sec = nglob / DMODEL;
                    const int rem = nglob - sec * DMODEL;
                    const int hh = rem >> 6, dd = rem & 63;
                    const int bh = bb * NH + hh;
                    if (sec == 2) {
                        __half h0 = __float2half_rn(v0);
                        __half h1 = __float2half_rn(v1);
                        __half e0 = __float2half_rn(v0 - __half2float(h0));
                        __half e1 = __float2half_rn(v1 - __half2float(h1));
                        const size_t a0 = ((size_t)bh * DH + dd) * SEQ + sq;
                        const size_t a1 = ((size_t)bh * DH + dd + 1) * SEQ + sq;
                        g_vh[a0] = h0; g_vh[a1] = h1;
                        g_vl[a0] = e0; g_vl[a1] = e1;
                    } else {
                        const size_t a = ((size_t)bh * SEQ + sq) * DH + dd;
                        const uint32_t hv = pack_hf(__float2half_rn(v0), __float2half_rn(v1));
                        if (sec == 0) *(uint32_t*)&g_qh[a] = hv;
                        else          *(uint32_t*)&g_kh[a] = hv;
                    }
                }
            }
        }
    }
}

// ---------------------------------------------------------------------------
// fp16 tensor-core flash attention.
// CTA: 128 queries x one (b,h); 4 warps, each M=32 (2 m16 tiles), N=64 keys.
// QK^T: 1-pass fp16. PV: 3-pass fp16 (Ph*Vh + Pl*Vh + Ph*Vl).
// smem: Qh 16KB | 2 stages x {Kh,Vh,Vl each 8KB} = 64KB.
// Mask loads gated by per-tile nonzero flags.
// ---------------------------------------------------------------------------
#define FSM_TOTAL 65536

__global__ __launch_bounds__(128, 2) void flash_mma_kernel(const float* __restrict__ Mask)
{
    extern __shared__ __align__(1024) char fsm[];
    const uint32_t sb = smem_u32(fsm);
    const int tid = threadIdx.x, lane = tid & 31, wid = tid >> 5;
    const int grp = lane >> 2, tig = lane & 3;
    const int qb = blockIdx.x, h = blockIdx.y, b = blockIdx.z;
    const int bh = b * NH + h;

    const __half* qhp = g_qh + ((size_t)bh * SEQ + qb * 128) * DH;
    const __half* khp = g_kh + (size_t)bh * SEQ * DH;
    const __half* vhp = g_vh + (size_t)bh * DH * SEQ;
    const __half* vlp = g_vl + (size_t)bh * DH * SEQ;

    // Q tile: 128 rows x 128B
#pragma unroll
    for (int i = 0; i < 8; i++) {
        const int t = tid + i * 128;
        const int r = t >> 3, c = t & 7;
        CP_ASYNC16(sb + swz(r * 128 + c * 16), qhp + (size_t)r * DH + c * 8);
    }

    auto load_kv = [&](int kb, int buf) {
        const uint32_t base = sb + 16384 + buf * 24576;
#pragma unroll
        for (int i = 0; i < 4; i++) {
            const int t = tid + i * 128;           // 512 chunks
            const int r = t >> 3, c = t & 7;
            const uint32_t d = swz(r * 128 + c * 16);
            CP_ASYNC16(base + d,         khp + (size_t)(kb * 64 + r) * DH + c * 8);
            CP_ASYNC16(base + 8192 + d,  vhp + (size_t)r * SEQ + kb * 64 + c * 8);
            CP_ASYNC16(base + 16384 + d, vlp + (size_t)r * SEQ + kb * 64 + c * 8);
        }
        CP_COMMIT();
    };
    load_kv(0, 0);
    load_kv(1, 1);

    float O[2][8][4];
#pragma unroll
    for (int t = 0; t < 2; t++)
#pragma unroll
        for (int nf = 0; nf < 8; nf++)
#pragma unroll
            for (int q = 0; q < 4; q++) O[t][nf][q] = 0.f;
    float mrun[4] = {-1e30f, -1e30f, -1e30f, -1e30f};
    float lrun[4] = {0.f, 0.f, 0.f, 0.f};

    const int qrowbase = qb * 128 + wid * 32;
    // mask row pointers for row-sets j = t*2+half
    const float* mrp[4];
#pragma unroll
    for (int j = 0; j < 4; j++) {
        const int t = j >> 1, half = j & 1;
        mrp[j] = Mask + ((size_t)b * SEQ + qrowbase + t * 16 + half * 8 + grp) * SEQ;
    }
    const unsigned char* flagp = g_mflag + (size_t)b * 1024 + (qb * 2 + (wid >> 1)) * 32;

    const int arow = lane & 15;
    const int acol = (lane >> 4) * 8;
    const int b4row = ((lane >> 4) & 1) * 8 + (lane & 7);
    const int b4col = ((lane >> 3) & 1) * 8;

    const float SCL2E = 0.125f * 1.44269504f;
    const float L2E = 1.44269504f;

#pragma unroll 1
    for (int kb = 0; kb < 32; kb++) {
        if (kb < 31) { CP_WAIT1(); } else { CP_WAIT0(); }
        __syncthreads();
        const uint32_t kbase = sb + 16384 + (kb & 1) * 24576;

        // ---- S = Q K^T (1-pass fp16) ----
        float S[2][8][4];
#pragma unroll
        for (int t = 0; t < 2; t++)
#pragma unroll
            for (int nf = 0; nf < 8; nf++)
#pragma unroll
                for (int q = 0; q < 4; q++) S[t][nf][q] = 0.f;

#pragma unroll
        for (int kf = 0; kf < 4; kf++) {
            uint32_t aq[2][4];
#pragma unroll
            for (int t = 0; t < 2; t++)
                ldm4(sb + swz((wid * 32 + t * 16 + arow) * 128 + (kf * 16 + acol) * 2), aq[t]);
#pragma unroll
            for (int n2 = 0; n2 < 4; n2++) {
                uint32_t kh4[4];
                ldm4(kbase + swz((n2 * 16 + b4row) * 128 + (kf * 16 + b4col) * 2), kh4);
#pragma unroll
                for (int t = 0; t < 2; t++) {
                    mma_fp(S[t][n2*2],   aq[t], kh4);
                    mma_fp(S[t][n2*2+1], aq[t], kh4 + 2);
                }
            }
        }

        // ---- scale (+ mask if tile nonzero), log2 domain ----
        if (flagp[kb]) {
#pragma unroll
            for (int t = 0; t < 2; t++)
#pragma unroll
                for (int nf = 0; nf < 8; nf++) {
                    float2 u = *(const float2*)&mrp[t*2    ][kb * 64 + nf * 8 + tig * 2];
                    float2 w = *(const float2*)&mrp[t*2 + 1][kb * 64 + nf * 8 + tig * 2];
                    S[t][nf][0] = fmaf(S[t][nf][0], SCL2E, u.x * L2E);
                    S[t][nf][1] = fmaf(S[t][nf][1], SCL2E, u.y * L2E);
                    S[t][nf][2] = fmaf(S[t][nf][2], SCL2E, w.x * L2E);
                    S[t][nf][3] = fmaf(S[t][nf][3], SCL2E, w.y * L2E);
                }
        } else {
#pragma unroll
            for (int t = 0; t < 2; t++)
#pragma unroll
                for (int nf = 0; nf < 8; nf++)
#pragma unroll
                    for (int q = 0; q < 4; q++) S[t][nf][q] *= SCL2E;
        }

        // ---- online softmax per row-set j (rows reduce over tig: xor 1,2) ----
        float al[4];
#pragma unroll
        for (int j = 0; j < 4; j++) {
            const int t = j >> 1, half = j & 1;
            float rm = -1e30f;
#pragma unroll
            for (int nf = 0; nf < 8; nf++)
                rm = fmaxf(rm, fmaxf(S[t][nf][half*2], S[t][nf][half*2+1]));
            rm = fmaxf(rm, __shfl_xor_sync(0xffffffffu, rm, 1));
            rm = fmaxf(rm, __shfl_xor_sync(0xffffffffu, rm, 2));
            const float mn = fmaxf(mrun[j], rm);
            al[j] = ex2(mrun[j] - mn);
            mrun[j] = mn;
            float rs = 0.f;
#pragma unroll
            for (int nf = 0; nf < 8; nf++) {
                const float p0 = ex2(S[t][nf][half*2]   - mn);
                const float p1 = ex2(S[t][nf][half*2+1] - mn);
                S[t][nf][half*2]   = p0;
                S[t][nf][half*2+1] = p1;
                rs += p0 + p1;
            }
            rs += __shfl_xor_sync(0xffffffffu, rs, 1);
            rs += __shfl_xor_sync(0xffffffffu, rs, 2);
            lrun[j] = lrun[j] * al[j] + rs;
        }
#pragma unroll
        for (int t = 0; t < 2; t++)
#pragma unroll
            for (int nf = 0; nf < 8; nf++) {
                O[t][nf][0] *= al[t*2];   O[t][nf][1] *= al[t*2];
                O[t][nf][2] *= al[t*2+1]; O[t][nf][3] *= al[t*2+1];
            }

        // ---- O += Ph Vh + Pl Vh + Ph Vl ----
#pragma unroll
        for (int kc = 0; kc < 4; kc++) {
            uint32_t phi[2][4], plo[2][4];
#pragma unroll
            for (int t = 0; t < 2; t++) {
#pragma unroll
                for (int hf = 0; hf < 2; hf++) {
                    const int nf = kc * 2 + hf;
                    const float x0 = S[t][nf][0], y0 = S[t][nf][1];
                    const float x1 = S[t][nf][2], y1 = S[t][nf][3];
                    __half hx0 = __float2half_rn(x0), hy0 = __float2half_rn(y0);
                    __half hx1 = __float2half_rn(x1), hy1 = __float2half_rn(y1);
                    phi[t][hf*2+0] = pack_hf(hx0, hy0);
                    phi[t][hf*2+1] = pack_hf(hx1, hy1);
                    plo[t][hf*2+0] = pack_hf(__float2half_rn(x0 - __half2float(hx0)),
                                             __float2half_rn(y0 - __half2float(hy0)));
                    plo[t][hf*2+1] = pack_hf(__float2half_rn(x1 - __half2float(hx1)),
                                             __float2half_rn(y1 - __half2float(hy1)));
                }
            }
#pragma unroll
            for (int n2 = 0; n2 < 4; n2++) {
                uint32_t vh4[4], vl4[4];
                const uint32_t off = swz((n2 * 16 + b4row) * 128 + (kc * 16 + b4col) * 2);
                ldm4(kbase + 8192 + off, vh4);
                ldm4(kbase + 16384 + off, vl4);
#pragma unroll
                for (int t = 0; t < 2; t++) {
                    mma_fp(O[t][n2*2],   phi[t], vh4);
                    mma_fp(O[t][n2*2],   plo[t], vh4);
                    mma_fp(O[t][n2*2],   phi[t], vl4);
                    mma_fp(O[t][n2*2+1], phi[t], vh4 + 2);
                    mma_fp(O[t][n2*2+1], plo[t], vh4 + 2);
                    mma_fp(O[t][n2*2+1], phi[t], vl4 + 2);
                }
            }
        }

        __syncthreads();
        if (kb + 2 < 32) load_kv(kb + 2, kb & 1);
    }

    // ---- epilogue: write normalized O as [Ah|Al|Ah] split rows of g_A2buf ----
#pragma unroll
    for (int j = 0; j < 4; j++) {
        const int t = j >> 1, half = j & 1;
        const int row = qrowbase + t * 16 + half * 8 + grp;
        const float inv = 1.f / lrun[j];
        __nv_bfloat16* op = g_A2buf + ((size_t)b * SEQ + row) * KTOT;
#pragma unroll
        for (int nf = 0; nf < 8; nf++) {
            const int col = h * 64 + nf * 8 + tig * 2;
            const float x = O[t][nf][half*2] * inv, y = O[t][nf][half*2+1] * inv;
            __nv_bfloat16 hx = __float2bfloat16(x), hy = __float2bfloat16(y);
            const uint32_t hi = pack_bf(hx, hy);
            const uint32_t lo = pack_bf(__float2bfloat16(x - __bfloat162float(hx)),
                                        __float2bfloat16(y - __bfloat162float(hy)));
            *(uint32_t*)&op[col]            = hi;
            *(uint32_t*)&op[DMODEL + col]   = lo;
            *(uint32_t*)&op[2*DMODEL + col] = hi;
        }
    }
}

// ---------------------------------------------------------------------------
extern "C" void kernel_launch(void* const* d_in, const int* in_sizes, int n_in,
                              void* d_out, int out_size)
{
    const float* hidden = (const float*)d_in[0];
    const float* mask   = (const float*)d_in[1];
    const float* w_qkv  = (const float*)d_in[2];
    const float* w_out  = (const float*)d_in[3];
    const float* b_out  = (const float*)d_in[4];
    float* out = (float*)d_out;

    cudaFuncSetAttribute(gemm_mma_kernel,
                         cudaFuncAttributeMaxDynamicSharedMemorySize, SM_TOTAL);
    cudaFuncSetAttribute(flash_mma_kernel,
                         cudaFuncAttributeMaxDynamicSharedMemorySize, FSM_TOTAL);

    __nv_bfloat16 *abuf, *wt, *w2t, *a2buf;
    cudaGetSymbolAddress((void**)&abuf, g_Abuf);
    cudaGetSymbolAddress((void**)&wt, g_Wt);
    cudaGetSymbolAddress((void**)&w2t, g_W2t);
    cudaGetSymbolAddress((void**)&a2buf, g_A2buf);

    // 1. conversions + mask tile flags
    mask_flag_kernel<<<BATCH * 32 * 32, 128>>>(mask);
    split_rows_kernel<<<MTOT, 320>>>(hidden, abuf);
    split_w_kernel<<<(3840 * 320 + 255) / 256, 256>>>(w_qkv, wt, 3840);
    split_w_kernel<<<(1280 * 320 + 255) / 256, 256>>>(w_out, w2t, 1280);

    // 2. QKV projection (bf16 3-pass) -> fp16 q/k hi, v hi+lo
    gemm_mma_kernel<<<dim3(3840 / 128, MTOT / 128), 256, SM_TOTAL>>>(
        abuf, wt, 0, nullptr, nullptr);

    // 3. fp16 tensor-core flash attention -> split bf16 attn rows
    flash_mma_kernel<<<dim3(SEQ / 128, NH, BATCH), 128, FSM_TOTAL>>>(mask);

    // 4. out-projection (bf16 3-pass)
    gemm_mma_kernel<<<dim3(1280 / 128, MTOT / 128), 256, SM_TOTAL>>>(
        a2buf, w2t, 1, b_out, out);
}

// round 8
// speedup vs baseline: 4.2347x; 1.2688x over previous
#include <cuda_runtime.h>
#include <cuda_bf16.h>
#include <cuda_fp16.h>
#include <cstdint>

#define NH 20
#define DH 64
#define DMODEL 1280
#define BATCH 2
#define SEQ 2048
#define MTOT (BATCH*SEQ)      /* 4096 */
#define KTOT 2560             /* 2 * 1280 fp16 split-K concat */
#define NST 40                /* 2560 / 64 */

// ---------------------------------------------------------------------------
// Device-global scratch (allocation-free rule)
// ---------------------------------------------------------------------------
__device__ __half g_qh[BATCH*NH*SEQ*DH];         // [bh][s][dd] fp16 (hi only)
__device__ __half g_kh[BATCH*NH*SEQ*DH];         // [bh][s][dd] fp16 (hi only)
__device__ __half g_vh[BATCH*NH*DH*SEQ];         // d-major [bh][dd][s]
__device__ __half g_vl[BATCH*NH*DH*SEQ];         // fp16 residual of V
__device__ __half g_Abuf[(size_t)MTOT*KTOT];     // [Xh | Xl]
__device__ __half g_Wt[(size_t)3840*KTOT];       // [n][Wh | Wh]
__device__ __half g_W2t[(size_t)1280*KTOT];
__device__ __half g_A2buf[(size_t)MTOT*KTOT];    // [Ah | Al] of attn
__device__ unsigned char g_mflag[BATCH*32*32];   // mask 64x64 tile nonzero flags

// ---------------------------------------------------------------------------
// Baseline-PTX helpers
// ---------------------------------------------------------------------------
__device__ __forceinline__ uint32_t smem_u32(const void* p) {
    uint32_t a;
    asm("{ .reg .u64 t; cvta.to.shared.u64 t, %1; cvt.u32.u64 %0, t; }"
        : "=r"(a) : "l"(p));
    return a;
}
__device__ __forceinline__ uint32_t swz(uint32_t off) {  // SW128 byte swizzle
    return off ^ ((off >> 3) & 0x70);
}
__device__ __forceinline__ float ex2(float x) {
    float y;
    asm("ex2.approx.ftz.f32 %0, %1;" : "=f"(y) : "f"(x));
    return y;
}

#define CP_ASYNC16(dst, src) \
    asm volatile("cp.async.cg.shared.global [%0], [%1], 16;" :: "r"(dst), "l"(src))
#define CP_COMMIT() asm volatile("cp.async.commit_group;" ::: "memory")
#define CP_WAIT1()  asm volatile("cp.async.wait_group 1;" ::: "memory")
#define CP_WAIT0()  asm volatile("cp.async.wait_group 0;" ::: "memory")

__device__ __forceinline__ void ldm4(uint32_t addr, uint32_t* r) {
    asm volatile("ldmatrix.sync.aligned.m8n8.x4.shared.b16 {%0,%1,%2,%3}, [%4];"
                 : "=r"(r[0]), "=r"(r[1]), "=r"(r[2]), "=r"(r[3]) : "r"(addr));
}
__device__ __forceinline__ void mma_fp(float* c, const uint32_t* a, const uint32_t* b) {
    asm volatile("mma.sync.aligned.m16n8k16.row.col.f32.f16.f16.f32 "
                 "{%0,%1,%2,%3}, {%4,%5,%6,%7}, {%8,%9}, {%0,%1,%2,%3};"
                 : "+f"(c[0]), "+f"(c[1]), "+f"(c[2]), "+f"(c[3])
                 : "r"(a[0]), "r"(a[1]), "r"(a[2]), "r"(a[3]),
                   "r"(b[0]), "r"(b[1]));
}

__device__ __forceinline__ uint32_t pack_hf(__half x, __half y) {
    __half2 t = __halves2half2(x, y);
    return *reinterpret_cast<uint32_t*>(&t);
}

// ---------------------------------------------------------------------------
// Mask tile flags: 1 if any nonzero in the (b, qt, kt) 64x64 tile.
// ---------------------------------------------------------------------------
__global__ __launch_bounds__(128) void mask_flag_kernel(const float* __restrict__ Mask)
{
    const int blk = blockIdx.x;                 // b*1024 + qt*32 + kt
    const int b = blk >> 10, qt = (blk >> 5) & 31, kt = blk & 31;
    const float* p = Mask + ((size_t)b * SEQ + qt * 64) * SEQ + kt * 64;
    const int tid = threadIdx.x;
    bool nz = false;
#pragma unroll
    for (int i = 0; i < 8; i++) {
        const int t = tid + i * 128;            // 1024 float4 = 4096 floats
        const int r = t >> 4, c = (t & 15) * 4;
        float4 v = *(const float4*)&p[(size_t)r * SEQ + c];
        nz |= (v.x != 0.f) | (v.y != 0.f) | (v.z != 0.f) | (v.w != 0.f);
    }
    const int any = __syncthreads_or((int)nz);
    if (tid == 0) g_mflag[blk] = (unsigned char)(any != 0);
}

// ---------------------------------------------------------------------------
// Split conversions (fp32 -> fp16 hi/lo sections)
// ---------------------------------------------------------------------------
union HfPack { __half h[4]; uint2 u; };

// src [rows][1280] fp32 -> dst [rows][2560] fp16 sections [hi | lo]
__global__ __launch_bounds__(320) void split_rows_kernel(
    const float* __restrict__ src, __half* __restrict__ dst)
{
    const int m = blockIdx.x;
    const int k4 = threadIdx.x * 4;
    float4 v = *(const float4*)&src[(size_t)m * DMODEL + k4];
    HfPack hi, lo;
    float f[4] = {v.x, v.y, v.z, v.w};
#pragma unroll
    for (int i = 0; i < 4; i++) {
        hi.h[i] = __float2half_rn(f[i]);
        lo.h[i] = __float2half_rn(f[i] - __half2float(hi.h[i]));
    }
    __half* row = dst + (size_t)m * KTOT;
    *(uint2*)&row[k4]          = hi.u;
    *(uint2*)&row[DMODEL + k4] = lo.u;
}

// src W [K=1280][N] fp32 -> dst [N][2560] fp16 sections [hi | hi]
__global__ __launch_bounds__(256) void split_w_kernel(
    const float* __restrict__ src, __half* __restrict__ dst, int N)
{
    const int idx = blockIdx.x * 256 + threadIdx.x;
    const int n = idx % N;
    const int k4i = idx / N;
    if (k4i >= DMODEL / 4) return;
    const int k = k4i * 4;
    HfPack hi;
#pragma unroll
    for (int i = 0; i < 4; i++)
        hi.h[i] = __float2half_rn(src[(size_t)(k + i) * N + n]);
    __half* row = dst + (size_t)n * KTOT;
    *(uint2*)&row[k]          = hi.u;
    *(uint2*)&row[DMODEL + k] = hi.u;
}

// ---------------------------------------------------------------------------
// fp16 2-pass mma.sync GEMM: C[128x128] per CTA, 8 warps of 64x32,
// K'=2560 in 40 BK=64 stages through a 3-buffer cp.async ring.
// mode 0: QKV epilogue -> fp16 qh/kh (row-major), vh+vl (d-major)
// mode 1: out = A*B^T + bias (fp32)
// ---------------------------------------------------------------------------
#define STAGE_BYTES 32768
#define SM_TOTAL (3*STAGE_BYTES)

__global__ __launch_bounds__(256) void gemm_mma_kernel(
    const __half* __restrict__ A,
    const __half* __restrict__ Bt,
    int mode, const float* __restrict__ bias, float* __restrict__ Cout)
{
    extern __shared__ __align__(1024) char smem[];
    const uint32_t sb = smem_u32(smem);
    const int tid = threadIdx.x;
    const int lane = tid & 31, wid = tid >> 5;
    const int wm = wid >> 2, wn = wid & 3;
    const int m0 = blockIdx.y * 128, n0 = blockIdx.x * 128;

    auto load_stage = [&](int s, int buf) {
        const uint32_t base = sb + buf * STAGE_BYTES;
        const __half* ap = A  + (size_t)m0 * KTOT + s * 64;
        const __half* bp = Bt + (size_t)n0 * KTOT + s * 64;
#pragma unroll
        for (int i = 0; i < 4; i++) {
            const int t = tid + i * 256;
            const int r = t >> 3, c = t & 7;
            CP_ASYNC16(base + swz(r * 128 + c * 16), ap + (size_t)r * KTOT + c * 8);
        }
#pragma unroll
        for (int i = 0; i < 4; i++) {
            const int t = tid + i * 256;
            const int r = t >> 3, c = t & 7;
            CP_ASYNC16(base + 16384 + swz(r * 128 + c * 16), bp + (size_t)r * KTOT + c * 8);
        }
        CP_COMMIT();
    };

    float acc[4][4][4];
#pragma unroll
    for (int mi = 0; mi < 4; mi++)
#pragma unroll
        for (int ni = 0; ni < 4; ni++)
#pragma unroll
            for (int q = 0; q < 4; q++) acc[mi][ni][q] = 0.f;

    load_stage(0, 0);
    load_stage(1, 1);

    const int arow = lane & 15;
    const int acol = (lane >> 4) * 8;
    const int b4row = ((lane >> 4) & 1) * 8 + (lane & 7);
    const int b4col = ((lane >> 3) & 1) * 8;

#pragma unroll 1
    for (int s = 0; s < NST; s++) {
        if (s + 1 < NST) { CP_WAIT1(); } else { CP_WAIT0(); }
        __syncthreads();
        if (s + 2 < NST) load_stage(s + 2, (s + 2) % 3);

        const uint32_t abase = sb + (s % 3) * STAGE_BYTES;
        const uint32_t bbase = abase + 16384;
#pragma unroll
        for (int kf = 0; kf < 4; kf++) {
            uint32_t a[4][4], b2[2][4];
#pragma unroll
            for (int mi = 0; mi < 4; mi++)
                ldm4(abase + swz((wm*64 + mi*16 + arow) * 128 + (kf*16 + acol) * 2), a[mi]);
#pragma unroll
            for (int n2 = 0; n2 < 2; n2++)
                ldm4(bbase + swz((wn*32 + n2*16 + b4row) * 128 + (kf*16 + b4col) * 2), b2[n2]);
#pragma unroll
            for (int mi = 0; mi < 4; mi++)
#pragma unroll
                for (int n2 = 0; n2 < 2; n2++) {
                    mma_fp(acc[mi][n2*2],   a[mi], b2[n2]);
                    mma_fp(acc[mi][n2*2+1], a[mi], b2[n2] + 2);
                }
        }
    }

    // ---- epilogue ----
    const int grp = lane >> 2, tig = lane & 3;
#pragma unroll
    for (int mi = 0; mi < 4; mi++) {
#pragma unroll
        for (int half = 0; half < 2; half++) {
            const int r = wm * 64 + mi * 16 + grp + half * 8;
            const int m = m0 + r;
            const int bb = m >> 11, sq = m & 2047;
#pragma unroll
            for (int ni = 0; ni < 4; ni++) {
                const float v0 = acc[mi][ni][half * 2];
                const float v1 = acc[mi][ni][half * 2 + 1];
                const int nglob = n0 + wn * 32 + ni * 8 + tig * 2;
                if (mode == 1) {
                    float2 bv = *(const float2*)&bias[nglob];
                    *(float2*)&Cout[(size_t)m * DMODEL + nglob] =
                        make_float2(v0 + bv.x, v1 + bv.y);
                } else {
                    const int sec = nglob / DMODEL;
                    const int rem = nglob - sec * DMODEL;
                    const int hh = rem >> 6, dd = rem & 63;
                    const int bh = bb * NH + hh;
                    if (sec == 2) {
                        __half h0 = __float2half_rn(v0);
                        __half h1 = __float2half_rn(v1);
                        __half e0 = __float2half_rn(v0 - __half2float(h0));
                        __half e1 = __float2half_rn(v1 - __half2float(h1));
                        const size_t a0 = ((size_t)bh * DH + dd) * SEQ + sq;
                        const size_t a1 = ((size_t)bh * DH + dd + 1) * SEQ + sq;
                        g_vh[a0] = h0; g_vh[a1] = h1;
                        g_vl[a0] = e0; g_vl[a1] = e1;
                    } else {
                        const size_t a = ((size_t)bh * SEQ + sq) * DH + dd;
                        const uint32_t hv = pack_hf(__float2half_rn(v0), __float2half_rn(v1));
                        if (sec == 0) *(uint32_t*)&g_qh[a] = hv;
                        else          *(uint32_t*)&g_kh[a] = hv;
                    }
                }
            }
        }
    }
}

// ---------------------------------------------------------------------------
// fp16 tensor-core flash attention.
// CTA: 128 queries x one (b,h); 4 warps, each M=32 (2 m16 tiles), N=64 keys.
// QK^T: 1-pass fp16. PV: 3-pass fp16 (Ph*Vh + Pl*Vh + Ph*Vl).
// smem: Qh 16KB | 2 stages x {Kh,Vh,Vl each 8KB} = 64KB.
// Mask loads gated by per-tile nonzero flags.
// ---------------------------------------------------------------------------
#define FSM_TOTAL 65536

__global__ __launch_bounds__(128, 2) void flash_mma_kernel(const float* __restrict__ Mask)
{
    extern __shared__ __align__(1024) char fsm[];
    const uint32_t sb = smem_u32(fsm);
    const int tid = threadIdx.x, lane = tid & 31, wid = tid >> 5;
    const int grp = lane >> 2, tig = lane & 3;
    const int qb = blockIdx.x, h = blockIdx.y, b = blockIdx.z;
    const int bh = b * NH + h;

    const __half* qhp = g_qh + ((size_t)bh * SEQ + qb * 128) * DH;
    const __half* khp = g_kh + (size_t)bh * SEQ * DH;
    const __half* vhp = g_vh + (size_t)bh * DH * SEQ;
    const __half* vlp = g_vl + (size_t)bh * DH * SEQ;

    // Q tile: 128 rows x 128B
#pragma unroll
    for (int i = 0; i < 8; i++) {
        const int t = tid + i * 128;
        const int r = t >> 3, c = t & 7;
        CP_ASYNC16(sb + swz(r * 128 + c * 16), qhp + (size_t)r * DH + c * 8);
    }

    auto load_kv = [&](int kb, int buf) {
        const uint32_t base = sb + 16384 + buf * 24576;
#pragma unroll
        for (int i = 0; i < 4; i++) {
            const int t = tid + i * 128;           // 512 chunks
            const int r = t >> 3, c = t & 7;
            const uint32_t d = swz(r * 128 + c * 16);
            CP_ASYNC16(base + d,         khp + (size_t)(kb * 64 + r) * DH + c * 8);
            CP_ASYNC16(base + 8192 + d,  vhp + (size_t)r * SEQ + kb * 64 + c * 8);
            CP_ASYNC16(base + 16384 + d, vlp + (size_t)r * SEQ + kb * 64 + c * 8);
        }
        CP_COMMIT();
    };
    load_kv(0, 0);
    load_kv(1, 1);

    float O[2][8][4];
#pragma unroll
    for (int t = 0; t < 2; t++)
#pragma unroll
        for (int nf = 0; nf < 8; nf++)
#pragma unroll
            for (int q = 0; q < 4; q++) O[t][nf][q] = 0.f;
    float mrun[4] = {-1e30f, -1e30f, -1e30f, -1e30f};
    float lrun[4] = {0.f, 0.f, 0.f, 0.f};

    const int qrowbase = qb * 128 + wid * 32;
    const float* mrp[4];
#pragma unroll
    for (int j = 0; j < 4; j++) {
        const int t = j >> 1, half = j & 1;
        mrp[j] = Mask + ((size_t)b * SEQ + qrowbase + t * 16 + half * 8 + grp) * SEQ;
    }
    const unsigned char* flagp = g_mflag + (size_t)b * 1024 + (qb * 2 + (wid >> 1)) * 32;

    const int arow = lane & 15;
    const int acol = (lane >> 4) * 8;
    const int b4row = ((lane >> 4) & 1) * 8 + (lane & 7);
    const int b4col = ((lane >> 3) & 1) * 8;

    const float SCL2E = 0.125f * 1.44269504f;
    const float L2E = 1.44269504f;

#pragma unroll 1
    for (int kb = 0; kb < 32; kb++) {
        if (kb < 31) { CP_WAIT1(); } else { CP_WAIT0(); }
        __syncthreads();
        const uint32_t kbase = sb + 16384 + (kb & 1) * 24576;

        // ---- S = Q K^T (1-pass fp16) ----
        float S[2][8][4];
#pragma unroll
        for (int t = 0; t < 2; t++)
#pragma unroll
            for (int nf = 0; nf < 8; nf++)
#pragma unroll
                for (int q = 0; q < 4; q++) S[t][nf][q] = 0.f;

#pragma unroll
        for (int kf = 0; kf < 4; kf++) {
            uint32_t aq[2][4];
#pragma unroll
            for (int t = 0; t < 2; t++)
                ldm4(sb + swz((wid * 32 + t * 16 + arow) * 128 + (kf * 16 + acol) * 2), aq[t]);
#pragma unroll
            for (int n2 = 0; n2 < 4; n2++) {
                uint32_t kh4[4];
                ldm4(kbase + swz((n2 * 16 + b4row) * 128 + (kf * 16 + b4col) * 2), kh4);
#pragma unroll
                for (int t = 0; t < 2; t++) {
                    mma_fp(S[t][n2*2],   aq[t], kh4);
                    mma_fp(S[t][n2*2+1], aq[t], kh4 + 2);
                }
            }
        }

        // ---- scale (+ mask if tile nonzero), log2 domain ----
        if (flagp[kb]) {
#pragma unroll
            for (int t = 0; t < 2; t++)
#pragma unroll
                for (int nf = 0; nf < 8; nf++) {
                    float2 u = *(const float2*)&mrp[t*2    ][kb * 64 + nf * 8 + tig * 2];
                    float2 w = *(const float2*)&mrp[t*2 + 1][kb * 64 + nf * 8 + tig * 2];
                    S[t][nf][0] = fmaf(S[t][nf][0], SCL2E, u.x * L2E);
                    S[t][nf][1] = fmaf(S[t][nf][1], SCL2E, u.y * L2E);
                    S[t][nf][2] = fmaf(S[t][nf][2], SCL2E, w.x * L2E);
                    S[t][nf][3] = fmaf(S[t][nf][3], SCL2E, w.y * L2E);
                }
        } else {
#pragma unroll
            for (int t = 0; t < 2; t++)
#pragma unroll
                for (int nf = 0; nf < 8; nf++)
#pragma unroll
                    for (int q = 0; q < 4; q++) S[t][nf][q] *= SCL2E;
        }

        // ---- online softmax per row-set j ----
        float al[4];
#pragma unroll
        for (int j = 0; j < 4; j++) {
            const int t = j >> 1, half = j & 1;
            float rm = -1e30f;
#pragma unroll
            for (int nf = 0; nf < 8; nf++)
                rm = fmaxf(rm, fmaxf(S[t][nf][half*2], S[t][nf][half*2+1]));
            rm = fmaxf(rm, __shfl_xor_sync(0xffffffffu, rm, 1));
            rm = fmaxf(rm, __shfl_xor_sync(0xffffffffu, rm, 2));
            const float mn = fmaxf(mrun[j], rm);
            al[j] = ex2(mrun[j] - mn);
            mrun[j] = mn;
            float rs = 0.f;
#pragma unroll
            for (int nf = 0; nf < 8; nf++) {
                const float p0 = ex2(S[t][nf][half*2]   - mn);
                const float p1 = ex2(S[t][nf][half*2+1] - mn);
                S[t][nf][half*2]   = p0;
                S[t][nf][half*2+1] = p1;
                rs += p0 + p1;
            }
            rs += __shfl_xor_sync(0xffffffffu, rs, 1);
            rs += __shfl_xor_sync(0xffffffffu, rs, 2);
            lrun[j] = lrun[j] * al[j] + rs;
        }
#pragma unroll
        for (int t = 0; t < 2; t++)
#pragma unroll
            for (int nf = 0; nf < 8; nf++) {
                O[t][nf][0] *= al[t*2];   O[t][nf][1] *= al[t*2];
                O[t][nf][2] *= al[t*2+1]; O[t][nf][3] *= al[t*2+1];
            }

        // ---- O += Ph Vh + Pl Vh + Ph Vl ----
#pragma unroll
        for (int kc = 0; kc < 4; kc++) {
            uint32_t phi[2][4], plo[2][4];
#pragma unroll
            for (int t = 0; t < 2; t++) {
#pragma unroll
                for (int hf = 0; hf < 2; hf++) {
                    const int nf = kc * 2 + hf;
                    const float x0 = S[t][nf][0], y0 = S[t][nf][1];
                    const float x1 = S[t][nf][2], y1 = S[t][nf][3];
                    __half hx0 = __float2half_rn(x0), hy0 = __float2half_rn(y0);
                    __half hx1 = __float2half_rn(x1), hy1 = __float2half_rn(y1);
                    phi[t][hf*2+0] = pack_hf(hx0, hy0);
                    phi[t][hf*2+1] = pack_hf(hx1, hy1);
                    plo[t][hf*2+0] = pack_hf(__float2half_rn(x0 - __half2float(hx0)),
                                             __float2half_rn(y0 - __half2float(hy0)));
                    plo[t][hf*2+1] = pack_hf(__float2half_rn(x1 - __half2float(hx1)),
                                             __float2half_rn(y1 - __half2float(hy1)));
                }
            }
#pragma unroll
            for (int n2 = 0; n2 < 4; n2++) {
                uint32_t vh4[4], vl4[4];
                const uint32_t off = swz((n2 * 16 + b4row) * 128 + (kc * 16 + b4col) * 2);
                ldm4(kbase + 8192 + off, vh4);
                ldm4(kbase + 16384 + off, vl4);
#pragma unroll
                for (int t = 0; t < 2; t++) {
                    mma_fp(O[t][n2*2],   phi[t], vh4);
                    mma_fp(O[t][n2*2],   plo[t], vh4);
                    mma_fp(O[t][n2*2],   phi[t], vl4);
                    mma_fp(O[t][n2*2+1], phi[t], vh4 + 2);
                    mma_fp(O[t][n2*2+1], plo[t], vh4 + 2);
                    mma_fp(O[t][n2*2+1], phi[t], vl4 + 2);
                }
            }
        }

        __syncthreads();
        if (kb + 2 < 32) load_kv(kb + 2, kb & 1);
    }

    // ---- epilogue: write normalized O as [Ah|Al] split rows of g_A2buf ----
#pragma unroll
    for (int j = 0; j < 4; j++) {
        const int t = j >> 1, half = j & 1;
        const int row = qrowbase + t * 16 + half * 8 + grp;
        const float inv = 1.f / lrun[j];
        __half* op = g_A2buf + ((size_t)b * SEQ + row) * KTOT;
#pragma unroll
        for (int nf = 0; nf < 8; nf++) {
            const int col = h * 64 + nf * 8 + tig * 2;
            const float x = O[t][nf][half*2] * inv, y = O[t][nf][half*2+1] * inv;
            __half hx = __float2half_rn(x), hy = __float2half_rn(y);
            *(uint32_t*)&op[col]          = pack_hf(hx, hy);
            *(uint32_t*)&op[DMODEL + col] = pack_hf(__float2half_rn(x - __half2float(hx)),
                                                    __float2half_rn(y - __half2float(hy)));
        }
    }
}

// ---------------------------------------------------------------------------
extern "C" void kernel_launch(void* const* d_in, const int* in_sizes, int n_in,
                              void* d_out, int out_size)
{
    const float* hidden = (const float*)d_in[0];
    const float* mask   = (const float*)d_in[1];
    const float* w_qkv  = (const float*)d_in[2];
    const float* w_out  = (const float*)d_in[3];
    const float* b_out  = (const float*)d_in[4];
    float* out = (float*)d_out;

    cudaFuncSetAttribute(gemm_mma_kernel,
                         cudaFuncAttributeMaxDynamicSharedMemorySize, SM_TOTAL);
    cudaFuncSetAttribute(flash_mma_kernel,
                         cudaFuncAttributeMaxDynamicSharedMemorySize, FSM_TOTAL);

    __half *abuf, *wt, *w2t, *a2buf;
    cudaGetSymbolAddress((void**)&abuf, g_Abuf);
    cudaGetSymbolAddress((void**)&wt, g_Wt);
    cudaGetSymbolAddress((void**)&w2t, g_W2t);
    cudaGetSymbolAddress((void**)&a2buf, g_A2buf);

    // 1. conversions + mask tile flags
    mask_flag_kernel<<<BATCH * 32 * 32, 128>>>(mask);
    split_rows_kernel<<<MTOT, 320>>>(hidden, abuf);
    split_w_kernel<<<(3840 * 320 + 255) / 256, 256>>>(w_qkv, wt, 3840);
    split_w_kernel<<<(1280 * 320 + 255) / 256, 256>>>(w_out, w2t, 1280);

    // 2. QKV projection (fp16 2-pass) -> fp16 q/k hi, v hi+lo
    gemm_mma_kernel<<<dim3(3840 / 128, MTOT / 128), 256, SM_TOTAL>>>(
        abuf, wt, 0, nullptr, nullptr);

    // 3. fp16 tensor-core flash attention -> split fp16 attn rows
    flash_mma_kernel<<<dim3(SEQ / 128, NH, BATCH), 128, FSM_TOTAL>>>(mask);

    // 4. out-projection (fp16 2-pass)
    gemm_mma_kernel<<<dim3(1280 / 128, MTOT / 128), 256, SM_TOTAL>>>(
        a2buf, w2t, 1, b_out, out);
}

// round 11
// speedup vs baseline: 4.7125x; 1.1128x over previous
#include <cuda_runtime.h>
#include <cuda_bf16.h>
#include <cuda_fp16.h>
#include <cstdint>

#define NH 20
#define DH 64
#define DMODEL 1280
#define BATCH 2
#define SEQ 2048
#define MTOT (BATCH*SEQ)      /* 4096 */
#define KTOT 2560             /* 2 * 1280 fp16 split-K concat */
#define NST 40                /* 2560 / 64 */

// ---------------------------------------------------------------------------
// Device-global scratch (allocation-free rule)
// ---------------------------------------------------------------------------
__device__ __half g_qh[BATCH*NH*SEQ*DH];         // [bh][s][dd] fp16 (hi only)
__device__ __half g_kh[BATCH*NH*SEQ*DH];         // [bh][s][dd] fp16 (hi only)
__device__ __half g_vh[BATCH*NH*DH*SEQ];         // d-major [bh][dd][s]
__device__ __half g_vl[BATCH*NH*DH*SEQ];         // fp16 residual of V
__device__ __half g_Abuf[(size_t)MTOT*KTOT];     // [Xh | Xl]
__device__ __half g_Wt[(size_t)3840*KTOT];       // [n][Wh | Wh]
__device__ __half g_W2t[(size_t)1280*KTOT];
__device__ __half g_A2buf[(size_t)MTOT*KTOT];    // [Ah | Al] of attn
__device__ unsigned char g_mflag[BATCH*32*32];   // mask 64x64 tile nonzero flags

// ---------------------------------------------------------------------------
// Baseline-PTX helpers
// ---------------------------------------------------------------------------
__device__ __forceinline__ uint32_t smem_u32(const void* p) {
    uint32_t a;
    asm("{ .reg .u64 t; cvta.to.shared.u64 t, %1; cvt.u32.u64 %0, t; }"
        : "=r"(a) : "l"(p));
    return a;
}
__device__ __forceinline__ uint32_t swz(uint32_t off) {  // SW128 byte swizzle
    return off ^ ((off >> 3) & 0x70);
}
__device__ __forceinline__ float ex2(float x) {
    float y;
    asm("ex2.approx.ftz.f32 %0, %1;" : "=f"(y) : "f"(x));
    return y;
}

#define CP_ASYNC16(dst, src) \
    asm volatile("cp.async.cg.shared.global [%0], [%1], 16;" :: "r"(dst), "l"(src))
#define CP_COMMIT() asm volatile("cp.async.commit_group;" ::: "memory")
#define CP_WAIT1()  asm volatile("cp.async.wait_group 1;" ::: "memory")
#define CP_WAIT0()  asm volatile("cp.async.wait_group 0;" ::: "memory")

__device__ __forceinline__ void ldm4(uint32_t addr, uint32_t* r) {
    asm volatile("ldmatrix.sync.aligned.m8n8.x4.shared.b16 {%0,%1,%2,%3}, [%4];"
                 : "=r"(r[0]), "=r"(r[1]), "=r"(r[2]), "=r"(r[3]) : "r"(addr));
}
__device__ __forceinline__ void mma_fp(float* c, const uint32_t* a, const uint32_t* b) {
    asm volatile("mma.sync.aligned.m16n8k16.row.col.f32.f16.f16.f32 "
                 "{%0,%1,%2,%3}, {%4,%5,%6,%7}, {%8,%9}, {%0,%1,%2,%3};"
                 : "+f"(c[0]), "+f"(c[1]), "+f"(c[2]), "+f"(c[3])
                 : "r"(a[0]), "r"(a[1]), "r"(a[2]), "r"(a[3]),
                   "r"(b[0]), "r"(b[1]));
}

__device__ __forceinline__ uint32_t pack_hf(__half x, __half y) {
    __half2 t = __halves2half2(x, y);
    return *reinterpret_cast<uint32_t*>(&t);
}

// ---------------------------------------------------------------------------
// Mask tile flags: 1 if any nonzero in the (b, qt, kt) 64x64 tile.
// ---------------------------------------------------------------------------
__global__ __launch_bounds__(128) void mask_flag_kernel(const float* __restrict__ Mask)
{
    const int blk = blockIdx.x;                 // b*1024 + qt*32 + kt
    const int b = blk >> 10, qt = (blk >> 5) & 31, kt = blk & 31;
    const float* p = Mask + ((size_t)b * SEQ + qt * 64) * SEQ + kt * 64;
    const int tid = threadIdx.x;
    bool nz = false;
#pragma unroll
    for (int i = 0; i < 8; i++) {
        const int t = tid + i * 128;
        const int r = t >> 4, c = (t & 15) * 4;
        float4 v = *(const float4*)&p[(size_t)r * SEQ + c];
        nz |= (v.x != 0.f) | (v.y != 0.f) | (v.z != 0.f) | (v.w != 0.f);
    }
    const int any = __syncthreads_or((int)nz);
    if (tid == 0) g_mflag[blk] = (unsigned char)(any != 0);
}

// ---------------------------------------------------------------------------
// Split conversions (fp32 -> fp16 hi/lo sections)
// ---------------------------------------------------------------------------
union HfPack { __half h[4]; uint2 u; };

__global__ __launch_bounds__(320) void split_rows_kernel(
    const float* __restrict__ src, __half* __restrict__ dst)
{
    const int m = blockIdx.x;
    const int k4 = threadIdx.x * 4;
    float4 v = *(const float4*)&src[(size_t)m * DMODEL + k4];
    HfPack hi, lo;
    float f[4] = {v.x, v.y, v.z, v.w};
#pragma unroll
    for (int i = 0; i < 4; i++) {
        hi.h[i] = __float2half_rn(f[i]);
        lo.h[i] = __float2half_rn(f[i] - __half2float(hi.h[i]));
    }
    __half* row = dst + (size_t)m * KTOT;
    *(uint2*)&row[k4]          = hi.u;
    *(uint2*)&row[DMODEL + k4] = lo.u;
}

__global__ __launch_bounds__(256) void split_w_kernel(
    const float* __restrict__ src, __half* __restrict__ dst, int N)
{
    const int idx = blockIdx.x * 256 + threadIdx.x;
    const int n = idx % N;
    const int k4i = idx / N;
    if (k4i >= DMODEL / 4) return;
    const int k = k4i * 4;
    HfPack hi;
#pragma unroll
    for (int i = 0; i < 4; i++)
        hi.h[i] = __float2half_rn(src[(size_t)(k + i) * N + n]);
    __half* row = dst + (size_t)n * KTOT;
    *(uint2*)&row[k]          = hi.u;
    *(uint2*)&row[DMODEL + k] = hi.u;
}

// ---------------------------------------------------------------------------
// QKV GEMM (big tiles): CTA 128x256, 8 warps of 64x64, 3-stage ring (144KB).
// Epilogue scatters fp16 q/k (row-major) and v hi+lo (d-major).
// ---------------------------------------------------------------------------
#define BSTAGE 49152          /* A 16KB + B 32KB */
#define SMQ_TOTAL (3*BSTAGE)

__global__ __launch_bounds__(256, 1) void qkv_gemm_kernel(
    const __half* __restrict__ A,    // [4096][2560]
    const __half* __restrict__ Bt)   // [3840][2560]
{
    extern __shared__ __align__(1024) char smem[];
    const uint32_t sb = smem_u32(smem);
    const int tid = threadIdx.x;
    const int lane = tid & 31, wid = tid >> 5;
    const int wm = wid >> 2, wn = wid & 3;      // warp grid 2 x 4 (64 x 64 tiles)
    const int m0 = blockIdx.y * 128, n0 = blockIdx.x * 256;

    auto load_stage = [&](int s, int buf) {
        const uint32_t base = sb + buf * BSTAGE;
        const __half* ap = A  + (size_t)m0 * KTOT + s * 64;
        const __half* bp = Bt + (size_t)n0 * KTOT + s * 64;
#pragma unroll
        for (int i = 0; i < 4; i++) {           // A: 128 rows x 8 chunks
            const int t = tid + i * 256;
            const int r = t >> 3, c = t & 7;
            CP_ASYNC16(base + swz(r * 128 + c * 16), ap + (size_t)r * KTOT + c * 8);
        }
#pragma unroll
        for (int i = 0; i < 8; i++) {           // B: 256 rows x 8 chunks
            const int t = tid + i * 256;
            const int r = t >> 3, c = t & 7;
            CP_ASYNC16(base + 16384 + swz(r * 128 + c * 16), bp + (size_t)r * KTOT + c * 8);
        }
        CP_COMMIT();
    };

    float acc[4][8][4];
#pragma unroll
    for (int mi = 0; mi < 4; mi++)
#pragma unroll
        for (int ni = 0; ni < 8; ni++)
#pragma unroll
            for (int q = 0; q < 4; q++) acc[mi][ni][q] = 0.f;

    load_stage(0, 0);
    load_stage(1, 1);

    const int arow = lane & 15;
    const int acol = (lane >> 4) * 8;
    const int b4row = ((lane >> 4) & 1) * 8 + (lane & 7);
    const int b4col = ((lane >> 3) & 1) * 8;

#pragma unroll 1
    for (int s = 0; s < NST; s++) {
        if (s + 1 < NST) { CP_WAIT1(); } else { CP_WAIT0(); }
        __syncthreads();
        if (s + 2 < NST) load_stage(s + 2, (s + 2) % 3);

        const uint32_t abase = sb + (s % 3) * BSTAGE;
        const uint32_t bbase = abase + 16384;
#pragma unroll
        for (int kf = 0; kf < 4; kf++) {
            uint32_t a[4][4], b[4][4];
#pragma unroll
            for (int mi = 0; mi < 4; mi++)
                ldm4(abase + swz((wm*64 + mi*16 + arow) * 128 + (kf*16 + acol) * 2), a[mi]);
#pragma unroll
            for (int n2 = 0; n2 < 4; n2++)
                ldm4(bbase + swz((wn*64 + n2*16 + b4row) * 128 + (kf*16 + b4col) * 2), b[n2]);
#pragma unroll
            for (int mi = 0; mi < 4; mi++)
#pragma unroll
                for (int n2 = 0; n2 < 4; n2++) {
                    mma_fp(acc[mi][n2*2],   a[mi], b[n2]);
                    mma_fp(acc[mi][n2*2+1], a[mi], b[n2] + 2);
                }
        }
    }

    // ---- epilogue: scatter into q/k (row-major fp16) and v (d-major hi+lo) ----
    const int grp = lane >> 2, tig = lane & 3;
    const int sec = n0 / DMODEL;                 // uniform per CTA (256 | 1280*? no:
    // 1280 % 256 == 0, so a 256 tile sits inside one section only when
    // n0/1280 == (n0+255)/1280; 1280/256=5 exactly -> always true.
#pragma unroll
    for (int mi = 0; mi < 4; mi++) {
#pragma unroll
        for (int half = 0; half < 2; half++) {
            const int r = wm * 64 + mi * 16 + grp + half * 8;
            const int m = m0 + r;
            const int bb = m >> 11, sq = m & 2047;
#pragma unroll
            for (int ni = 0; ni < 8; ni++) {
                const float v0 = acc[mi][ni][half * 2];
                const float v1 = acc[mi][ni][half * 2 + 1];
                const int nglob = n0 + wn * 64 + ni * 8 + tig * 2;
                const int rem = nglob - sec * DMODEL;
                const int hh = rem >> 6, dd = rem & 63;
                const int bh = bb * NH + hh;
                if (sec == 2) {
                    __half h0 = __float2half_rn(v0);
                    __half h1 = __float2half_rn(v1);
                    __half e0 = __float2half_rn(v0 - __half2float(h0));
                    __half e1 = __float2half_rn(v1 - __half2float(h1));
                    const size_t a0 = ((size_t)bh * DH + dd) * SEQ + sq;
                    const size_t a1 = ((size_t)bh * DH + dd + 1) * SEQ + sq;
                    g_vh[a0] = h0; g_vh[a1] = h1;
                    g_vl[a0] = e0; g_vl[a1] = e1;
                } else {
                    const size_t a = ((size_t)bh * SEQ + sq) * DH + dd;
                    const uint32_t hv = pack_hf(__float2half_rn(v0), __float2half_rn(v1));
                    if (sec == 0) *(uint32_t*)&g_qh[a] = hv;
                    else          *(uint32_t*)&g_kh[a] = hv;
                }
            }
        }
    }
}

// ---------------------------------------------------------------------------
// Out-projection GEMM (proven 128x128, 8 warps of 64x32): out = A*B^T + bias
// ---------------------------------------------------------------------------
#define STAGE_BYTES 32768
#define SM_TOTAL (3*STAGE_BYTES)

__global__ __launch_bounds__(256) void out_gemm_kernel(
    const __half* __restrict__ A,
    const __half* __restrict__ Bt,
    const float* __restrict__ bias, float* __restrict__ Cout)
{
    extern __shared__ __align__(1024) char smem[];
    const uint32_t sb = smem_u32(smem);
    const int tid = threadIdx.x;
    const int lane = tid & 31, wid = tid >> 5;
    const int wm = wid >> 2, wn = wid & 3;
    const int m0 = blockIdx.y * 128, n0 = blockIdx.x * 128;

    auto load_stage = [&](int s, int buf) {
        const uint32_t base = sb + buf * STAGE_BYTES;
        const __half* ap = A  + (size_t)m0 * KTOT + s * 64;
        const __half* bp = Bt + (size_t)n0 * KTOT + s * 64;
#pragma unroll
        for (int i = 0; i < 4; i++) {
            const int t = tid + i * 256;
            const int r = t >> 3, c = t & 7;
            CP_ASYNC16(base + swz(r * 128 + c * 16), ap + (size_t)r * KTOT + c * 8);
        }
#pragma unroll
        for (int i = 0; i < 4; i++) {
            const int t = tid + i * 256;
            const int r = t >> 3, c = t & 7;
            CP_ASYNC16(base + 16384 + swz(r * 128 + c * 16), bp + (size_t)r * KTOT + c * 8);
        }
        CP_COMMIT();
    };

    float acc[4][4][4];
#pragma unroll
    for (int mi = 0; mi < 4; mi++)
#pragma unroll
        for (int ni = 0; ni < 4; ni++)
#pragma unroll
            for (int q = 0; q < 4; q++) acc[mi][ni][q] = 0.f;

    load_stage(0, 0);
    load_stage(1, 1);

    const int arow = lane & 15;
    const int acol = (lane >> 4) * 8;
    const int b4row = ((lane >> 4) & 1) * 8 + (lane & 7);
    const int b4col = ((lane >> 3) & 1) * 8;

#pragma unroll 1
    for (int s = 0; s < NST; s++) {
        if (s + 1 < NST) { CP_WAIT1(); } else { CP_WAIT0(); }
        __syncthreads();
        if (s + 2 < NST) load_stage(s + 2, (s + 2) % 3);

        const uint32_t abase = sb + (s % 3) * STAGE_BYTES;
        const uint32_t bbase = abase + 16384;
#pragma unroll
        for (int kf = 0; kf < 4; kf++) {
            uint32_t a[4][4], b2[2][4];
#pragma unroll
            for (int mi = 0; mi < 4; mi++)
                ldm4(abase + swz((wm*64 + mi*16 + arow) * 128 + (kf*16 + acol) * 2), a[mi]);
#pragma unroll
            for (int n2 = 0; n2 < 2; n2++)
                ldm4(bbase + swz((wn*32 + n2*16 + b4row) * 128 + (kf*16 + b4col) * 2), b2[n2]);
#pragma unroll
            for (int mi = 0; mi < 4; mi++)
#pragma unroll
                for (int n2 = 0; n2 < 2; n2++) {
                    mma_fp(acc[mi][n2*2],   a[mi], b2[n2]);
                    mma_fp(acc[mi][n2*2+1], a[mi], b2[n2] + 2);
                }
        }
    }

    const int grp = lane >> 2, tig = lane & 3;
#pragma unroll
    for (int mi = 0; mi < 4; mi++) {
#pragma unroll
        for (int half = 0; half < 2; half++) {
            const int m = m0 + wm * 64 + mi * 16 + grp + half * 8;
#pragma unroll
            for (int ni = 0; ni < 4; ni++) {
                const int nglob = n0 + wn * 32 + ni * 8 + tig * 2;
                float2 bv = *(const float2*)&bias[nglob];
                *(float2*)&Cout[(size_t)m * DMODEL + nglob] =
                    make_float2(acc[mi][ni][half*2] + bv.x, acc[mi][ni][half*2+1] + bv.y);
            }
        }
    }
}

// ---------------------------------------------------------------------------
// fp16 tensor-core flash attention.
// CTA: 128 queries x one (b,h); 4 warps, each M=32, N=64 keys.
// QK^T: 1-pass fp16. PV: 2-pass (Ph*Vh + Ph*Vl). Mask gated by tile flags.
// smem: Qh 16KB | 2 stages x {Kh,Vh,Vl each 8KB} = 64KB.
// ---------------------------------------------------------------------------
#define FSM_TOTAL 65536

__global__ __launch_bounds__(128, 2) void flash_mma_kernel(const float* __restrict__ Mask)
{
    extern __shared__ __align__(1024) char fsm[];
    const uint32_t sb = smem_u32(fsm);
    const int tid = threadIdx.x, lane = tid & 31, wid = tid >> 5;
    const int grp = lane >> 2, tig = lane & 3;
    const int qb = blockIdx.x, h = blockIdx.y, b = blockIdx.z;
    const int bh = b * NH + h;

    const __half* qhp = g_qh + ((size_t)bh * SEQ + qb * 128) * DH;
    const __half* khp = g_kh + (size_t)bh * SEQ * DH;
    const __half* vhp = g_vh + (size_t)bh * DH * SEQ;
    const __half* vlp = g_vl + (size_t)bh * DH * SEQ;

#pragma unroll
    for (int i = 0; i < 8; i++) {
        const int t = tid + i * 128;
        const int r = t >> 3, c = t & 7;
        CP_ASYNC16(sb + swz(r * 128 + c * 16), qhp + (size_t)r * DH + c * 8);
    }

    auto load_kv = [&](int kb, int buf) {
        const uint32_t base = sb + 16384 + buf * 24576;
#pragma unroll
        for (int i = 0; i < 4; i++) {
            const int t = tid + i * 128;
            const int r = t >> 3, c = t & 7;
            const uint32_t d = swz(r * 128 + c * 16);
            CP_ASYNC16(base + d,         khp + (size_t)(kb * 64 + r) * DH + c * 8);
            CP_ASYNC16(base + 8192 + d,  vhp + (size_t)r * SEQ + kb * 64 + c * 8);
            CP_ASYNC16(base + 16384 + d, vlp + (size_t)r * SEQ + kb * 64 + c * 8);
        }
        CP_COMMIT();
    };
    load_kv(0, 0);
    load_kv(1, 1);

    float O[2][8][4];
#pragma unroll
    for (int t = 0; t < 2; t++)
#pragma unroll
        for (int nf = 0; nf < 8; nf++)
#pragma unroll
            for (int q = 0; q < 4; q++) O[t][nf][q] = 0.f;
    float mrun[4] = {-1e30f, -1e30f, -1e30f, -1e30f};
    float lrun[4] = {0.f, 0.f, 0.f, 0.f};

    const int qrowbase = qb * 128 + wid * 32;
    const float* mrp[4];
#pragma unroll
    for (int j = 0; j < 4; j++) {
        const int t = j >> 1, half = j & 1;
        mrp[j] = Mask + ((size_t)b * SEQ + qrowbase + t * 16 + half * 8 + grp) * SEQ;
    }
    const unsigned char* flagp = g_mflag + (size_t)b * 1024 + (qb * 2 + (wid >> 1)) * 32;

    const int arow = lane & 15;
    const int acol = (lane >> 4) * 8;
    const int b4row = ((lane >> 4) & 1) * 8 + (lane & 7);
    const int b4col = ((lane >> 3) & 1) * 8;

    const float SCL2E = 0.125f * 1.44269504f;
    const float L2E = 1.44269504f;

#pragma unroll 1
    for (int kb = 0; kb < 32; kb++) {
        if (kb < 31) { CP_WAIT1(); } else { CP_WAIT0(); }
        __syncthreads();
        const uint32_t kbase = sb + 16384 + (kb & 1) * 24576;

        // ---- S = Q K^T (1-pass fp16) ----
        float S[2][8][4];
#pragma unroll
        for (int t = 0; t < 2; t++)
#pragma unroll
            for (int nf = 0; nf < 8; nf++)
#pragma unroll
                for (int q = 0; q < 4; q++) S[t][nf][q] = 0.f;

#pragma unroll
        for (int kf = 0; kf < 4; kf++) {
            uint32_t aq[2][4];
#pragma unroll
            for (int t = 0; t < 2; t++)
                ldm4(sb + swz((wid * 32 + t * 16 + arow) * 128 + (kf * 16 + acol) * 2), aq[t]);
#pragma unroll
            for (int n2 = 0; n2 < 4; n2++) {
                uint32_t kh4[4];
                ldm4(kbase + swz((n2 * 16 + b4row) * 128 + (kf * 16 + b4col) * 2), kh4);
#pragma unroll
                for (int t = 0; t < 2; t++) {
                    mma_fp(S[t][n2*2],   aq[t], kh4);
                    mma_fp(S[t][n2*2+1], aq[t], kh4 + 2);
                }
            }
        }

        // ---- scale (+ mask if tile nonzero), log2 domain ----
        if (flagp[kb]) {
#pragma unroll
            for (int t = 0; t < 2; t++)
#pragma unroll
                for (int nf = 0; nf < 8; nf++) {
                    float2 u = *(const float2*)&mrp[t*2    ][kb * 64 + nf * 8 + tig * 2];
                    float2 w = *(const float2*)&mrp[t*2 + 1][kb * 64 + nf * 8 + tig * 2];
                    S[t][nf][0] = fmaf(S[t][nf][0], SCL2E, u.x * L2E);
                    S[t][nf][1] = fmaf(S[t][nf][1], SCL2E, u.y * L2E);
                    S[t][nf][2] = fmaf(S[t][nf][2], SCL2E, w.x * L2E);
                    S[t][nf][3] = fmaf(S[t][nf][3], SCL2E, w.y * L2E);
                }
        } else {
#pragma unroll
            for (int t = 0; t < 2; t++)
#pragma unroll
                for (int nf = 0; nf < 8; nf++)
#pragma unroll
                    for (int q = 0; q < 4; q++) S[t][nf][q] *= SCL2E;
        }

        // ---- online softmax per row-set j ----
        float al[4];
#pragma unroll
        for (int j = 0; j < 4; j++) {
            const int t = j >> 1, half = j & 1;
            float rm = -1e30f;
#pragma unroll
            for (int nf = 0; nf < 8; nf++)
                rm = fmaxf(rm, fmaxf(S[t][nf][half*2], S[t][nf][half*2+1]));
            rm = fmaxf(rm, __shfl_xor_sync(0xffffffffu, rm, 1));
            rm = fmaxf(rm, __shfl_xor_sync(0xffffffffu, rm, 2));
            const float mn = fmaxf(mrun[j], rm);
            al[j] = ex2(mrun[j] - mn);
            mrun[j] = mn;
            float rs = 0.f;
#pragma unroll
            for (int nf = 0; nf < 8; nf++) {
                const float p0 = ex2(S[t][nf][half*2]   - mn);
                const float p1 = ex2(S[t][nf][half*2+1] - mn);
                S[t][nf][half*2]   = p0;
                S[t][nf][half*2+1] = p1;
                rs += p0 + p1;
            }
            rs += __shfl_xor_sync(0xffffffffu, rs, 1);
            rs += __shfl_xor_sync(0xffffffffu, rs, 2);
            lrun[j] = lrun[j] * al[j] + rs;
        }
#pragma unroll
        for (int t = 0; t < 2; t++)
#pragma unroll
            for (int nf = 0; nf < 8; nf++) {
                O[t][nf][0] *= al[t*2];   O[t][nf][1] *= al[t*2];
                O[t][nf][2] *= al[t*2+1]; O[t][nf][3] *= al[t*2+1];
            }

        // ---- O += Ph Vh + Ph Vl (2-pass) ----
#pragma unroll
        for (int kc = 0; kc < 4; kc++) {
            uint32_t phi[2][4];
#pragma unroll
            for (int t = 0; t < 2; t++) {
#pragma unroll
                for (int hf = 0; hf < 2; hf++) {
                    const int nf = kc * 2 + hf;
                    phi[t][hf*2+0] = pack_hf(__float2half_rn(S[t][nf][0]),
                                             __float2half_rn(S[t][nf][1]));
                    phi[t][hf*2+1] = pack_hf(__float2half_rn(S[t][nf][2]),
                                             __float2half_rn(S[t][nf][3]));
                }
            }
#pragma unroll
            for (int n2 = 0; n2 < 4; n2++) {
                uint32_t vh4[4], vl4[4];
                const uint32_t off = swz((n2 * 16 + b4row) * 128 + (kc * 16 + b4col) * 2);
                ldm4(kbase + 8192 + off, vh4);
                ldm4(kbase + 16384 + off, vl4);
#pragma unroll
                for (int t = 0; t < 2; t++) {
                    mma_fp(O[t][n2*2],   phi[t], vh4);
                    mma_fp(O[t][n2*2],   phi[t], vl4);
                    mma_fp(O[t][n2*2+1], phi[t], vh4 + 2);
                    mma_fp(O[t][n2*2+1], phi[t], vl4 + 2);
                }
            }
        }

        __syncthreads();
        if (kb + 2 < 32) load_kv(kb + 2, kb & 1);
    }

    // ---- epilogue: write normalized O as [Ah|Al] split rows of g_A2buf ----
#pragma unroll
    for (int j = 0; j < 4; j++) {
        const int t = j >> 1, half = j & 1;
        const int row = qrowbase + t * 16 + half * 8 + grp;
        const float inv = 1.f / lrun[j];
        __half* op = g_A2buf + ((size_t)b * SEQ + row) * KTOT;
#pragma unroll
        for (int nf = 0; nf < 8; nf++) {
            const int col = h * 64 + nf * 8 + tig * 2;
            const float x = O[t][nf][half*2] * inv, y = O[t][nf][half*2+1] * inv;
            __half hx = __float2half_rn(x), hy = __float2half_rn(y);
            *(uint32_t*)&op[col]          = pack_hf(hx, hy);
            *(uint32_t*)&op[DMODEL + col] = pack_hf(__float2half_rn(x - __half2float(hx)),
                                                    __float2half_rn(y - __half2float(hy)));
        }
    }
}

// ---------------------------------------------------------------------------
extern "C" void kernel_launch(void* const* d_in, const int* in_sizes, int n_in,
                              void* d_out, int out_size)
{
    const float* hidden = (const float*)d_in[0];
    const float* mask   = (const float*)d_in[1];
    const float* w_qkv  = (const float*)d_in[2];
    const float* w_out  = (const float*)d_in[3];
    const float* b_out  = (const float*)d_in[4];
    float* out = (float*)d_out;

    cudaFuncSetAttribute(qkv_gemm_kernel,
                         cudaFuncAttributeMaxDynamicSharedMemorySize, SMQ_TOTAL);
    cudaFuncSetAttribute(out_gemm_kernel,
                         cudaFuncAttributeMaxDynamicSharedMemorySize, SM_TOTAL);
    cudaFuncSetAttribute(flash_mma_kernel,
                         cudaFuncAttributeMaxDynamicSharedMemorySize, FSM_TOTAL);

    __half *abuf, *wt, *w2t, *a2buf;
    cudaGetSymbolAddress((void**)&abuf, g_Abuf);
    cudaGetSymbolAddress((void**)&wt, g_Wt);
    cudaGetSymbolAddress((void**)&w2t, g_W2t);
    cudaGetSymbolAddress((void**)&a2buf, g_A2buf);

    // 1. conversions + mask tile flags
    mask_flag_kernel<<<BATCH * 32 * 32, 128>>>(mask);
    split_rows_kernel<<<MTOT, 320>>>(hidden, abuf);
    split_w_kernel<<<(3840 * 320 + 255) / 256, 256>>>(w_qkv, wt, 3840);
    split_w_kernel<<<(1280 * 320 + 255) / 256, 256>>>(w_out, w2t, 1280);

    // 2. QKV projection (fp16 2-pass, 128x256 tiles) -> fp16 q/k hi, v hi+lo
    qkv_gemm_kernel<<<dim3(3840 / 256, MTOT / 128), 256, SMQ_TOTAL>>>(abuf, wt);

    // 3. fp16 tensor-core flash attention -> split fp16 attn rows
    flash_mma_kernel<<<dim3(SEQ / 128, NH, BATCH), 128, FSM_TOTAL>>>(mask);

    // 4. out-projection (fp16 2-pass, 128x128 tiles)
    out_gemm_kernel<<<dim3(1280 / 128, MTOT / 128), 256, SM_TOTAL>>>(
        a2buf, w2t, b_out, out);
}

// round 12
// speedup vs baseline: 5.0537x; 1.0724x over previous
#include <cuda_runtime.h>
#include <cuda_bf16.h>
#include <cuda_fp16.h>
#include <cstdint>

#define NH 20
#define DH 64
#define DMODEL 1280
#define BATCH 2
#define SEQ 2048
#define MTOT (BATCH*SEQ)      /* 4096 */
#define KTOT 2560             /* 2 * 1280 fp16 split-K concat (A side) */
#define NST 40                /* 2560 / 64 */

// ---------------------------------------------------------------------------
// Device-global scratch (allocation-free rule)
// ---------------------------------------------------------------------------
__device__ __half g_qh[BATCH*NH*SEQ*DH];         // [bh][s][dd] fp16
__device__ __half g_kh[BATCH*NH*SEQ*DH];         // [bh][s][dd] fp16
__device__ __half g_vh[BATCH*NH*DH*SEQ];         // d-major [bh][dd][s] fp16
__device__ __half g_Abuf[(size_t)MTOT*KTOT];     // [Xh | Xl]
__device__ __half g_Wt[(size_t)3840*DMODEL];     // [n][Wh] (read twice by GEMM)
__device__ __half g_W2t[(size_t)1280*DMODEL];
__device__ __half g_A2buf[(size_t)MTOT*KTOT];    // [Ah | Al] of attn
__device__ unsigned char g_mflag[BATCH*32*32];   // mask 64x64 tile nonzero flags

// ---------------------------------------------------------------------------
// Baseline-PTX helpers
// ---------------------------------------------------------------------------
__device__ __forceinline__ uint32_t smem_u32(const void* p) {
    uint32_t a;
    asm("{ .reg .u64 t; cvta.to.shared.u64 t, %1; cvt.u32.u64 %0, t; }"
        : "=r"(a) : "l"(p));
    return a;
}
__device__ __forceinline__ uint32_t swz(uint32_t off) {  // SW128 byte swizzle
    return off ^ ((off >> 3) & 0x70);
}
__device__ __forceinline__ float ex2(float x) {
    float y;
    asm("ex2.approx.ftz.f32 %0, %1;" : "=f"(y) : "f"(x));
    return y;
}

#define CP_ASYNC16(dst, src) \
    asm volatile("cp.async.cg.shared.global [%0], [%1], 16;" :: "r"(dst), "l"(src))
#define CP_COMMIT() asm volatile("cp.async.commit_group;" ::: "memory")
#define CP_WAIT1()  asm volatile("cp.async.wait_group 1;" ::: "memory")
#define CP_WAIT0()  asm volatile("cp.async.wait_group 0;" ::: "memory")

__device__ __forceinline__ void ldm4(uint32_t addr, uint32_t* r) {
    asm volatile("ldmatrix.sync.aligned.m8n8.x4.shared.b16 {%0,%1,%2,%3}, [%4];"
                 : "=r"(r[0]), "=r"(r[1]), "=r"(r[2]), "=r"(r[3]) : "r"(addr));
}
__device__ __forceinline__ void mma_fp(float* c, const uint32_t* a, const uint32_t* b) {
    asm volatile("mma.sync.aligned.m16n8k16.row.col.f32.f16.f16.f32 "
                 "{%0,%1,%2,%3}, {%4,%5,%6,%7}, {%8,%9}, {%0,%1,%2,%3};"
                 : "+f"(c[0]), "+f"(c[1]), "+f"(c[2]), "+f"(c[3])
                 : "r"(a[0]), "r"(a[1]), "r"(a[2]), "r"(a[3]),
                   "r"(b[0]), "r"(b[1]));
}

__device__ __forceinline__ uint32_t pack_hf(__half x, __half y) {
    __half2 t = __halves2half2(x, y);
    return *reinterpret_cast<uint32_t*>(&t);
}

// ---------------------------------------------------------------------------
// Mask tile flags: 1 if any nonzero in the (b, qt, kt) 64x64 tile.
// ---------------------------------------------------------------------------
__global__ __launch_bounds__(128) void mask_flag_kernel(const float* __restrict__ Mask)
{
    const int blk = blockIdx.x;                 // b*1024 + qt*32 + kt
    const int b = blk >> 10, qt = (blk >> 5) & 31, kt = blk & 31;
    const float* p = Mask + ((size_t)b * SEQ + qt * 64) * SEQ + kt * 64;
    const int tid = threadIdx.x;
    bool nz = false;
#pragma unroll
    for (int i = 0; i < 8; i++) {
        const int t = tid + i * 128;
        const int r = t >> 4, c = (t & 15) * 4;
        float4 v = *(const float4*)&p[(size_t)r * SEQ + c];
        nz |= (v.x != 0.f) | (v.y != 0.f) | (v.z != 0.f) | (v.w != 0.f);
    }
    const int any = __syncthreads_or((int)nz);
    if (tid == 0) g_mflag[blk] = (unsigned char)(any != 0);
}

// ---------------------------------------------------------------------------
// Split conversions (fp32 -> fp16)
// ---------------------------------------------------------------------------
union HfPack { __half h[4]; uint2 u; };

// src [rows][1280] fp32 -> dst [rows][2560] fp16 sections [hi | lo]
__global__ __launch_bounds__(320) void split_rows_kernel(
    const float* __restrict__ src, __half* __restrict__ dst)
{
    const int m = blockIdx.x;
    const int k4 = threadIdx.x * 4;
    float4 v = *(const float4*)&src[(size_t)m * DMODEL + k4];
    HfPack hi, lo;
    float f[4] = {v.x, v.y, v.z, v.w};
#pragma unroll
    for (int i = 0; i < 4; i++) {
        hi.h[i] = __float2half_rn(f[i]);
        lo.h[i] = __float2half_rn(f[i] - __half2float(hi.h[i]));
    }
    __half* row = dst + (size_t)m * KTOT;
    *(uint2*)&row[k4]          = hi.u;
    *(uint2*)&row[DMODEL + k4] = lo.u;
}

// src W [K=1280][N] fp32 -> dst [N][1280] fp16 (hi only, transposed)
__global__ __launch_bounds__(256) void split_w_kernel(
    const float* __restrict__ src, __half* __restrict__ dst, int N)
{
    const int idx = blockIdx.x * 256 + threadIdx.x;
    const int n = idx % N;
    const int k4i = idx / N;
    if (k4i >= DMODEL / 4) return;
    const int k = k4i * 4;
    HfPack hi;
#pragma unroll
    for (int i = 0; i < 4; i++)
        hi.h[i] = __float2half_rn(src[(size_t)(k + i) * N + n]);
    *(uint2*)&dst[(size_t)n * DMODEL + k] = hi.u;
}

// B-section column offset for stage s: K' index wraps at 1280.
__device__ __forceinline__ int bcol_of(int s) { return (s >= 20 ? s - 20 : s) * 64; }

// ---------------------------------------------------------------------------
// QKV GEMM (big tiles): CTA 128x256, 8 warps of 64x64, 3-stage ring (144KB).
// A [4096][2560] = [Xh|Xl]; B [3840][1280] read twice (K' wrap).
// Epilogue scatters fp16 q/k (row-major) and v (d-major, hi only).
// ---------------------------------------------------------------------------
#define BSTAGE 49152          /* A 16KB + B 32KB */
#define SMQ_TOTAL (3*BSTAGE)

__global__ __launch_bounds__(256, 1) void qkv_gemm_kernel(
    const __half* __restrict__ A,
    const __half* __restrict__ Bt)
{
    extern __shared__ __align__(1024) char smem[];
    const uint32_t sb = smem_u32(smem);
    const int tid = threadIdx.x;
    const int lane = tid & 31, wid = tid >> 5;
    const int wm = wid >> 2, wn = wid & 3;      // warp grid 2 x 4 (64 x 64 tiles)
    const int m0 = blockIdx.y * 128, n0 = blockIdx.x * 256;

    auto load_stage = [&](int s, int buf) {
        const uint32_t base = sb + buf * BSTAGE;
        const __half* ap = A  + (size_t)m0 * KTOT + s * 64;
        const __half* bp = Bt + (size_t)n0 * DMODEL + bcol_of(s);
#pragma unroll
        for (int i = 0; i < 4; i++) {           // A: 128 rows x 8 chunks
            const int t = tid + i * 256;
            const int r = t >> 3, c = t & 7;
            CP_ASYNC16(base + swz(r * 128 + c * 16), ap + (size_t)r * KTOT + c * 8);
        }
#pragma unroll
        for (int i = 0; i < 8; i++) {           // B: 256 rows x 8 chunks
            const int t = tid + i * 256;
            const int r = t >> 3, c = t & 7;
            CP_ASYNC16(base + 16384 + swz(r * 128 + c * 16), bp + (size_t)r * DMODEL + c * 8);
        }
        CP_COMMIT();
    };

    float acc[4][8][4];
#pragma unroll
    for (int mi = 0; mi < 4; mi++)
#pragma unroll
        for (int ni = 0; ni < 8; ni++)
#pragma unroll
            for (int q = 0; q < 4; q++) acc[mi][ni][q] = 0.f;

    load_stage(0, 0);
    load_stage(1, 1);

    const int arow = lane & 15;
    const int acol = (lane >> 4) * 8;
    const int b4row = ((lane >> 4) & 1) * 8 + (lane & 7);
    const int b4col = ((lane >> 3) & 1) * 8;

#pragma unroll 1
    for (int s = 0; s < NST; s++) {
        if (s + 1 < NST) { CP_WAIT1(); } else { CP_WAIT0(); }
        __syncthreads();
        if (s + 2 < NST) load_stage(s + 2, (s + 2) % 3);

        const uint32_t abase = sb + (s % 3) * BSTAGE;
        const uint32_t bbase = abase + 16384;
#pragma unroll
        for (int kf = 0; kf < 4; kf++) {
            uint32_t a[4][4], b[4][4];
#pragma unroll
            for (int mi = 0; mi < 4; mi++)
                ldm4(abase + swz((wm*64 + mi*16 + arow) * 128 + (kf*16 + acol) * 2), a[mi]);
#pragma unroll
            for (int n2 = 0; n2 < 4; n2++)
                ldm4(bbase + swz((wn*64 + n2*16 + b4row) * 128 + (kf*16 + b4col) * 2), b[n2]);
#pragma unroll
            for (int mi = 0; mi < 4; mi++)
#pragma unroll
                for (int n2 = 0; n2 < 4; n2++) {
                    mma_fp(acc[mi][n2*2],   a[mi], b[n2]);
                    mma_fp(acc[mi][n2*2+1], a[mi], b[n2] + 2);
                }
        }
    }

    // ---- epilogue: scatter into q/k (row-major fp16) and v (d-major fp16) ----
    const int grp = lane >> 2, tig = lane & 3;
    const int sec = n0 / DMODEL;   // 1280 % 256 == 0 -> tile inside one section
#pragma unroll
    for (int mi = 0; mi < 4; mi++) {
#pragma unroll
        for (int half = 0; half < 2; half++) {
            const int r = wm * 64 + mi * 16 + grp + half * 8;
            const int m = m0 + r;
            const int bb = m >> 11, sq = m & 2047;
#pragma unroll
            for (int ni = 0; ni < 8; ni++) {
                const float v0 = acc[mi][ni][half * 2];
                const float v1 = acc[mi][ni][half * 2 + 1];
                const int nglob = n0 + wn * 64 + ni * 8 + tig * 2;
                const int rem = nglob - sec * DMODEL;
                const int hh = rem >> 6, dd = rem & 63;
                const int bh = bb * NH + hh;
                if (sec == 2) {
                    g_vh[((size_t)bh * DH + dd) * SEQ + sq]     = __float2half_rn(v0);
                    g_vh[((size_t)bh * DH + dd + 1) * SEQ + sq] = __float2half_rn(v1);
                } else {
                    const size_t a = ((size_t)bh * SEQ + sq) * DH + dd;
                    const uint32_t hv = pack_hf(__float2half_rn(v0), __float2half_rn(v1));
                    if (sec == 0) *(uint32_t*)&g_qh[a] = hv;
                    else          *(uint32_t*)&g_kh[a] = hv;
                }
            }
        }
    }
}

// ---------------------------------------------------------------------------
// Out-projection GEMM (128x128, 8 warps of 64x32): out = A*B^T + bias
// A [4096][2560] = [Ah|Al]; B [1280][1280] read twice (K' wrap).
// ---------------------------------------------------------------------------
#define STAGE_BYTES 32768
#define SM_TOTAL (3*STAGE_BYTES)

__global__ __launch_bounds__(256) void out_gemm_kernel(
    const __half* __restrict__ A,
    const __half* __restrict__ Bt,
    const float* __restrict__ bias, float* __restrict__ Cout)
{
    extern __shared__ __align__(1024) char smem[];
    const uint32_t sb = smem_u32(smem);
    const int tid = threadIdx.x;
    const int lane = tid & 31, wid = tid >> 5;
    const int wm = wid >> 2, wn = wid & 3;
    const int m0 = blockIdx.y * 128, n0 = blockIdx.x * 128;

    auto load_stage = [&](int s, int buf) {
        const uint32_t base = sb + buf * STAGE_BYTES;
        const __half* ap = A  + (size_t)m0 * KTOT + s * 64;
        const __half* bp = Bt + (size_t)n0 * DMODEL + bcol_of(s);
#pragma unroll
        for (int i = 0; i < 4; i++) {
            const int t = tid + i * 256;
            const int r = t >> 3, c = t & 7;
            CP_ASYNC16(base + swz(r * 128 + c * 16), ap + (size_t)r * KTOT + c * 8);
        }
#pragma unroll
        for (int i = 0; i < 4; i++) {
            const int t = tid + i * 256;
            const int r = t >> 3, c = t & 7;
            CP_ASYNC16(base + 16384 + swz(r * 128 + c * 16), bp + (size_t)r * DMODEL + c * 8);
        }
        CP_COMMIT();
    };

    float acc[4][4][4];
#pragma unroll
    for (int mi = 0; mi < 4; mi++)
#pragma unroll
        for (int ni = 0; ni < 4; ni++)
#pragma unroll
            for (int q = 0; q < 4; q++) acc[mi][ni][q] = 0.f;

    load_stage(0, 0);
    load_stage(1, 1);

    const int arow = lane & 15;
    const int acol = (lane >> 4) * 8;
    const int b4row = ((lane >> 4) & 1) * 8 + (lane & 7);
    const int b4col = ((lane >> 3) & 1) * 8;

#pragma unroll 1
    for (int s = 0; s < NST; s++) {
        if (s + 1 < NST) { CP_WAIT1(); } else { CP_WAIT0(); }
        __syncthreads();
        if (s + 2 < NST) load_stage(s + 2, (s + 2) % 3);

        const uint32_t abase = sb + (s % 3) * STAGE_BYTES;
        const uint32_t bbase = abase + 16384;
#pragma unroll
        for (int kf = 0; kf < 4; kf++) {
            uint32_t a[4][4], b2[2][4];
#pragma unroll
            for (int mi = 0; mi < 4; mi++)
                ldm4(abase + swz((wm*64 + mi*16 + arow) * 128 + (kf*16 + acol) * 2), a[mi]);
#pragma unroll
            for (int n2 = 0; n2 < 2; n2++)
                ldm4(bbase + swz((wn*32 + n2*16 + b4row) * 128 + (kf*16 + b4col) * 2), b2[n2]);
#pragma unroll
            for (int mi = 0; mi < 4; mi++)
#pragma unroll
                for (int n2 = 0; n2 < 2; n2++) {
                    mma_fp(acc[mi][n2*2],   a[mi], b2[n2]);
                    mma_fp(acc[mi][n2*2+1], a[mi], b2[n2] + 2);
                }
        }
    }

    const int grp = lane >> 2, tig = lane & 3;
#pragma unroll
    for (int mi = 0; mi < 4; mi++) {
#pragma unroll
        for (int half = 0; half < 2; half++) {
            const int m = m0 + wm * 64 + mi * 16 + grp + half * 8;
#pragma unroll
            for (int ni = 0; ni < 4; ni++) {
                const int nglob = n0 + wn * 32 + ni * 8 + tig * 2;
                float2 bv = *(const float2*)&bias[nglob];
                *(float2*)&Cout[(size_t)m * DMODEL + nglob] =
                    make_float2(acc[mi][ni][half*2] + bv.x, acc[mi][ni][half*2+1] + bv.y);
            }
        }
    }
}

// ---------------------------------------------------------------------------
// fp16 tensor-core flash attention.
// CTA: 128 queries x one (b,h); 4 warps, each M=32, N=64 keys.
// QK^T: 1-pass fp16. PV: 1-pass fp16. Mask gated by tile flags.
// smem: Qh 16KB | 2 stages x {Kh,Vh each 8KB} = 48KB -> 3 CTAs/SM.
// ---------------------------------------------------------------------------
#define FSM_TOTAL 49152

__global__ __launch_bounds__(128, 3) void flash_mma_kernel(const float* __restrict__ Mask)
{
    extern __shared__ __align__(1024) char fsm[];
    const uint32_t sb = smem_u32(fsm);
    const int tid = threadIdx.x, lane = tid & 31, wid = tid >> 5;
    const int grp = lane >> 2, tig = lane & 3;
    const int qb = blockIdx.x, h = blockIdx.y, b = blockIdx.z;
    const int bh = b * NH + h;

    const __half* qhp = g_qh + ((size_t)bh * SEQ + qb * 128) * DH;
    const __half* khp = g_kh + (size_t)bh * SEQ * DH;
    const __half* vhp = g_vh + (size_t)bh * DH * SEQ;

#pragma unroll
    for (int i = 0; i < 8; i++) {
        const int t = tid + i * 128;
        const int r = t >> 3, c = t & 7;
        CP_ASYNC16(sb + swz(r * 128 + c * 16), qhp + (size_t)r * DH + c * 8);
    }

    auto load_kv = [&](int kb, int buf) {
        const uint32_t base = sb + 16384 + buf * 16384;
#pragma unroll
        for (int i = 0; i < 4; i++) {
            const int t = tid + i * 128;
            const int r = t >> 3, c = t & 7;
            const uint32_t d = swz(r * 128 + c * 16);
            CP_ASYNC16(base + d,        khp + (size_t)(kb * 64 + r) * DH + c * 8);
            CP_ASYNC16(base + 8192 + d, vhp + (size_t)r * SEQ + kb * 64 + c * 8);
        }
        CP_COMMIT();
    };
    load_kv(0, 0);
    load_kv(1, 1);

    float O[2][8][4];
#pragma unroll
    for (int t = 0; t < 2; t++)
#pragma unroll
        for (int nf = 0; nf < 8; nf++)
#pragma unroll
            for (int q = 0; q < 4; q++) O[t][nf][q] = 0.f;
    float mrun[4] = {-1e30f, -1e30f, -1e30f, -1e30f};
    float lrun[4] = {0.f, 0.f, 0.f, 0.f};

    const int qrowbase = qb * 128 + wid * 32;
    const float* mrp[4];
#pragma unroll
    for (int j = 0; j < 4; j++) {
        const int t = j >> 1, half = j & 1;
        mrp[j] = Mask + ((size_t)b * SEQ + qrowbase + t * 16 + half * 8 + grp) * SEQ;
    }
    const unsigned char* flagp = g_mflag + (size_t)b * 1024 + (qb * 2 + (wid >> 1)) * 32;

    const int arow = lane & 15;
    const int acol = (lane >> 4) * 8;
    const int b4row = ((lane >> 4) & 1) * 8 + (lane & 7);
    const int b4col = ((lane >> 3) & 1) * 8;

    const float SCL2E = 0.125f * 1.44269504f;
    const float L2E = 1.44269504f;

#pragma unroll 1
    for (int kb = 0; kb < 32; kb++) {
        if (kb < 31) { CP_WAIT1(); } else { CP_WAIT0(); }
        __syncthreads();
        const uint32_t kbase = sb + 16384 + (kb & 1) * 16384;

        // ---- S = Q K^T (1-pass fp16) ----
        float S[2][8][4];
#pragma unroll
        for (int t = 0; t < 2; t++)
#pragma unroll
            for (int nf = 0; nf < 8; nf++)
#pragma unroll
                for (int q = 0; q < 4; q++) S[t][nf][q] = 0.f;

#pragma unroll
        for (int kf = 0; kf < 4; kf++) {
            uint32_t aq[2][4];
#pragma unroll
            for (int t = 0; t < 2; t++)
                ldm4(sb + swz((wid * 32 + t * 16 + arow) * 128 + (kf * 16 + acol) * 2), aq[t]);
#pragma unroll
            for (int n2 = 0; n2 < 4; n2++) {
                uint32_t kh4[4];
                ldm4(kbase + swz((n2 * 16 + b4row) * 128 + (kf * 16 + b4col) * 2), kh4);
#pragma unroll
                for (int t = 0; t < 2; t++) {
                    mma_fp(S[t][n2*2],   aq[t], kh4);
                    mma_fp(S[t][n2*2+1], aq[t], kh4 + 2);
                }
            }
        }

        // ---- scale (+ mask if tile nonzero), log2 domain ----
        if (flagp[kb]) {
#pragma unroll
            for (int t = 0; t < 2; t++)
#pragma unroll
                for (int nf = 0; nf < 8; nf++) {
                    float2 u = *(const float2*)&mrp[t*2    ][kb * 64 + nf * 8 + tig * 2];
                    float2 w = *(const float2*)&mrp[t*2 + 1][kb * 64 + nf * 8 + tig * 2];
                    S[t][nf][0] = fmaf(S[t][nf][0], SCL2E, u.x * L2E);
                    S[t][nf][1] = fmaf(S[t][nf][1], SCL2E, u.y * L2E);
                    S[t][nf][2] = fmaf(S[t][nf][2], SCL2E, w.x * L2E);
                    S[t][nf][3] = fmaf(S[t][nf][3], SCL2E, w.y * L2E);
                }
        } else {
#pragma unroll
            for (int t = 0; t < 2; t++)
#pragma unroll
                for (int nf = 0; nf < 8; nf++)
#pragma unroll
                    for (int q = 0; q < 4; q++) S[t][nf][q] *= SCL2E;
        }

        // ---- online softmax per row-set j ----
        float al[4];
#pragma unroll
        for (int j = 0; j < 4; j++) {
            const int t = j >> 1, half = j & 1;
            float rm = -1e30f;
#pragma unroll
            for (int nf = 0; nf < 8; nf++)
                rm = fmaxf(rm, fmaxf(S[t][nf][half*2], S[t][nf][half*2+1]));
            rm = fmaxf(rm, __shfl_xor_sync(0xffffffffu, rm, 1));
            rm = fmaxf(rm, __shfl_xor_sync(0xffffffffu, rm, 2));
            const float mn = fmaxf(mrun[j], rm);
            al[j] = ex2(mrun[j] - mn);
            mrun[j] = mn;
            float rs = 0.f;
#pragma unroll
            for (int nf = 0; nf < 8; nf++) {
                const float p0 = ex2(S[t][nf][half*2]   - mn);
                const float p1 = ex2(S[t][nf][half*2+1] - mn);
                S[t][nf][half*2]   = p0;
                S[t][nf][half*2+1] = p1;
                rs += p0 + p1;
            }
            rs += __shfl_xor_sync(0xffffffffu, rs, 1);
            rs += __shfl_xor_sync(0xffffffffu, rs, 2);
            lrun[j] = lrun[j] * al[j] + rs;
        }
#pragma unroll
        for (int t = 0; t < 2; t++)
#pragma unroll
            for (int nf = 0; nf < 8; nf++) {
                O[t][nf][0] *= al[t*2];   O[t][nf][1] *= al[t*2];
                O[t][nf][2] *= al[t*2+1]; O[t][nf][3] *= al[t*2+1];
            }

        // ---- O += Ph Vh (1-pass) ----
#pragma unroll
        for (int kc = 0; kc < 4; kc++) {
            uint32_t phi[2][4];
#pragma unroll
            for (int t = 0; t < 2; t++) {
#pragma unroll
                for (int hf = 0; hf < 2; hf++) {
                    const int nf = kc * 2 + hf;
                    phi[t][hf*2+0] = pack_hf(__float2half_rn(S[t][nf][0]),
                                             __float2half_rn(S[t][nf][1]));
                    phi[t][hf*2+1] = pack_hf(__float2half_rn(S[t][nf][2]),
                                             __float2half_rn(S[t][nf][3]));
                }
            }
#pragma unroll
            for (int n2 = 0; n2 < 4; n2++) {
                uint32_t vh4[4];
                const uint32_t off = swz((n2 * 16 + b4row) * 128 + (kc * 16 + b4col) * 2);
                ldm4(kbase + 8192 + off, vh4);
#pragma unroll
                for (int t = 0; t < 2; t++) {
                    mma_fp(O[t][n2*2],   phi[t], vh4);
                    mma_fp(O[t][n2*2+1], phi[t], vh4 + 2);
                }
            }
        }

        __syncthreads();
        if (kb + 2 < 32) load_kv(kb + 2, kb & 1);
    }

    // ---- epilogue: write normalized O as [Ah|Al] split rows of g_A2buf ----
#pragma unroll
    for (int j = 0; j < 4; j++) {
        const int t = j >> 1, half = j & 1;
        const int row = qrowbase + t * 16 + half * 8 + grp;
        const float inv = 1.f / lrun[j];
        __half* op = g_A2buf + ((size_t)b * SEQ + row) * KTOT;
#pragma unroll
        for (int nf = 0; nf < 8; nf++) {
            const int col = h * 64 + nf * 8 + tig * 2;
            const float x = O[t][nf][half*2] * inv, y = O[t][nf][half*2+1] * inv;
            __half hx = __float2half_rn(x), hy = __float2half_rn(y);
            *(uint32_t*)&op[col]          = pack_hf(hx, hy);
            *(uint32_t*)&op[DMODEL + col] = pack_hf(__float2half_rn(x - __half2float(hx)),
                                                    __float2half_rn(y - __half2float(hy)));
        }
    }
}

// ---------------------------------------------------------------------------
extern "C" void kernel_launch(void* const* d_in, const int* in_sizes, int n_in,
                              void* d_out, int out_size)
{
    const float* hidden = (const float*)d_in[0];
    const float* mask   = (const float*)d_in[1];
    const float* w_qkv  = (const float*)d_in[2];
    const float* w_out  = (const float*)d_in[3];
    const float* b_out  = (const float*)d_in[4];
    float* out = (float*)d_out;

    cudaFuncSetAttribute(qkv_gemm_kernel,
                         cudaFuncAttributeMaxDynamicSharedMemorySize, SMQ_TOTAL);
    cudaFuncSetAttribute(out_gemm_kernel,
                         cudaFuncAttributeMaxDynamicSharedMemorySize, SM_TOTAL);
    cudaFuncSetAttribute(flash_mma_kernel,
                         cudaFuncAttributeMaxDynamicSharedMemorySize, FSM_TOTAL);

    __half *abuf, *wt, *w2t, *a2buf;
    cudaGetSymbolAddress((void**)&abuf, g_Abuf);
    cudaGetSymbolAddress((void**)&wt, g_Wt);
    cudaGetSymbolAddress((void**)&w2t, g_W2t);
    cudaGetSymbolAddress((void**)&a2buf, g_A2buf);

    // 1. conversions + mask tile flags
    mask_flag_kernel<<<BATCH * 32 * 32, 128>>>(mask);
    split_rows_kernel<<<MTOT, 320>>>(hidden, abuf);
    split_w_kernel<<<(3840 * 320 + 255) / 256, 256>>>(w_qkv, wt, 3840);
    split_w_kernel<<<(1280 * 320 + 255) / 256, 256>>>(w_out, w2t, 1280);

    // 2. QKV projection (fp16 2-pass, 128x256 tiles) -> fp16 q/k/v
    qkv_gemm_kernel<<<dim3(3840 / 256, MTOT / 128), 256, SMQ_TOTAL>>>(abuf, wt);

    // 3. fp16 tensor-core flash attention (QK 1-pass, PV 1-pass)
    flash_mma_kernel<<<dim3(SEQ / 128, NH, BATCH), 128, FSM_TOTAL>>>(mask);

    // 4. out-projection (fp16 2-pass, 128x128 tiles)
    out_gemm_kernel<<<dim3(1280 / 128, MTOT / 128), 256, SM_TOTAL>>>(
        a2buf, w2t, b_out, out);
}

// round 13
// speedup vs baseline: 5.4445x; 1.0773x over previous
#include <cuda_runtime.h>
#include <cuda_bf16.h>
#include <cuda_fp16.h>
#include <cstdint>

#define NH 20
#define DH 64
#define DMODEL 1280
#define BATCH 2
#define SEQ 2048
#define MTOT (BATCH*SEQ)      /* 4096 */
#define KTOT 2560             /* 2 * 1280 fp16 split-K concat (QKV A side) */
#define NST 40                /* 2560 / 64 */
#define NSTO 20               /* out-proj: 1280 / 64 */

// ---------------------------------------------------------------------------
// Device-global scratch (allocation-free rule)
// ---------------------------------------------------------------------------
__device__ __half g_qh[BATCH*NH*SEQ*DH];         // [bh][s][dd] fp16
__device__ __half g_kh[BATCH*NH*SEQ*DH];         // [bh][s][dd] fp16
__device__ __half g_vh[BATCH*NH*DH*SEQ];         // d-major [bh][dd][s] fp16
__device__ __half g_Abuf[(size_t)MTOT*KTOT];     // [Xh | Xl]
__device__ __half g_Wt[(size_t)3840*DMODEL];     // [n][Wh] (read twice by GEMM)
__device__ __half g_W2t[(size_t)1280*DMODEL];
__device__ __half g_A2buf[(size_t)MTOT*DMODEL];  // attn rows, plain fp16
__device__ unsigned char g_mflag[BATCH*32*32];   // mask 64x64 tile nonzero flags

// ---------------------------------------------------------------------------
// Baseline-PTX helpers
// ---------------------------------------------------------------------------
__device__ __forceinline__ uint32_t smem_u32(const void* p) {
    uint32_t a;
    asm("{ .reg .u64 t; cvta.to.shared.u64 t, %1; cvt.u32.u64 %0, t; }"
        : "=r"(a) : "l"(p));
    return a;
}
__device__ __forceinline__ uint32_t swz(uint32_t off) {  // SW128 byte swizzle
    return off ^ ((off >> 3) & 0x70);
}
__device__ __forceinline__ float ex2(float x) {
    float y;
    asm("ex2.approx.ftz.f32 %0, %1;" : "=f"(y) : "f"(x));
    return y;
}
// pack two f32 -> half2 (lo, hi), then exp2 in fp16x2 (one MUFU op per pair)
__device__ __forceinline__ uint32_t cvt_h2(float lo, float hi) {
    __half2 t = __float22half2_rn(make_float2(lo, hi));
    return *reinterpret_cast<uint32_t*>(&t);
}
__device__ __forceinline__ uint32_t ex2h2(uint32_t x) {
    __half2 v = *reinterpret_cast<__half2*>(&x);
    __half2 r = h2exp2(v);
    return *reinterpret_cast<uint32_t*>(&r);
}

#define CP_ASYNC16(dst, src) \
    asm volatile("cp.async.cg.shared.global [%0], [%1], 16;" :: "r"(dst), "l"(src))
#define CP_COMMIT() asm volatile("cp.async.commit_group;" ::: "memory")
#define CP_WAIT1()  asm volatile("cp.async.wait_group 1;" ::: "memory")
#define CP_WAIT0()  asm volatile("cp.async.wait_group 0;" ::: "memory")

__device__ __forceinline__ void ldm4(uint32_t addr, uint32_t* r) {
    asm volatile("ldmatrix.sync.aligned.m8n8.x4.shared.b16 {%0,%1,%2,%3}, [%4];"
                 : "=r"(r[0]), "=r"(r[1]), "=r"(r[2]), "=r"(r[3]) : "r"(addr));
}
__device__ __forceinline__ void mma_fp(float* c, const uint32_t* a, const uint32_t* b) {
    asm volatile("mma.sync.aligned.m16n8k16.row.col.f32.f16.f16.f32 "
                 "{%0,%1,%2,%3}, {%4,%5,%6,%7}, {%8,%9}, {%0,%1,%2,%3};"
                 : "+f"(c[0]), "+f"(c[1]), "+f"(c[2]), "+f"(c[3])
                 : "r"(a[0]), "r"(a[1]), "r"(a[2]), "r"(a[3]),
                   "r"(b[0]), "r"(b[1]));
}

__device__ __forceinline__ uint32_t pack_hf(__half x, __half y) {
    __half2 t = __halves2half2(x, y);
    return *reinterpret_cast<uint32_t*>(&t);
}

// ---------------------------------------------------------------------------
// Mask tile flags: 1 if any nonzero in the (b, qt, kt) 64x64 tile.
// ---------------------------------------------------------------------------
__global__ __launch_bounds__(128) void mask_flag_kernel(const float* __restrict__ Mask)
{
    const int blk = blockIdx.x;                 // b*1024 + qt*32 + kt
    const int b = blk >> 10, qt = (blk >> 5) & 31, kt = blk & 31;
    const float* p = Mask + ((size_t)b * SEQ + qt * 64) * SEQ + kt * 64;
    const int tid = threadIdx.x;
    bool nz = false;
#pragma unroll
    for (int i = 0; i < 8; i++) {
        const int t = tid + i * 128;
        const int r = t >> 4, c = (t & 15) * 4;
        float4 v = *(const float4*)&p[(size_t)r * SEQ + c];
        nz |= (v.x != 0.f) | (v.y != 0.f) | (v.z != 0.f) | (v.w != 0.f);
    }
    const int any = __syncthreads_or((int)nz);
    if (tid == 0) g_mflag[blk] = (unsigned char)(any != 0);
}

// ---------------------------------------------------------------------------
// Split conversions (fp32 -> fp16)
// ---------------------------------------------------------------------------
union HfPack { __half h[4]; uint2 u; };

// src [rows][1280] fp32 -> dst [rows][2560] fp16 sections [hi | lo]
__global__ __launch_bounds__(320) void split_rows_kernel(
    const float* __restrict__ src, __half* __restrict__ dst)
{
    const int m = blockIdx.x;
    const int k4 = threadIdx.x * 4;
    float4 v = *(const float4*)&src[(size_t)m * DMODEL + k4];
    HfPack hi, lo;
    float f[4] = {v.x, v.y, v.z, v.w};
#pragma unroll
    for (int i = 0; i < 4; i++) {
        hi.h[i] = __float2half_rn(f[i]);
        lo.h[i] = __float2half_rn(f[i] - __half2float(hi.h[i]));
    }
    __half* row = dst + (size_t)m * KTOT;
    *(uint2*)&row[k4]          = hi.u;
    *(uint2*)&row[DMODEL + k4] = lo.u;
}

// src W [K=1280][N] fp32 -> dst [N][1280] fp16 (hi only, transposed)
__global__ __launch_bounds__(256) void split_w_kernel(
    const float* __restrict__ src, __half* __restrict__ dst, int N)
{
    const int idx = blockIdx.x * 256 + threadIdx.x;
    const int n = idx % N;
    const int k4i = idx / N;
    if (k4i >= DMODEL / 4) return;
    const int k = k4i * 4;
    HfPack hi;
#pragma unroll
    for (int i = 0; i < 4; i++)
        hi.h[i] = __float2half_rn(src[(size_t)(k + i) * N + n]);
    *(uint2*)&dst[(size_t)n * DMODEL + k] = hi.u;
}

// B-section column offset for stage s: K' index wraps at 1280.
__device__ __forceinline__ int bcol_of(int s) { return (s >= 20 ? s - 20 : s) * 64; }

// ---------------------------------------------------------------------------
// QKV GEMM (big tiles): CTA 128x256, 8 warps of 64x64, 3-stage ring (144KB).
// A [4096][2560] = [Xh|Xl]; B [3840][1280] read twice (K' wrap).
// Epilogue scatters fp16 q/k (row-major) and v (d-major).
// ---------------------------------------------------------------------------
#define BSTAGE 49152          /* A 16KB + B 32KB */
#define SMQ_TOTAL (3*BSTAGE)

__global__ __launch_bounds__(256, 1) void qkv_gemm_kernel(
    const __half* __restrict__ A,
    const __half* __restrict__ Bt)
{
    extern __shared__ __align__(1024) char smem[];
    const uint32_t sb = smem_u32(smem);
    const int tid = threadIdx.x;
    const int lane = tid & 31, wid = tid >> 5;
    const int wm = wid >> 2, wn = wid & 3;      // warp grid 2 x 4 (64 x 64 tiles)
    const int m0 = blockIdx.y * 128, n0 = blockIdx.x * 256;

    auto load_stage = [&](int s, int buf) {
        const uint32_t base = sb + buf * BSTAGE;
        const __half* ap = A  + (size_t)m0 * KTOT + s * 64;
        const __half* bp = Bt + (size_t)n0 * DMODEL + bcol_of(s);
#pragma unroll
        for (int i = 0; i < 4; i++) {           // A: 128 rows x 8 chunks
            const int t = tid + i * 256;
            const int r = t >> 3, c = t & 7;
            CP_ASYNC16(base + swz(r * 128 + c * 16), ap + (size_t)r * KTOT + c * 8);
        }
#pragma unroll
        for (int i = 0; i < 8; i++) {           // B: 256 rows x 8 chunks
            const int t = tid + i * 256;
            const int r = t >> 3, c = t & 7;
            CP_ASYNC16(base + 16384 + swz(r * 128 + c * 16), bp + (size_t)r * DMODEL + c * 8);
        }
        CP_COMMIT();
    };

    float acc[4][8][4];
#pragma unroll
    for (int mi = 0; mi < 4; mi++)
#pragma unroll
        for (int ni = 0; ni < 8; ni++)
#pragma unroll
            for (int q = 0; q < 4; q++) acc[mi][ni][q] = 0.f;

    load_stage(0, 0);
    load_stage(1, 1);

    const int arow = lane & 15;
    const int acol = (lane >> 4) * 8;
    const int b4row = ((lane >> 4) & 1) * 8 + (lane & 7);
    const int b4col = ((lane >> 3) & 1) * 8;

#pragma unroll 1
    for (int s = 0; s < NST; s++) {
        if (s + 1 < NST) { CP_WAIT1(); } else { CP_WAIT0(); }
        __syncthreads();
        if (s + 2 < NST) load_stage(s + 2, (s + 2) % 3);

        const uint32_t abase = sb + (s % 3) * BSTAGE;
        const uint32_t bbase = abase + 16384;
#pragma unroll
        for (int kf = 0; kf < 4; kf++) {
            uint32_t a[4][4], b[4][4];
#pragma unroll
            for (int mi = 0; mi < 4; mi++)
                ldm4(abase + swz((wm*64 + mi*16 + arow) * 128 + (kf*16 + acol) * 2), a[mi]);
#pragma unroll
            for (int n2 = 0; n2 < 4; n2++)
                ldm4(bbase + swz((wn*64 + n2*16 + b4row) * 128 + (kf*16 + b4col) * 2), b[n2]);
#pragma unroll
            for (int mi = 0; mi < 4; mi++)
#pragma unroll
                for (int n2 = 0; n2 < 4; n2++) {
                    mma_fp(acc[mi][n2*2],   a[mi], b[n2]);
                    mma_fp(acc[mi][n2*2+1], a[mi], b[n2] + 2);
                }
        }
    }

    // ---- epilogue: scatter into q/k (row-major fp16) and v (d-major fp16) ----
    const int grp = lane >> 2, tig = lane & 3;
    const int sec = n0 / DMODEL;   // 1280 % 256 == 0 -> tile inside one section
#pragma unroll
    for (int mi = 0; mi < 4; mi++) {
#pragma unroll
        for (int half = 0; half < 2; half++) {
            const int r = wm * 64 + mi * 16 + grp + half * 8;
            const int m = m0 + r;
            const int bb = m >> 11, sq = m & 2047;
#pragma unroll
            for (int ni = 0; ni < 8; ni++) {
                const float v0 = acc[mi][ni][half * 2];
                const float v1 = acc[mi][ni][half * 2 + 1];
                const int nglob = n0 + wn * 64 + ni * 8 + tig * 2;
                const int rem = nglob - sec * DMODEL;
                const int hh = rem >> 6, dd = rem & 63;
                const int bh = bb * NH + hh;
                if (sec == 2) {
                    g_vh[((size_t)bh * DH + dd) * SEQ + sq]     = __float2half_rn(v0);
                    g_vh[((size_t)bh * DH + dd + 1) * SEQ + sq] = __float2half_rn(v1);
                } else {
                    const size_t a = ((size_t)bh * SEQ + sq) * DH + dd;
                    const uint32_t hv = pack_hf(__float2half_rn(v0), __float2half_rn(v1));
                    if (sec == 0) *(uint32_t*)&g_qh[a] = hv;
                    else          *(uint32_t*)&g_kh[a] = hv;
                }
            }
        }
    }
}

// ---------------------------------------------------------------------------
// Out-projection GEMM (128x128, 8 warps of 64x32): out = A*B^T + bias
// A [4096][1280] fp16 (1-pass); B [1280][1280].
// ---------------------------------------------------------------------------
#define STAGE_BYTES 32768
#define SM_TOTAL (3*STAGE_BYTES)

__global__ __launch_bounds__(256) void out_gemm_kernel(
    const __half* __restrict__ A,
    const __half* __restrict__ Bt,
    const float* __restrict__ bias, float* __restrict__ Cout)
{
    extern __shared__ __align__(1024) char smem[];
    const uint32_t sb = smem_u32(smem);
    const int tid = threadIdx.x;
    const int lane = tid & 31, wid = tid >> 5;
    const int wm = wid >> 2, wn = wid & 3;
    const int m0 = blockIdx.y * 128, n0 = blockIdx.x * 128;

    auto load_stage = [&](int s, int buf) {
        const uint32_t base = sb + buf * STAGE_BYTES;
        const __half* ap = A  + (size_t)m0 * DMODEL + s * 64;
        const __half* bp = Bt + (size_t)n0 * DMODEL + s * 64;
#pragma unroll
        for (int i = 0; i < 4; i++) {
            const int t = tid + i * 256;
            const int r = t >> 3, c = t & 7;
            CP_ASYNC16(base + swz(r * 128 + c * 16), ap + (size_t)r * DMODEL + c * 8);
        }
#pragma unroll
        for (int i = 0; i < 4; i++) {
            const int t = tid + i * 256;
            const int r = t >> 3, c = t & 7;
            CP_ASYNC16(base + 16384 + swz(r * 128 + c * 16), bp + (size_t)r * DMODEL + c * 8);
        }
        CP_COMMIT();
    };

    float acc[4][4][4];
#pragma unroll
    for (int mi = 0; mi < 4; mi++)
#pragma unroll
        for (int ni = 0; ni < 4; ni++)
#pragma unroll
            for (int q = 0; q < 4; q++) acc[mi][ni][q] = 0.f;

    load_stage(0, 0);
    load_stage(1, 1);

    const int arow = lane & 15;
    const int acol = (lane >> 4) * 8;
    const int b4row = ((lane >> 4) & 1) * 8 + (lane & 7);
    const int b4col = ((lane >> 3) & 1) * 8;

#pragma unroll 1
    for (int s = 0; s < NSTO; s++) {
        if (s + 1 < NSTO) { CP_WAIT1(); } else { CP_WAIT0(); }
        __syncthreads();
        if (s + 2 < NSTO) load_stage(s + 2, (s + 2) % 3);

        const uint32_t abase = sb + (s % 3) * STAGE_BYTES;
        const uint32_t bbase = abase + 16384;
#pragma unroll
        for (int kf = 0; kf < 4; kf++) {
            uint32_t a[4][4], b2[2][4];
#pragma unroll
            for (int mi = 0; mi < 4; mi++)
                ldm4(abase + swz((wm*64 + mi*16 + arow) * 128 + (kf*16 + acol) * 2), a[mi]);
#pragma unroll
            for (int n2 = 0; n2 < 2; n2++)
                ldm4(bbase + swz((wn*32 + n2*16 + b4row) * 128 + (kf*16 + b4col) * 2), b2[n2]);
#pragma unroll
            for (int mi = 0; mi < 4; mi++)
#pragma unroll
                for (int n2 = 0; n2 < 2; n2++) {
                    mma_fp(acc[mi][n2*2],   a[mi], b2[n2]);
                    mma_fp(acc[mi][n2*2+1], a[mi], b2[n2] + 2);
                }
        }
    }

    const int grp = lane >> 2, tig = lane & 3;
#pragma unroll
    for (int mi = 0; mi < 4; mi++) {
#pragma unroll
        for (int half = 0; half < 2; half++) {
            const int m = m0 + wm * 64 + mi * 16 + grp + half * 8;
#pragma unroll
            for (int ni = 0; ni < 4; ni++) {
                const int nglob = n0 + wn * 32 + ni * 8 + tig * 2;
                float2 bv = *(const float2*)&bias[nglob];
                *(float2*)&Cout[(size_t)m * DMODEL + nglob] =
                    make_float2(acc[mi][ni][half*2] + bv.x, acc[mi][ni][half*2+1] + bv.y);
            }
        }
    }
}

// ---------------------------------------------------------------------------
// fp16 tensor-core flash attention.
// CTA: 128 queries x one (b,h); 4 warps, each M=32, N=64 keys.
// QK^T 1-pass; softmax via h2exp2 producing packed fp16 P fragments;
// row-sum l via an extra ones-column mma; PV 1-pass.
// smem: Qh 16KB | 2 stages x {Kh,Vh each 8KB} = 48KB -> 3 CTAs/SM.
// ---------------------------------------------------------------------------
#define FSM_TOTAL 49152

__global__ __launch_bounds__(128, 3) void flash_mma_kernel(const float* __restrict__ Mask)
{
    extern __shared__ __align__(1024) char fsm[];
    const uint32_t sb = smem_u32(fsm);
    const int tid = threadIdx.x, lane = tid & 31, wid = tid >> 5;
    const int grp = lane >> 2, tig = lane & 3;
    const int qb = blockIdx.x, h = blockIdx.y, b = blockIdx.z;
    const int bh = b * NH + h;

    const __half* qhp = g_qh + ((size_t)bh * SEQ + qb * 128) * DH;
    const __half* khp = g_kh + (size_t)bh * SEQ * DH;
    const __half* vhp = g_vh + (size_t)bh * DH * SEQ;

#pragma unroll
    for (int i = 0; i < 8; i++) {
        const int t = tid + i * 128;
        const int r = t >> 3, c = t & 7;
        CP_ASYNC16(sb + swz(r * 128 + c * 16), qhp + (size_t)r * DH + c * 8);
    }

    auto load_kv = [&](int kb, int buf) {
        const uint32_t base = sb + 16384 + buf * 16384;
#pragma unroll
        for (int i = 0; i < 4; i++) {
            const int t = tid + i * 128;
            const int r = t >> 3, c = t & 7;
            const uint32_t d = swz(r * 128 + c * 16);
            CP_ASYNC16(base + d,        khp + (size_t)(kb * 64 + r) * DH + c * 8);
            CP_ASYNC16(base + 8192 + d, vhp + (size_t)r * SEQ + kb * 64 + c * 8);
        }
        CP_COMMIT();
    };
    load_kv(0, 0);
    load_kv(1, 1);

    float O[2][8][4];
    float lacc[2][4];
#pragma unroll
    for (int t = 0; t < 2; t++) {
#pragma unroll
        for (int nf = 0; nf < 8; nf++)
#pragma unroll
            for (int q = 0; q < 4; q++) O[t][nf][q] = 0.f;
#pragma unroll
        for (int q = 0; q < 4; q++) lacc[t][q] = 0.f;
    }
    float mrun[4] = {-1e30f, -1e30f, -1e30f, -1e30f};

    const int qrowbase = qb * 128 + wid * 32;
    const float* mrp[4];
#pragma unroll
    for (int j = 0; j < 4; j++) {
        const int t = j >> 1, half = j & 1;
        mrp[j] = Mask + ((size_t)b * SEQ + qrowbase + t * 16 + half * 8 + grp) * SEQ;
    }
    const unsigned char* flagp = g_mflag + (size_t)b * 1024 + (qb * 2 + (wid >> 1)) * 32;

    const int arow = lane & 15;
    const int acol = (lane >> 4) * 8;
    const int b4row = ((lane >> 4) & 1) * 8 + (lane & 7);
    const int b4col = ((lane >> 3) & 1) * 8;

    const float SCL2E = 0.125f * 1.44269504f;
    const float L2E = 1.44269504f;
    const uint32_t ONES2 = 0x3C003C00u;          // half2(1,1)
    const uint32_t onesb[2] = {ONES2, ONES2};

#pragma unroll 1
    for (int kb = 0; kb < 32; kb++) {
        if (kb < 31) { CP_WAIT1(); } else { CP_WAIT0(); }
        __syncthreads();
        const uint32_t kbase = sb + 16384 + (kb & 1) * 16384;

        // ---- S = Q K^T (1-pass fp16) ----
        float S[2][8][4];
#pragma unroll
        for (int t = 0; t < 2; t++)
#pragma unroll
            for (int nf = 0; nf < 8; nf++)
#pragma unroll
                for (int q = 0; q < 4; q++) S[t][nf][q] = 0.f;

#pragma unroll
        for (int kf = 0; kf < 4; kf++) {
            uint32_t aq[2][4];
#pragma unroll
            for (int t = 0; t < 2; t++)
                ldm4(sb + swz((wid * 32 + t * 16 + arow) * 128 + (kf * 16 + acol) * 2), aq[t]);
#pragma unroll
            for (int n2 = 0; n2 < 4; n2++) {
                uint32_t kh4[4];
                ldm4(kbase + swz((n2 * 16 + b4row) * 128 + (kf * 16 + b4col) * 2), kh4);
#pragma unroll
                for (int t = 0; t < 2; t++) {
                    mma_fp(S[t][n2*2],   aq[t], kh4);
                    mma_fp(S[t][n2*2+1], aq[t], kh4 + 2);
                }
            }
        }

        // ---- scale (+ mask if tile nonzero), log2 domain ----
        if (flagp[kb]) {
#pragma unroll
            for (int t = 0; t < 2; t++)
#pragma unroll
                for (int nf = 0; nf < 8; nf++) {
                    float2 u = *(const float2*)&mrp[t*2    ][kb * 64 + nf * 8 + tig * 2];
                    float2 w = *(const float2*)&mrp[t*2 + 1][kb * 64 + nf * 8 + tig * 2];
                    S[t][nf][0] = fmaf(S[t][nf][0], SCL2E, u.x * L2E);
                    S[t][nf][1] = fmaf(S[t][nf][1], SCL2E, u.y * L2E);
                    S[t][nf][2] = fmaf(S[t][nf][2], SCL2E, w.x * L2E);
                    S[t][nf][3] = fmaf(S[t][nf][3], SCL2E, w.y * L2E);
                }
        } else {
#pragma unroll
            for (int t = 0; t < 2; t++)
#pragma unroll
                for (int nf = 0; nf < 8; nf++)
#pragma unroll
                    for (int q = 0; q < 4; q++) S[t][nf][q] *= SCL2E;
        }

        // ---- running max per row-set j ----
        float al[4], mnv[4];
#pragma unroll
        for (int j = 0; j < 4; j++) {
            const int t = j >> 1, half = j & 1;
            float rm = -1e30f;
#pragma unroll
            for (int nf = 0; nf < 8; nf++)
                rm = fmaxf(rm, fmaxf(S[t][nf][half*2], S[t][nf][half*2+1]));
            rm = fmaxf(rm, __shfl_xor_sync(0xffffffffu, rm, 1));
            rm = fmaxf(rm, __shfl_xor_sync(0xffffffffu, rm, 2));
            const float mn = fmaxf(mrun[j], rm);
            al[j] = ex2(mrun[j] - mn);
            mrun[j] = mn;
            mnv[j] = mn;
        }

        // ---- P = exp2(S - m) in fp16, directly packed as mma A-fragments ----
        uint32_t Pp[2][8][2];
#pragma unroll
        for (int t = 0; t < 2; t++)
#pragma unroll
            for (int nf = 0; nf < 8; nf++) {
                Pp[t][nf][0] = ex2h2(cvt_h2(S[t][nf][0] - mnv[t*2],
                                            S[t][nf][1] - mnv[t*2]));
                Pp[t][nf][1] = ex2h2(cvt_h2(S[t][nf][2] - mnv[t*2+1],
                                            S[t][nf][3] - mnv[t*2+1]));
            }

        // ---- rescale O and l ----
#pragma unroll
        for (int t = 0; t < 2; t++) {
#pragma unroll
            for (int nf = 0; nf < 8; nf++) {
                O[t][nf][0] *= al[t*2];   O[t][nf][1] *= al[t*2];
                O[t][nf][2] *= al[t*2+1]; O[t][nf][3] *= al[t*2+1];
            }
            lacc[t][0] *= al[t*2];   lacc[t][1] *= al[t*2];
            lacc[t][2] *= al[t*2+1]; lacc[t][3] *= al[t*2+1];
        }

        // ---- O += P Vh ; l += P * ones ----
#pragma unroll
        for (int kc = 0; kc < 4; kc++) {
            uint32_t phi[2][4];
#pragma unroll
            for (int t = 0; t < 2; t++) {
                phi[t][0] = Pp[t][kc*2][0];
                phi[t][1] = Pp[t][kc*2][1];
                phi[t][2] = Pp[t][kc*2+1][0];
                phi[t][3] = Pp[t][kc*2+1][1];
                mma_fp(lacc[t], phi[t], onesb);
            }
#pragma unroll
            for (int n2 = 0; n2 < 4; n2++) {
                uint32_t vh4[4];
                const uint32_t off = swz((n2 * 16 + b4row) * 128 + (kc * 16 + b4col) * 2);
                ldm4(kbase + 8192 + off, vh4);
#pragma unroll
                for (int t = 0; t < 2; t++) {
                    mma_fp(O[t][n2*2],   phi[t], vh4);
                    mma_fp(O[t][n2*2+1], phi[t], vh4 + 2);
                }
            }
        }

        __syncthreads();
        if (kb + 2 < 32) load_kv(kb + 2, kb & 1);
    }

    // ---- epilogue: write normalized O as plain fp16 rows of g_A2buf ----
#pragma unroll
    for (int j = 0; j < 4; j++) {
        const int t = j >> 1, half = j & 1;
        const int row = qrowbase + t * 16 + half * 8 + grp;
        const float inv = 1.f / lacc[t][half * 2];
        __half* op = g_A2buf + ((size_t)b * SEQ + row) * DMODEL;
#pragma unroll
        for (int nf = 0; nf < 8; nf++) {
            const int col = h * 64 + nf * 8 + tig * 2;
            *(uint32_t*)&op[col] = pack_hf(__float2half_rn(O[t][nf][half*2] * inv),
                                           __float2half_rn(O[t][nf][half*2+1] * inv));
        }
    }
}

// ---------------------------------------------------------------------------
extern "C" void kernel_launch(void* const* d_in, const int* in_sizes, int n_in,
                              void* d_out, int out_size)
{
    const float* hidden = (const float*)d_in[0];
    const float* mask   = (const float*)d_in[1];
    const float* w_qkv  = (const float*)d_in[2];
    const float* w_out  = (const float*)d_in[3];
    const float* b_out  = (const float*)d_in[4];
    float* out = (float*)d_out;

    cudaFuncSetAttribute(qkv_gemm_kernel,
                         cudaFuncAttributeMaxDynamicSharedMemorySize, SMQ_TOTAL);
    cudaFuncSetAttribute(out_gemm_kernel,
                         cudaFuncAttributeMaxDynamicSharedMemorySize, SM_TOTAL);
    cudaFuncSetAttribute(flash_mma_kernel,
                         cudaFuncAttributeMaxDynamicSharedMemorySize, FSM_TOTAL);

    __half *abuf, *wt, *w2t, *a2buf;
    cudaGetSymbolAddress((void**)&abuf, g_Abuf);
    cudaGetSymbolAddress((void**)&wt, g_Wt);
    cudaGetSymbolAddress((void**)&w2t, g_W2t);
    cudaGetSymbolAddress((void**)&a2buf, g_A2buf);

    // 1. conversions + mask tile flags
    mask_flag_kernel<<<BATCH * 32 * 32, 128>>>(mask);
    split_rows_kernel<<<MTOT, 320>>>(hidden, abuf);
    split_w_kernel<<<(3840 * 320 + 255) / 256, 256>>>(w_qkv, wt, 3840);
    split_w_kernel<<<(1280 * 320 + 255) / 256, 256>>>(w_out, w2t, 1280);

    // 2. QKV projection (fp16 2-pass, 128x256 tiles) -> fp16 q/k/v
    qkv_gemm_kernel<<<dim3(3840 / 256, MTOT / 128), 256, SMQ_TOTAL>>>(abuf, wt);

    // 3. fp16 tensor-core flash attention (fp16 softmax, ones-mma row sums)
    flash_mma_kernel<<<dim3(SEQ / 128, NH, BATCH), 128, FSM_TOTAL>>>(mask);

    // 4. out-projection (fp16 1-pass, 128x128 tiles)
    out_gemm_kernel<<<dim3(1280 / 128, MTOT / 128), 256, SM_TOTAL>>>(
        a2buf, w2t, b_out, out);
}

// round 15
// speedup vs baseline: 7.1341x; 1.3103x over previous
#include <cuda_runtime.h>
#include <cuda_bf16.h>
#include <cuda_fp16.h>
#include <cstdint>

#define NH 20
#define DH 64
#define DMODEL 1280
#define BATCH 2
#define SEQ 2048
#define MTOT (BATCH*SEQ)      /* 4096 */
#define NST1 20               /* 1280 / 64 : 1-pass GEMM stages */

// ---------------------------------------------------------------------------
// Device-global scratch (allocation-free rule)
// ---------------------------------------------------------------------------
__device__ __half g_qh[BATCH*NH*SEQ*DH];         // [bh][s][dd] fp16
__device__ __half g_kh[BATCH*NH*SEQ*DH];         // [bh][s][dd] fp16
__device__ __half g_vh[BATCH*NH*DH*SEQ];         // d-major [bh][dd][s] fp16
__device__ __half g_Abuf[(size_t)MTOT*DMODEL];   // X as fp16
__device__ __half g_Wt[(size_t)3840*DMODEL];     // [n][Wh]
__device__ __half g_W2t[(size_t)1280*DMODEL];
__device__ __half g_A2buf[(size_t)MTOT*DMODEL];  // attn rows, plain fp16
__device__ unsigned char g_mflag[BATCH*32*32];   // mask 64x64 tile nonzero flags

// ---------------------------------------------------------------------------
// Baseline-PTX helpers
// ---------------------------------------------------------------------------
__device__ __forceinline__ uint32_t smem_u32(const void* p) {
    uint32_t a;
    asm("{ .reg .u64 t; cvta.to.shared.u64 t, %1; cvt.u32.u64 %0, t; }"
        : "=r"(a) : "l"(p));
    return a;
}
__device__ __forceinline__ uint32_t swz(uint32_t off) {  // SW128 byte swizzle
    return off ^ ((off >> 3) & 0x70);
}
__device__ __forceinline__ float ex2(float x) {
    float y;
    asm("ex2.approx.ftz.f32 %0, %1;" : "=f"(y) : "f"(x));
    return y;
}
// pack two f32 -> half2 (lo, hi), then exp2 in fp16x2
__device__ __forceinline__ uint32_t cvt_h2(float lo, float hi) {
    __half2 t = __float22half2_rn(make_float2(lo, hi));
    return *reinterpret_cast<uint32_t*>(&t);
}
__device__ __forceinline__ uint32_t ex2h2(uint32_t x) {
    __half2 v = *reinterpret_cast<__half2*>(&x);
    __half2 r = h2exp2(v);
    return *reinterpret_cast<uint32_t*>(&r);
}

#define CP_ASYNC16(dst, src) \
    asm volatile("cp.async.cg.shared.global [%0], [%1], 16;" :: "r"(dst), "l"(src))
#define CP_COMMIT() asm volatile("cp.async.commit_group;" ::: "memory")
#define CP_WAIT1()  asm volatile("cp.async.wait_group 1;" ::: "memory")
#define CP_WAIT0()  asm volatile("cp.async.wait_group 0;" ::: "memory")

__device__ __forceinline__ void ldm4(uint32_t addr, uint32_t* r) {
    asm volatile("ldmatrix.sync.aligned.m8n8.x4.shared.b16 {%0,%1,%2,%3}, [%4];"
                 : "=r"(r[0]), "=r"(r[1]), "=r"(r[2]), "=r"(r[3]) : "r"(addr));
}
__device__ __forceinline__ void mma_fp(float* c, const uint32_t* a, const uint32_t* b) {
    asm volatile("mma.sync.aligned.m16n8k16.row.col.f32.f16.f16.f32 "
                 "{%0,%1,%2,%3}, {%4,%5,%6,%7}, {%8,%9}, {%0,%1,%2,%3};"
                 : "+f"(c[0]), "+f"(c[1]), "+f"(c[2]), "+f"(c[3])
                 : "r"(a[0]), "r"(a[1]), "r"(a[2]), "r"(a[3]),
                   "r"(b[0]), "r"(b[1]));
}

__device__ __forceinline__ uint32_t pack_hf(__half x, __half y) {
    __half2 t = __halves2half2(x, y);
    return *reinterpret_cast<uint32_t*>(&t);
}

// ---------------------------------------------------------------------------
// Mask tile flags: 1 if any nonzero in the (b, qt, kt) 64x64 tile.
// ---------------------------------------------------------------------------
__global__ __launch_bounds__(128) void mask_flag_kernel(const float* __restrict__ Mask)
{
    const int blk = blockIdx.x;                 // b*1024 + qt*32 + kt
    const int b = blk >> 10, qt = (blk >> 5) & 31, kt = blk & 31;
    const float* p = Mask + ((size_t)b * SEQ + qt * 64) * SEQ + kt * 64;
    const int tid = threadIdx.x;
    bool nz = false;
#pragma unroll
    for (int i = 0; i < 8; i++) {
        const int t = tid + i * 128;
        const int r = t >> 4, c = (t & 15) * 4;
        float4 v = *(const float4*)&p[(size_t)r * SEQ + c];
        nz |= (v.x != 0.f) | (v.y != 0.f) | (v.z != 0.f) | (v.w != 0.f);
    }
    const int any = __syncthreads_or((int)nz);
    if (tid == 0) g_mflag[blk] = (unsigned char)(any != 0);
}

// ---------------------------------------------------------------------------
// Conversions (fp32 -> fp16)
// ---------------------------------------------------------------------------
union HfPack { __half h[4]; uint2 u; };

// src [rows][1280] fp32 -> dst [rows][1280] fp16
__global__ __launch_bounds__(320) void conv_rows_kernel(
    const float* __restrict__ src, __half* __restrict__ dst)
{
    const int m = blockIdx.x;
    const int k4 = threadIdx.x * 4;
    float4 v = *(const float4*)&src[(size_t)m * DMODEL + k4];
    HfPack hi;
    hi.h[0] = __float2half_rn(v.x);
    hi.h[1] = __float2half_rn(v.y);
    hi.h[2] = __float2half_rn(v.z);
    hi.h[3] = __float2half_rn(v.w);
    *(uint2*)&dst[(size_t)m * DMODEL + k4] = hi.u;
}

// src W [K=1280][N] fp32 -> dst [N][1280] fp16 (transposed)
__global__ __launch_bounds__(256) void split_w_kernel(
    const float* __restrict__ src, __half* __restrict__ dst, int N)
{
    const int idx = blockIdx.x * 256 + threadIdx.x;
    const int n = idx % N;
    const int k4i = idx / N;
    if (k4i >= DMODEL / 4) return;
    const int k = k4i * 4;
    HfPack hi;
#pragma unroll
    for (int i = 0; i < 4; i++)
        hi.h[i] = __float2half_rn(src[(size_t)(k + i) * N + n]);
    *(uint2*)&dst[(size_t)n * DMODEL + k] = hi.u;
}

// ---------------------------------------------------------------------------
// QKV GEMM (big tiles): CTA 128x256, 8 warps of 64x64, 3-stage ring (144KB).
// A [4096][1280] fp16 (1-pass); B [3840][1280].
// Epilogue scatters fp16 q/k (row-major) and v (d-major).
// ---------------------------------------------------------------------------
#define BSTAGE 49152          /* A 16KB + B 32KB */
#define SMQ_TOTAL (3*BSTAGE)

__global__ __launch_bounds__(256, 1) void qkv_gemm_kernel(
    const __half* __restrict__ A,
    const __half* __restrict__ Bt)
{
    extern __shared__ __align__(1024) char smem[];
    const uint32_t sb = smem_u32(smem);
    const int tid = threadIdx.x;
    const int lane = tid & 31, wid = tid >> 5;
    const int wm = wid >> 2, wn = wid & 3;      // warp grid 2 x 4 (64 x 64 tiles)
    const int m0 = blockIdx.y * 128, n0 = blockIdx.x * 256;

    auto load_stage = [&](int s, int buf) {
        const uint32_t base = sb + buf * BSTAGE;
        const __half* ap = A  + (size_t)m0 * DMODEL + s * 64;
        const __half* bp = Bt + (size_t)n0 * DMODEL + s * 64;
#pragma unroll
        for (int i = 0; i < 4; i++) {           // A: 128 rows x 8 chunks
            const int t = tid + i * 256;
            const int r = t >> 3, c = t & 7;
            CP_ASYNC16(base + swz(r * 128 + c * 16), ap + (size_t)r * DMODEL + c * 8);
        }
#pragma unroll
        for (int i = 0; i < 8; i++) {           // B: 256 rows x 8 chunks
            const int t = tid + i * 256;
            const int r = t >> 3, c = t & 7;
            CP_ASYNC16(base + 16384 + swz(r * 128 + c * 16), bp + (size_t)r * DMODEL + c * 8);
        }
        CP_COMMIT();
    };

    float acc[4][8][4];
#pragma unroll
    for (int mi = 0; mi < 4; mi++)
#pragma unroll
        for (int ni = 0; ni < 8; ni++)
#pragma unroll
            for (int q = 0; q < 4; q++) acc[mi][ni][q] = 0.f;

    load_stage(0, 0);
    load_stage(1, 1);

    const int arow = lane & 15;
    const int acol = (lane >> 4) * 8;
    const int b4row = ((lane >> 4) & 1) * 8 + (lane & 7);
    const int b4col = ((lane >> 3) & 1) * 8;

#pragma unroll 1
    for (int s = 0; s < NST1; s++) {
        if (s + 1 < NST1) { CP_WAIT1(); } else { CP_WAIT0(); }
        __syncthreads();
        if (s + 2 < NST1) load_stage(s + 2, (s + 2) % 3);

        const uint32_t abase = sb + (s % 3) * BSTAGE;
        const uint32_t bbase = abase + 16384;
#pragma unroll
        for (int kf = 0; kf < 4; kf++) {
            uint32_t a[4][4], b[4][4];
#pragma unroll
            for (int mi = 0; mi < 4; mi++)
                ldm4(abase + swz((wm*64 + mi*16 + arow) * 128 + (kf*16 + acol) * 2), a[mi]);
#pragma unroll
            for (int n2 = 0; n2 < 4; n2++)
                ldm4(bbase + swz((wn*64 + n2*16 + b4row) * 128 + (kf*16 + b4col) * 2), b[n2]);
#pragma unroll
            for (int mi = 0; mi < 4; mi++)
#pragma unroll
                for (int n2 = 0; n2 < 4; n2++) {
                    mma_fp(acc[mi][n2*2],   a[mi], b[n2]);
                    mma_fp(acc[mi][n2*2+1], a[mi], b[n2] + 2);
                }
        }
    }

    // ---- epilogue: scatter into q/k (row-major fp16) and v (d-major fp16) ----
    const int grp = lane >> 2, tig = lane & 3;
    const int sec = n0 / DMODEL;   // 1280 % 256 == 0 -> tile inside one section
#pragma unroll
    for (int mi = 0; mi < 4; mi++) {
#pragma unroll
        for (int half = 0; half < 2; half++) {
            const int r = wm * 64 + mi * 16 + grp + half * 8;
            const int m = m0 + r;
            const int bb = m >> 11, sq = m & 2047;
#pragma unroll
            for (int ni = 0; ni < 8; ni++) {
                const float v0 = acc[mi][ni][half * 2];
                const float v1 = acc[mi][ni][half * 2 + 1];
                const int nglob = n0 + wn * 64 + ni * 8 + tig * 2;
                const int rem = nglob - sec * DMODEL;
                const int hh = rem >> 6, dd = rem & 63;
                const int bh = bb * NH + hh;
                if (sec == 2) {
                    g_vh[((size_t)bh * DH + dd) * SEQ + sq]     = __float2half_rn(v0);
                    g_vh[((size_t)bh * DH + dd + 1) * SEQ + sq] = __float2half_rn(v1);
                } else {
                    const size_t a = ((size_t)bh * SEQ + sq) * DH + dd;
                    const uint32_t hv = pack_hf(__float2half_rn(v0), __float2half_rn(v1));
                    if (sec == 0) *(uint32_t*)&g_qh[a] = hv;
                    else          *(uint32_t*)&g_kh[a] = hv;
                }
            }
        }
    }
}

// ---------------------------------------------------------------------------
// Out-projection GEMM (128x128, 8 warps of 64x32): out = A*B^T + bias
// A [4096][1280] fp16 (1-pass); B [1280][1280].
// ---------------------------------------------------------------------------
#define STAGE_BYTES 32768
#define SM_TOTAL (3*STAGE_BYTES)

__global__ __launch_bounds__(256) void out_gemm_kernel(
    const __half* __restrict__ A,
    const __half* __restrict__ Bt,
    const float* __restrict__ bias, float* __restrict__ Cout)
{
    extern __shared__ __align__(1024) char smem[];
    const uint32_t sb = smem_u32(smem);
    const int tid = threadIdx.x;
    const int lane = tid & 31, wid = tid >> 5;
    const int wm = wid >> 2, wn = wid & 3;
    const int m0 = blockIdx.y * 128, n0 = blockIdx.x * 128;

    auto load_stage = [&](int s, int buf) {
        const uint32_t base = sb + buf * STAGE_BYTES;
        const __half* ap = A  + (size_t)m0 * DMODEL + s * 64;
        const __half* bp = Bt + (size_t)n0 * DMODEL + s * 64;
#pragma unroll
        for (int i = 0; i < 4; i++) {
            const int t = tid + i * 256;
            const int r = t >> 3, c = t & 7;
            CP_ASYNC16(base + swz(r * 128 + c * 16), ap + (size_t)r * DMODEL + c * 8);
        }
#pragma unroll
        for (int i = 0; i < 4; i++) {
            const int t = tid + i * 256;
            const int r = t >> 3, c = t & 7;
            CP_ASYNC16(base + 16384 + swz(r * 128 + c * 16), bp + (size_t)r * DMODEL + c * 8);
        }
        CP_COMMIT();
    };

    float acc[4][4][4];
#pragma unroll
    for (int mi = 0; mi < 4; mi++)
#pragma unroll
        for (int ni = 0; ni < 4; ni++)
#pragma unroll
            for (int q = 0; q < 4; q++) acc[mi][ni][q] = 0.f;

    load_stage(0, 0);
    load_stage(1, 1);

    const int arow = lane & 15;
    const int acol = (lane >> 4) * 8;
    const int b4row = ((lane >> 4) & 1) * 8 + (lane & 7);
    const int b4col = ((lane >> 3) & 1) * 8;

#pragma unroll 1
    for (int s = 0; s < NST1; s++) {
        if (s + 1 < NST1) { CP_WAIT1(); } else { CP_WAIT0(); }
        __syncthreads();
        if (s + 2 < NST1) load_stage(s + 2, (s + 2) % 3);

        const uint32_t abase = sb + (s % 3) * STAGE_BYTES;
        const uint32_t bbase = abase + 16384;
#pragma unroll
        for (int kf = 0; kf < 4; kf++) {
            uint32_t a[4][4], b2[2][4];
#pragma unroll
            for (int mi = 0; mi < 4; mi++)
                ldm4(abase + swz((wm*64 + mi*16 + arow) * 128 + (kf*16 + acol) * 2), a[mi]);
#pragma unroll
            for (int n2 = 0; n2 < 2; n2++)
                ldm4(bbase + swz((wn*32 + n2*16 + b4row) * 128 + (kf*16 + b4col) * 2), b2[n2]);
#pragma unroll
            for (int mi = 0; mi < 4; mi++)
#pragma unroll
                for (int n2 = 0; n2 < 2; n2++) {
                    mma_fp(acc[mi][n2*2],   a[mi], b2[n2]);
                    mma_fp(acc[mi][n2*2+1], a[mi], b2[n2] + 2);
                }
        }
    }

    const int grp = lane >> 2, tig = lane & 3;
#pragma unroll
    for (int mi = 0; mi < 4; mi++) {
#pragma unroll
        for (int half = 0; half < 2; half++) {
            const int m = m0 + wm * 64 + mi * 16 + grp + half * 8;
#pragma unroll
            for (int ni = 0; ni < 4; ni++) {
                const int nglob = n0 + wn * 32 + ni * 8 + tig * 2;
                float2 bv = *(const float2*)&bias[nglob];
                *(float2*)&Cout[(size_t)m * DMODEL + nglob] =
                    make_float2(acc[mi][ni][half*2] + bv.x, acc[mi][ni][half*2+1] + bv.y);
            }
        }
    }
}

// ---------------------------------------------------------------------------
// fp16 tensor-core flash attention.
// CTA: 128 queries x one (b,h); 4 warps, each M=32, N=64 keys.
// QK^T 1-pass; softmax via h2exp2 producing packed fp16 P fragments;
// row-sum l via an extra ones-column mma; PV 1-pass.
// smem: Qh 16KB | 2 stages x {Kh,Vh each 8KB} = 48KB -> 3 CTAs/SM.
// ---------------------------------------------------------------------------
#define FSM_TOTAL 49152

__global__ __launch_bounds__(128, 3) void flash_mma_kernel(const float* __restrict__ Mask)
{
    extern __shared__ __align__(1024) char fsm[];
    const uint32_t sb = smem_u32(fsm);
    const int tid = threadIdx.x, lane = tid & 31, wid = tid >> 5;
    const int grp = lane >> 2, tig = lane & 3;
    const int qb = blockIdx.x, h = blockIdx.y, b = blockIdx.z;
    const int bh = b * NH + h;

    const __half* qhp = g_qh + ((size_t)bh * SEQ + qb * 128) * DH;
    const __half* khp = g_kh + (size_t)bh * SEQ * DH;
    const __half* vhp = g_vh + (size_t)bh * DH * SEQ;

#pragma unroll
    for (int i = 0; i < 8; i++) {
        const int t = tid + i * 128;
        const int r = t >> 3, c = t & 7;
        CP_ASYNC16(sb + swz(r * 128 + c * 16), qhp + (size_t)r * DH + c * 8);
    }

    auto load_kv = [&](int kb, int buf) {
        const uint32_t base = sb + 16384 + buf * 16384;
#pragma unroll
        for (int i = 0; i < 4; i++) {
            const int t = tid + i * 128;
            const int r = t >> 3, c = t & 7;
            const uint32_t d = swz(r * 128 + c * 16);
            CP_ASYNC16(base + d,        khp + (size_t)(kb * 64 + r) * DH + c * 8);
            CP_ASYNC16(base + 8192 + d, vhp + (size_t)r * SEQ + kb * 64 + c * 8);
        }
        CP_COMMIT();
    };
    load_kv(0, 0);
    load_kv(1, 1);

    float O[2][8][4];
    float lacc[2][4];
#pragma unroll
    for (int t = 0; t < 2; t++) {
#pragma unroll
        for (int nf = 0; nf < 8; nf++)
#pragma unroll
            for (int q = 0; q < 4; q++) O[t][nf][q] = 0.f;
#pragma unroll
        for (int q = 0; q < 4; q++) lacc[t][q] = 0.f;
    }
    float mrun[4] = {-1e30f, -1e30f, -1e30f, -1e30f};

    const int qrowbase = qb * 128 + wid * 32;
    const float* mrp[4];
#pragma unroll
    for (int j = 0; j < 4; j++) {
        const int t = j >> 1, half = j & 1;
        mrp[j] = Mask + ((size_t)b * SEQ + qrowbase + t * 16 + half * 8 + grp) * SEQ;
    }
    const unsigned char* flagp = g_mflag + (size_t)b * 1024 + (qb * 2 + (wid >> 1)) * 32;

    const int arow = lane & 15;
    const int acol = (lane >> 4) * 8;
    const int b4row = ((lane >> 4) & 1) * 8 + (lane & 7);
    const int b4col = ((lane >> 3) & 1) * 8;

    const float SCL2E = 0.125f * 1.44269504f;
    const float L2E = 1.44269504f;
    const uint32_t ONES2 = 0x3C003C00u;          // half2(1,1)
    const uint32_t onesb[2] = {ONES2, ONES2};

#pragma unroll 1
    for (int kb = 0; kb < 32; kb++) {
        if (kb < 31) { CP_WAIT1(); } else { CP_WAIT0(); }
        __syncthreads();
        const uint32_t kbase = sb + 16384 + (kb & 1) * 16384;

        // ---- S = Q K^T (1-pass fp16) ----
        float S[2][8][4];
#pragma unroll
        for (int t = 0; t < 2; t++)
#pragma unroll
            for (int nf = 0; nf < 8; nf++)
#pragma unroll
                for (int q = 0; q < 4; q++) S[t][nf][q] = 0.f;

#pragma unroll
        for (int kf = 0; kf < 4; kf++) {
            uint32_t aq[2][4];
#pragma unroll
            for (int t = 0; t < 2; t++)
                ldm4(sb + swz((wid * 32 + t * 16 + arow) * 128 + (kf * 16 + acol) * 2), aq[t]);
#pragma unroll
            for (int n2 = 0; n2 < 4; n2++) {
                uint32_t kh4[4];
                ldm4(kbase + swz((n2 * 16 + b4row) * 128 + (kf * 16 + b4col) * 2), kh4);
#pragma unroll
                for (int t = 0; t < 2; t++) {
                    mma_fp(S[t][n2*2],   aq[t], kh4);
                    mma_fp(S[t][n2*2+1], aq[t], kh4 + 2);
                }
            }
        }

        // ---- scale (+ mask if tile nonzero), log2 domain ----
        if (flagp[kb]) {
#pragma unroll
            for (int t = 0; t < 2; t++)
#pragma unroll
                for (int nf = 0; nf < 8; nf++) {
                    float2 u = *(const float2*)&mrp[t*2    ][kb * 64 + nf * 8 + tig * 2];
                    float2 w = *(const float2*)&mrp[t*2 + 1][kb * 64 + nf * 8 + tig * 2];
                    S[t][nf][0] = fmaf(S[t][nf][0], SCL2E, u.x * L2E);
                    S[t][nf][1] = fmaf(S[t][nf][1], SCL2E, u.y * L2E);
                    S[t][nf][2] = fmaf(S[t][nf][2], SCL2E, w.x * L2E);
                    S[t][nf][3] = fmaf(S[t][nf][3], SCL2E, w.y * L2E);
                }
        } else {
#pragma unroll
            for (int t = 0; t < 2; t++)
#pragma unroll
                for (int nf = 0; nf < 8; nf++)
#pragma unroll
                    for (int q = 0; q < 4; q++) S[t][nf][q] *= SCL2E;
        }

        // ---- running max per row-set j ----
        float al[4], mnv[4];
#pragma unroll
        for (int j = 0; j < 4; j++) {
            const int t = j >> 1, half = j & 1;
            float rm = -1e30f;
#pragma unroll
            for (int nf = 0; nf < 8; nf++)
                rm = fmaxf(rm, fmaxf(S[t][nf][half*2], S[t][nf][half*2+1]));
            rm = fmaxf(rm, __shfl_xor_sync(0xffffffffu, rm, 1));
            rm = fmaxf(rm, __shfl_xor_sync(0xffffffffu, rm, 2));
            const float mn = fmaxf(mrun[j], rm);
            al[j] = ex2(mrun[j] - mn);
            mrun[j] = mn;
            mnv[j] = mn;
        }

        // ---- P = exp2(S - m) in fp16, directly packed as mma A-fragments ----
        uint32_t Pp[2][8][2];
#pragma unroll
        for (int t = 0; t < 2; t++)
#pragma unroll
            for (int nf = 0; nf < 8; nf++) {
                Pp[t][nf][0] = ex2h2(cvt_h2(S[t][nf][0] - mnv[t*2],
                                            S[t][nf][1] - mnv[t*2]));
                Pp[t][nf][1] = ex2h2(cvt_h2(S[t][nf][2] - mnv[t*2+1],
                                            S[t][nf][3] - mnv[t*2+1]));
            }

        // ---- rescale O and l ----
#pragma unroll
        for (int t = 0; t < 2; t++) {
#pragma unroll
            for (int nf = 0; nf < 8; nf++) {
                O[t][nf][0] *= al[t*2];   O[t][nf][1] *= al[t*2];
                O[t][nf][2] *= al[t*2+1]; O[t][nf][3] *= al[t*2+1];
            }
            lacc[t][0] *= al[t*2];   lacc[t][1] *= al[t*2];
            lacc[t][2] *= al[t*2+1]; lacc[t][3] *= al[t*2+1];
        }

        // ---- O += P Vh ; l += P * ones ----
#pragma unroll
        for (int kc = 0; kc < 4; kc++) {
            uint32_t phi[2][4];
#pragma unroll
            for (int t = 0; t < 2; t++) {
                phi[t][0] = Pp[t][kc*2][0];
                phi[t][1] = Pp[t][kc*2][1];
                phi[t][2] = Pp[t][kc*2+1][0];
                phi[t][3] = Pp[t][kc*2+1][1];
                mma_fp(lacc[t], phi[t], onesb);
            }
#pragma unroll
            for (int n2 = 0; n2 < 4; n2++) {
                uint32_t vh4[4];
                const uint32_t off = swz((n2 * 16 + b4row) * 128 + (kc * 16 + b4col) * 2);
                ldm4(kbase + 8192 + off, vh4);
#pragma unroll
                for (int t = 0; t < 2; t++) {
                    mma_fp(O[t][n2*2],   phi[t], vh4);
                    mma_fp(O[t][n2*2+1], phi[t], vh4 + 2);
                }
            }
        }

        __syncthreads();
        if (kb + 2 < 32) load_kv(kb + 2, kb & 1);
    }

    // ---- epilogue: write normalized O as plain fp16 rows of g_A2buf ----
#pragma unroll
    for (int j = 0; j < 4; j++) {
        const int t = j >> 1, half = j & 1;
        const int row = qrowbase + t * 16 + half * 8 + grp;
        const float inv = 1.f / lacc[t][half * 2];
        __half* op = g_A2buf + ((size_t)b * SEQ + row) * DMODEL;
#pragma unroll
        for (int nf = 0; nf < 8; nf++) {
            const int col = h * 64 + nf * 8 + tig * 2;
            *(uint32_t*)&op[col] = pack_hf(__float2half_rn(O[t][nf][half*2] * inv),
                                           __float2half_rn(O[t][nf][half*2+1] * inv));
        }
    }
}

// ---------------------------------------------------------------------------
extern "C" void kernel_launch(void* const* d_in, const int* in_sizes, int n_in,
                              void* d_out, int out_size)
{
    const float* hidden = (const float*)d_in[0];
    const float* mask   = (const float*)d_in[1];
    const float* w_qkv  = (const float*)d_in[2];
    const float* w_out  = (const float*)d_in[3];
    const float* b_out  = (const float*)d_in[4];
    float* out = (float*)d_out;

    cudaFuncSetAttribute(qkv_gemm_kernel,
                         cudaFuncAttributeMaxDynamicSharedMemorySize, SMQ_TOTAL);
    cudaFuncSetAttribute(out_gemm_kernel,
                         cudaFuncAttributeMaxDynamicSharedMemorySize, SM_TOTAL);
    cudaFuncSetAttribute(flash_mma_kernel,
                         cudaFuncAttributeMaxDynamicSharedMemorySize, FSM_TOTAL);

    __half *abuf, *wt, *w2t, *a2buf;
    cudaGetSymbolAddress((void**)&abuf, g_Abuf);
    cudaGetSymbolAddress((void**)&wt, g_Wt);
    cudaGetSymbolAddress((void**)&w2t, g_W2t);
    cudaGetSymbolAddress((void**)&a2buf, g_A2buf);

    // 1. conversions + mask tile flags
    mask_flag_kernel<<<BATCH * 32 * 32, 128>>>(mask);
    conv_rows_kernel<<<MTOT, 320>>>(hidden, abuf);
    split_w_kernel<<<(3840 * 320 + 255) / 256, 256>>>(w_qkv, wt, 3840);
    split_w_kernel<<<(1280 * 320 + 255) / 256, 256>>>(w_out, w2t, 1280);

    // 2. QKV projection (fp16 1-pass, 128x256 tiles) -> fp16 q/k/v
    qkv_gemm_kernel<<<dim3(3840 / 256, MTOT / 128), 256, SMQ_TOTAL>>>(abuf, wt);

    // 3. fp16 tensor-core flash attention (fp16 softmax, ones-mma row sums)
    flash_mma_kernel<<<dim3(SEQ / 128, NH, BATCH), 128, FSM_TOTAL>>>(mask);

    // 4. out-projection (fp16 1-pass, 128x128 tiles)
    out_gemm_kernel<<<dim3(1280 / 128, MTOT / 128), 256, SM_TOTAL>>>(
        a2buf, w2t, b_out, out);
}

// round 16
// speedup vs baseline: 7.2006x; 1.0093x over previous
#include <cuda_runtime.h>
#include <cuda_bf16.h>
#include <cuda_fp16.h>
#include <cstdint>

#define NH 20
#define DH 64
#define DMODEL 1280
#define BATCH 2
#define SEQ 2048
#define MTOT (BATCH*SEQ)      /* 4096 */
#define NST1 20               /* 1280 / 64 : 1-pass GEMM stages */

// ---------------------------------------------------------------------------
// Device-global scratch (allocation-free rule)
// ---------------------------------------------------------------------------
__device__ __half g_qh[BATCH*NH*SEQ*DH];         // [bh][s][dd] fp16
__device__ __half g_kh[BATCH*NH*SEQ*DH];         // [bh][s][dd] fp16
__device__ __half g_vh[BATCH*NH*DH*SEQ];         // d-major [bh][dd][s] fp16
__device__ __half g_Abuf[(size_t)MTOT*DMODEL];   // X as fp16
__device__ __half g_Wt[(size_t)3840*DMODEL];     // [n][Wh]
__device__ __half g_W2t[(size_t)1280*DMODEL];
__device__ __half g_A2buf[(size_t)MTOT*DMODEL];  // attn rows, plain fp16
__device__ unsigned char g_mflag[BATCH*32*32];   // mask 64x64 tile nonzero flags

// ---------------------------------------------------------------------------
// Baseline-PTX helpers
// ---------------------------------------------------------------------------
__device__ __forceinline__ uint32_t smem_u32(const void* p) {
    uint32_t a;
    asm("{ .reg .u64 t; cvta.to.shared.u64 t, %1; cvt.u32.u64 %0, t; }"
        : "=r"(a) : "l"(p));
    return a;
}
__device__ __forceinline__ uint32_t swz(uint32_t off) {  // SW128 byte swizzle
    return off ^ ((off >> 3) & 0x70);
}
__device__ __forceinline__ float ex2(float x) {
    float y;
    asm("ex2.approx.ftz.f32 %0, %1;" : "=f"(y) : "f"(x));
    return y;
}
// pack two f32 -> half2 (lo, hi), then exp2 in fp16x2
__device__ __forceinline__ uint32_t cvt_h2(float lo, float hi) {
    __half2 t = __float22half2_rn(make_float2(lo, hi));
    return *reinterpret_cast<uint32_t*>(&t);
}
__device__ __forceinline__ uint32_t ex2h2(uint32_t x) {
    __half2 v = *reinterpret_cast<__half2*>(&x);
    __half2 r = h2exp2(v);
    return *reinterpret_cast<uint32_t*>(&r);
}

#define CP_ASYNC16(dst, src) \
    asm volatile("cp.async.cg.shared.global [%0], [%1], 16;" :: "r"(dst), "l"(src))
#define CP_COMMIT() asm volatile("cp.async.commit_group;" ::: "memory")
#define CP_WAIT0()  asm volatile("cp.async.wait_group 0;" ::: "memory")
#define CP_WAIT1()  asm volatile("cp.async.wait_group 1;" ::: "memory")
#define CP_WAIT2()  asm volatile("cp.async.wait_group 2;" ::: "memory")
#define CP_WAIT3()  asm volatile("cp.async.wait_group 3;" ::: "memory")

__device__ __forceinline__ void ldm4(uint32_t addr, uint32_t* r) {
    asm volatile("ldmatrix.sync.aligned.m8n8.x4.shared.b16 {%0,%1,%2,%3}, [%4];"
                 : "=r"(r[0]), "=r"(r[1]), "=r"(r[2]), "=r"(r[3]) : "r"(addr));
}
__device__ __forceinline__ void mma_fp(float* c, const uint32_t* a, const uint32_t* b) {
    asm volatile("mma.sync.aligned.m16n8k16.row.col.f32.f16.f16.f32 "
                 "{%0,%1,%2,%3}, {%4,%5,%6,%7}, {%8,%9}, {%0,%1,%2,%3};"
                 : "+f"(c[0]), "+f"(c[1]), "+f"(c[2]), "+f"(c[3])
                 : "r"(a[0]), "r"(a[1]), "r"(a[2]), "r"(a[3]),
                   "r"(b[0]), "r"(b[1]));
}

__device__ __forceinline__ uint32_t pack_hf(__half x, __half y) {
    __half2 t = __halves2half2(x, y);
    return *reinterpret_cast<uint32_t*>(&t);
}

// ---------------------------------------------------------------------------
// Mask tile flags: 1 if any nonzero in the (b, qt, kt) 64x64 tile.
// ---------------------------------------------------------------------------
__global__ __launch_bounds__(128) void mask_flag_kernel(const float* __restrict__ Mask)
{
    const int blk = blockIdx.x;                 // b*1024 + qt*32 + kt
    const int b = blk >> 10, qt = (blk >> 5) & 31, kt = blk & 31;
    const float* p = Mask + ((size_t)b * SEQ + qt * 64) * SEQ + kt * 64;
    const int tid = threadIdx.x;
    bool nz = false;
#pragma unroll
    for (int i = 0; i < 8; i++) {
        const int t = tid + i * 128;
        const int r = t >> 4, c = (t & 15) * 4;
        float4 v = *(const float4*)&p[(size_t)r * SEQ + c];
        nz |= (v.x != 0.f) | (v.y != 0.f) | (v.z != 0.f) | (v.w != 0.f);
    }
    const int any = __syncthreads_or((int)nz);
    if (tid == 0) g_mflag[blk] = (unsigned char)(any != 0);
}

// ---------------------------------------------------------------------------
// Conversions (fp32 -> fp16)
// ---------------------------------------------------------------------------
union HfPack { __half h[4]; uint2 u; };

// src [rows][1280] fp32 -> dst [rows][1280] fp16
__global__ __launch_bounds__(320) void conv_rows_kernel(
    const float* __restrict__ src, __half* __restrict__ dst)
{
    const int m = blockIdx.x;
    const int k4 = threadIdx.x * 4;
    float4 v = *(const float4*)&src[(size_t)m * DMODEL + k4];
    HfPack hi;
    hi.h[0] = __float2half_rn(v.x);
    hi.h[1] = __float2half_rn(v.y);
    hi.h[2] = __float2half_rn(v.z);
    hi.h[3] = __float2half_rn(v.w);
    *(uint2*)&dst[(size_t)m * DMODEL + k4] = hi.u;
}

// src W [K=1280][N] fp32 -> dst [N][1280] fp16 (transposed)
__global__ __launch_bounds__(256) void split_w_kernel(
    const float* __restrict__ src, __half* __restrict__ dst, int N)
{
    const int idx = blockIdx.x * 256 + threadIdx.x;
    const int n = idx % N;
    const int k4i = idx / N;
    if (k4i >= DMODEL / 4) return;
    const int k = k4i * 4;
    HfPack hi;
#pragma unroll
    for (int i = 0; i < 4; i++)
        hi.h[i] = __float2half_rn(src[(size_t)(k + i) * N + n]);
    *(uint2*)&dst[(size_t)n * DMODEL + k] = hi.u;
}

// ---------------------------------------------------------------------------
// Big-tile GEMM: CTA 128x256, 8 warps of 64x64, 3-stage ring (144KB).
// A [4096][1280] fp16; B [N][1280] fp16.
// mode 0: QKV scatter epilogue. mode 1: fp32 out + bias.
// ---------------------------------------------------------------------------
#define BSTAGE 49152          /* A 16KB + B 32KB */
#define SMQ_TOTAL (3*BSTAGE)

__global__ __launch_bounds__(256, 1) void big_gemm_kernel(
    const __half* __restrict__ A,
    const __half* __restrict__ Bt,
    int mode, const float* __restrict__ bias, float* __restrict__ Cout)
{
    extern __shared__ __align__(1024) char smem[];
    const uint32_t sb = smem_u32(smem);
    const int tid = threadIdx.x;
    const int lane = tid & 31, wid = tid >> 5;
    const int wm = wid >> 2, wn = wid & 3;      // warp grid 2 x 4 (64 x 64 tiles)
    const int m0 = blockIdx.y * 128, n0 = blockIdx.x * 256;

    auto load_stage = [&](int s, int buf) {
        const uint32_t base = sb + buf * BSTAGE;
        const __half* ap = A  + (size_t)m0 * DMODEL + s * 64;
        const __half* bp = Bt + (size_t)n0 * DMODEL + s * 64;
#pragma unroll
        for (int i = 0; i < 4; i++) {           // A: 128 rows x 8 chunks
            const int t = tid + i * 256;
            const int r = t >> 3, c = t & 7;
            CP_ASYNC16(base + swz(r * 128 + c * 16), ap + (size_t)r * DMODEL + c * 8);
        }
#pragma unroll
        for (int i = 0; i < 8; i++) {           // B: 256 rows x 8 chunks
            const int t = tid + i * 256;
            const int r = t >> 3, c = t & 7;
            CP_ASYNC16(base + 16384 + swz(r * 128 + c * 16), bp + (size_t)r * DMODEL + c * 8);
        }
        CP_COMMIT();
    };

    float acc[4][8][4];
#pragma unroll
    for (int mi = 0; mi < 4; mi++)
#pragma unroll
        for (int ni = 0; ni < 8; ni++)
#pragma unroll
            for (int q = 0; q < 4; q++) acc[mi][ni][q] = 0.f;

    load_stage(0, 0);
    load_stage(1, 1);

    const int arow = lane & 15;
    const int acol = (lane >> 4) * 8;
    const int b4row = ((lane >> 4) & 1) * 8 + (lane & 7);
    const int b4col = ((lane >> 3) & 1) * 8;

#pragma unroll 1
    for (int s = 0; s < NST1; s++) {
        if (s + 1 < NST1) { CP_WAIT1(); } else { CP_WAIT0(); }
        __syncthreads();
        if (s + 2 < NST1) load_stage(s + 2, (s + 2) % 3);

        const uint32_t abase = sb + (s % 3) * BSTAGE;
        const uint32_t bbase = abase + 16384;
#pragma unroll
        for (int kf = 0; kf < 4; kf++) {
            uint32_t a[4][4], b[4][4];
#pragma unroll
            for (int mi = 0; mi < 4; mi++)
                ldm4(abase + swz((wm*64 + mi*16 + arow) * 128 + (kf*16 + acol) * 2), a[mi]);
#pragma unroll
            for (int n2 = 0; n2 < 4; n2++)
                ldm4(bbase + swz((wn*64 + n2*16 + b4row) * 128 + (kf*16 + b4col) * 2), b[n2]);
#pragma unroll
            for (int mi = 0; mi < 4; mi++)
#pragma unroll
                for (int n2 = 0; n2 < 4; n2++) {
                    mma_fp(acc[mi][n2*2],   a[mi], b[n2]);
                    mma_fp(acc[mi][n2*2+1], a[mi], b[n2] + 2);
                }
        }
    }

    // ---- epilogue ----
    const int grp = lane >> 2, tig = lane & 3;
    const int sec = n0 / DMODEL;   // for mode 0: 1280 % 256 == 0 -> one section
#pragma unroll
    for (int mi = 0; mi < 4; mi++) {
#pragma unroll
        for (int half = 0; half < 2; half++) {
            const int r = wm * 64 + mi * 16 + grp + half * 8;
            const int m = m0 + r;
            const int bb = m >> 11, sq = m & 2047;
#pragma unroll
            for (int ni = 0; ni < 8; ni++) {
                const float v0 = acc[mi][ni][half * 2];
                const float v1 = acc[mi][ni][half * 2 + 1];
                const int nglob = n0 + wn * 64 + ni * 8 + tig * 2;
                if (mode == 1) {
                    float2 bv = *(const float2*)&bias[nglob];
                    *(float2*)&Cout[(size_t)m * DMODEL + nglob] =
                        make_float2(v0 + bv.x, v1 + bv.y);
                } else {
                    const int rem = nglob - sec * DMODEL;
                    const int hh = rem >> 6, dd = rem & 63;
                    const int bh = bb * NH + hh;
                    if (sec == 2) {
                        g_vh[((size_t)bh * DH + dd) * SEQ + sq]     = __float2half_rn(v0);
                        g_vh[((size_t)bh * DH + dd + 1) * SEQ + sq] = __float2half_rn(v1);
                    } else {
                        const size_t a = ((size_t)bh * SEQ + sq) * DH + dd;
                        const uint32_t hv = pack_hf(__float2half_rn(v0), __float2half_rn(v1));
                        if (sec == 0) *(uint32_t*)&g_qh[a] = hv;
                        else          *(uint32_t*)&g_kh[a] = hv;
                    }
                }
            }
        }
    }
}

// ---------------------------------------------------------------------------
// fp16 tensor-core flash attention.
// CTA: 128 queries x one (b,h); 4 warps, each M=32, N=64 keys.
// Q fragments hoisted to registers (loaded once). 3-buffer KV cp.async ring.
// QK^T 1-pass; softmax via h2exp2 -> packed fp16 P; l via ones-mma; PV 1-pass.
// smem: Qh 16KB | 3 stages x {Kh,Vh each 8KB} = 64KB -> 2 CTAs/SM.
// ---------------------------------------------------------------------------
#define FSM_TOTAL 65536

__global__ __launch_bounds__(128, 2) void flash_mma_kernel(const float* __restrict__ Mask)
{
    extern __shared__ __align__(1024) char fsm[];
    const uint32_t sb = smem_u32(fsm);
    const int tid = threadIdx.x, lane = tid & 31, wid = tid >> 5;
    const int grp = lane >> 2, tig = lane & 3;
    const int qb = blockIdx.x, h = blockIdx.y, b = blockIdx.z;
    const int bh = b * NH + h;

    const __half* qhp = g_qh + ((size_t)bh * SEQ + qb * 128) * DH;
    const __half* khp = g_kh + (size_t)bh * SEQ * DH;
    const __half* vhp = g_vh + (size_t)bh * DH * SEQ;

    // Q tile: 128 rows x 128B (group 0)
#pragma unroll
    for (int i = 0; i < 8; i++) {
        const int t = tid + i * 128;
        const int r = t >> 3, c = t & 7;
        CP_ASYNC16(sb + swz(r * 128 + c * 16), qhp + (size_t)r * DH + c * 8);
    }
    CP_COMMIT();

    auto load_kv = [&](int kb, int buf) {
        const uint32_t base = sb + 16384 + buf * 16384;
#pragma unroll
        for (int i = 0; i < 4; i++) {
            const int t = tid + i * 128;
            const int r = t >> 3, c = t & 7;
            const uint32_t d = swz(r * 128 + c * 16);
            CP_ASYNC16(base + d,        khp + (size_t)(kb * 64 + r) * DH + c * 8);
            CP_ASYNC16(base + 8192 + d, vhp + (size_t)r * SEQ + kb * 64 + c * 8);
        }
        CP_COMMIT();
    };
    load_kv(0, 0);   // group 1
    load_kv(1, 1);   // group 2
    load_kv(2, 2);   // group 3

    const int arow = lane & 15;
    const int acol = (lane >> 4) * 8;
    const int b4row = ((lane >> 4) & 1) * 8 + (lane & 7);
    const int b4col = ((lane >> 3) & 1) * 8;

    // Wait for Q (<=3 pending: the 3 KV groups), then hoist Q frags to regs.
    CP_WAIT3();
    __syncthreads();
    uint32_t aqr[4][2][4];
#pragma unroll
    for (int kf = 0; kf < 4; kf++)
#pragma unroll
        for (int t = 0; t < 2; t++)
            ldm4(sb + swz((wid * 32 + t * 16 + arow) * 128 + (kf * 16 + acol) * 2),
                 aqr[kf][t]);

    float O[2][8][4];
    float lacc[2][4];
#pragma unroll
    for (int t = 0; t < 2; t++) {
#pragma unroll
        for (int nf = 0; nf < 8; nf++)
#pragma unroll
            for (int q = 0; q < 4; q++) O[t][nf][q] = 0.f;
#pragma unroll
        for (int q = 0; q < 4; q++) lacc[t][q] = 0.f;
    }
    float mrun[4] = {-1e30f, -1e30f, -1e30f, -1e30f};

    const int qrowbase = qb * 128 + wid * 32;
    const float* mrp[4];
#pragma unroll
    for (int j = 0; j < 4; j++) {
        const int t = j >> 1, half = j & 1;
        mrp[j] = Mask + ((size_t)b * SEQ + qrowbase + t * 16 + half * 8 + grp) * SEQ;
    }
    const unsigned char* flagp = g_mflag + (size_t)b * 1024 + (qb * 2 + (wid >> 1)) * 32;

    const float SCL2E = 0.125f * 1.44269504f;
    const float L2E = 1.44269504f;
    const uint32_t ONES2 = 0x3C003C00u;          // half2(1,1)
    const uint32_t onesb[2] = {ONES2, ONES2};

#pragma unroll 1
    for (int kb = 0; kb < 32; kb++) {
        // pending newer-than-kb groups: kb<=29 -> 2, kb==30 -> 1, kb==31 -> 0
        if (kb < 30) { CP_WAIT2(); } else if (kb == 30) { CP_WAIT1(); } else { CP_WAIT0(); }
        __syncthreads();
        const uint32_t kbase = sb + 16384 + (kb % 3) * 16384;

        // ---- S = Q K^T (1-pass fp16, Q from registers) ----
        float S[2][8][4];
#pragma unroll
        for (int t = 0; t < 2; t++)
#pragma unroll
            for (int nf = 0; nf < 8; nf++)
#pragma unroll
                for (int q = 0; q < 4; q++) S[t][nf][q] = 0.f;

#pragma unroll
        for (int kf = 0; kf < 4; kf++) {
#pragma unroll
            for (int n2 = 0; n2 < 4; n2++) {
                uint32_t kh4[4];
                ldm4(kbase + swz((n2 * 16 + b4row) * 128 + (kf * 16 + b4col) * 2), kh4);
#pragma unroll
                for (int t = 0; t < 2; t++) {
                    mma_fp(S[t][n2*2],   aqr[kf][t], kh4);
                    mma_fp(S[t][n2*2+1], aqr[kf][t], kh4 + 2);
                }
            }
        }

        // ---- scale (+ mask if tile nonzero), log2 domain ----
        if (flagp[kb]) {
#pragma unroll
            for (int t = 0; t < 2; t++)
#pragma unroll
                for (int nf = 0; nf < 8; nf++) {
                    float2 u = *(const float2*)&mrp[t*2    ][kb * 64 + nf * 8 + tig * 2];
                    float2 w = *(const float2*)&mrp[t*2 + 1][kb * 64 + nf * 8 + tig * 2];
                    S[t][nf][0] = fmaf(S[t][nf][0], SCL2E, u.x * L2E);
                    S[t][nf][1] = fmaf(S[t][nf][1], SCL2E, u.y * L2E);
                    S[t][nf][2] = fmaf(S[t][nf][2], SCL2E, w.x * L2E);
                    S[t][nf][3] = fmaf(S[t][nf][3], SCL2E, w.y * L2E);
                }
        } else {
#pragma unroll
            for (int t = 0; t < 2; t++)
#pragma unroll
                for (int nf = 0; nf < 8; nf++)
#pragma unroll
                    for (int q = 0; q < 4; q++) S[t][nf][q] *= SCL2E;
        }

        // ---- running max per row-set j ----
        float al[4], mnv[4];
#pragma unroll
        for (int j = 0; j < 4; j++) {
            const int t = j >> 1, half = j & 1;
            float rm = -1e30f;
#pragma unroll
            for (int nf = 0; nf < 8; nf++)
                rm = fmaxf(rm, fmaxf(S[t][nf][half*2], S[t][nf][half*2+1]));
            rm = fmaxf(rm, __shfl_xor_sync(0xffffffffu, rm, 1));
            rm = fmaxf(rm, __shfl_xor_sync(0xffffffffu, rm, 2));
            const float mn = fmaxf(mrun[j], rm);
            al[j] = ex2(mrun[j] - mn);
            mrun[j] = mn;
            mnv[j] = mn;
        }

        // ---- P = exp2(S - m) in fp16, directly packed as mma A-fragments ----
        uint32_t Pp[2][8][2];
#pragma unroll
        for (int t = 0; t < 2; t++)
#pragma unroll
            for (int nf = 0; nf < 8; nf++) {
                Pp[t][nf][0] = ex2h2(cvt_h2(S[t][nf][0] - mnv[t*2],
                                            S[t][nf][1] - mnv[t*2]));
                Pp[t][nf][1] = ex2h2(cvt_h2(S[t][nf][2] - mnv[t*2+1],
                                            S[t][nf][3] - mnv[t*2+1]));
            }

        // ---- rescale O and l ----
#pragma unroll
        for (int t = 0; t < 2; t++) {
#pragma unroll
            for (int nf = 0; nf < 8; nf++) {
                O[t][nf][0] *= al[t*2];   O[t][nf][1] *= al[t*2];
                O[t][nf][2] *= al[t*2+1]; O[t][nf][3] *= al[t*2+1];
            }
            lacc[t][0] *= al[t*2];   lacc[t][1] *= al[t*2];
            lacc[t][2] *= al[t*2+1]; lacc[t][3] *= al[t*2+1];
        }

        // ---- O += P Vh ; l += P * ones ----
#pragma unroll
        for (int kc = 0; kc < 4; kc++) {
            uint32_t phi[2][4];
#pragma unroll
            for (int t = 0; t < 2; t++) {
                phi[t][0] = Pp[t][kc*2][0];
                phi[t][1] = Pp[t][kc*2][1];
                phi[t][2] = Pp[t][kc*2+1][0];
                phi[t][3] = Pp[t][kc*2+1][1];
                mma_fp(lacc[t], phi[t], onesb);
            }
#pragma unroll
            for (int n2 = 0; n2 < 4; n2++) {
                uint32_t vh4[4];
                const uint32_t off = swz((n2 * 16 + b4row) * 128 + (kc * 16 + b4col) * 2);
                ldm4(kbase + 8192 + off, vh4);
#pragma unroll
                for (int t = 0; t < 2; t++) {
                    mma_fp(O[t][n2*2],   phi[t], vh4);
                    mma_fp(O[t][n2*2+1], phi[t], vh4 + 2);
                }
            }
        }

        __syncthreads();
        if (kb + 3 < 32) load_kv(kb + 3, kb % 3);
    }

    // ---- epilogue: write normalized O as plain fp16 rows of g_A2buf ----
#pragma unroll
    for (int j = 0; j < 4; j++) {
        const int t = j >> 1, half = j & 1;
        const int row = qrowbase + t * 16 + half * 8 + grp;
        const float inv = 1.f / lacc[t][half * 2];
        __half* op = g_A2buf + ((size_t)b * SEQ + row) * DMODEL;
#pragma unroll
        for (int nf = 0; nf < 8; nf++) {
            const int col = h * 64 + nf * 8 + tig * 2;
            *(uint32_t*)&op[col] = pack_hf(__float2half_rn(O[t][nf][half*2] * inv),
                                           __float2half_rn(O[t][nf][half*2+1] * inv));
        }
    }
}

// ---------------------------------------------------------------------------
extern "C" void kernel_launch(void* const* d_in, const int* in_sizes, int n_in,
                              void* d_out, int out_size)
{
    const float* hidden = (const float*)d_in[0];
    const float* mask   = (const float*)d_in[1];
    const float* w_qkv  = (const float*)d_in[2];
    const float* w_out  = (const float*)d_in[3];
    const float* b_out  = (const float*)d_in[4];
    float* out = (float*)d_out;

    cudaFuncSetAttribute(big_gemm_kernel,
                         cudaFuncAttributeMaxDynamicSharedMemorySize, SMQ_TOTAL);
    cudaFuncSetAttribute(flash_mma_kernel,
                         cudaFuncAttributeMaxDynamicSharedMemorySize, FSM_TOTAL);

    __half *abuf, *wt, *w2t, *a2buf;
    cudaGetSymbolAddress((void**)&abuf, g_Abuf);
    cudaGetSymbolAddress((void**)&wt, g_Wt);
    cudaGetSymbolAddress((void**)&w2t, g_W2t);
    cudaGetSymbolAddress((void**)&a2buf, g_A2buf);

    // 1. conversions + mask tile flags
    mask_flag_kernel<<<BATCH * 32 * 32, 128>>>(mask);
    conv_rows_kernel<<<MTOT, 320>>>(hidden, abuf);
    split_w_kernel<<<(3840 * 320 + 255) / 256, 256>>>(w_qkv, wt, 3840);
    split_w_kernel<<<(1280 * 320 + 255) / 256, 256>>>(w_out, w2t, 1280);

    // 2. QKV projection (fp16 1-pass, 128x256 tiles) -> fp16 q/k/v
    big_gemm_kernel<<<dim3(3840 / 256, MTOT / 128), 256, SMQ_TOTAL>>>(
        abuf, wt, 0, nullptr, nullptr);

    // 3. fp16 tensor-core flash attention (hoisted Q, 3-buffer ring)
    flash_mma_kernel<<<dim3(SEQ / 128, NH, BATCH), 128, FSM_TOTAL>>>(mask);

    // 4. out-projection (fp16 1-pass, 128x256 tiles; 160 CTAs ~ 1.08 waves)
    big_gemm_kernel<<<dim3(1280 / 256, MTOT / 128), 256, SMQ_TOTAL>>>(
        a2buf, w2t, 1, b_out, out);
}